// round 6
// baseline (speedup 1.0000x reference)
#include <cuda_runtime.h>
#include <cuda_bf16.h>
#include <math.h>

// Problem constants
#define S_    2048
#define HID_  4096
#define NH_   32
#define NKV_  8
#define HD_   128
#define EPS_  1e-5f
// 1/sqrt(128)
#define SCALE_ 0.088388347648318447f
// log2(500000)
#define LOG2_THETA 18.931568569324174f

// ---------------------------------------------------------------------------
// Scratch (device globals; no allocation allowed)
// ---------------------------------------------------------------------------
__device__ float g_q[S_ * NH_ * HD_];     // [S][NH][HD]   32 MB
__device__ float g_k[S_ * NKV_ * HD_];    // [S][NKV][HD]   8 MB
__device__ float g_v[S_ * NKV_ * HD_];    // [S][NKV][HD]   8 MB
__device__ float g_attn[S_ * NH_ * HD_];  // [S][NH][HD]   32 MB

// ---------------------------------------------------------------------------
// SGEMM: C[M,N] = A[M,K] @ B[N,K]^T + bias[N]
// BM=BN=128, BK=16, TM=TN=8, 256 threads. M,N multiples of 128, K of 16.
// ---------------------------------------------------------------------------
#define BM 128
#define BN 128
#define BK 16
#define ASTR (BM + 4)

__global__ __launch_bounds__(256, 2)
void sgemm_bias(int M, int N, int K,
                const float* __restrict__ A,
                const float* __restrict__ B,
                const float* __restrict__ bias,
                float* __restrict__ C)
{
    __shared__ float As[BK][ASTR];
    __shared__ float Bs[BK][ASTR];

    const int tid = threadIdx.x;
    const int bm = blockIdx.y * BM;
    const int bn = blockIdx.x * BN;

    const int lr = tid >> 2;          // 0..63 (load row)
    const int lc = (tid & 3) * 4;     // 0,4,8,12 (load col, float4)
    const int tr = tid >> 4;          // 0..15 (compute row group)
    const int tc = tid & 15;          // 0..15 (compute col group)

    const float* Ab = A + (size_t)bm * K;
    const float* Bb = B + (size_t)bn * K;

    float acc[8][8];
#pragma unroll
    for (int i = 0; i < 8; i++)
#pragma unroll
        for (int j = 0; j < 8; j++) acc[i][j] = 0.f;

    for (int k0 = 0; k0 < K; k0 += BK) {
#pragma unroll
        for (int r = 0; r < 2; r++) {
            const int row = lr + 64 * r;
            float4 a = *(const float4*)(Ab + (size_t)row * K + k0 + lc);
            As[lc + 0][row] = a.x;
            As[lc + 1][row] = a.y;
            As[lc + 2][row] = a.z;
            As[lc + 3][row] = a.w;
            float4 b = *(const float4*)(Bb + (size_t)row * K + k0 + lc);
            Bs[lc + 0][row] = b.x;
            Bs[lc + 1][row] = b.y;
            Bs[lc + 2][row] = b.z;
            Bs[lc + 3][row] = b.w;
        }
        __syncthreads();

#pragma unroll
        for (int kk = 0; kk < BK; kk++) {
            float a[8], b[8];
            *(float4*)&a[0] = *(const float4*)&As[kk][tr * 8];
            *(float4*)&a[4] = *(const float4*)&As[kk][tr * 8 + 4];
            *(float4*)&b[0] = *(const float4*)&Bs[kk][tc * 8];
            *(float4*)&b[4] = *(const float4*)&Bs[kk][tc * 8 + 4];
#pragma unroll
            for (int i = 0; i < 8; i++)
#pragma unroll
                for (int j = 0; j < 8; j++)
                    acc[i][j] += a[i] * b[j];
        }
        __syncthreads();
    }

    // epilogue: + bias, vectorized store
    float bv[8];
#pragma unroll
    for (int j = 0; j < 8; j++) bv[j] = bias[bn + tc * 8 + j];

#pragma unroll
    for (int i = 0; i < 8; i++) {
        const int row = bm + tr * 8 + i;
        float* dst = C + (size_t)row * N + bn + tc * 8;
#pragma unroll
        for (int j = 0; j < 8; j += 4) {
            float4 v;
            v.x = acc[i][j + 0] + bv[j + 0];
            v.y = acc[i][j + 1] + bv[j + 1];
            v.z = acc[i][j + 2] + bv[j + 2];
            v.w = acc[i][j + 3] + bv[j + 3];
            *(float4*)(dst + j) = v;
        }
    }
}

// ---------------------------------------------------------------------------
// Fused per-head LayerNorm (biased var) + RoPE, in place on [S][H][HD].
// One block per token s; 128 threads (one per HD dim); loop over H heads.
// Trig computed once per (s,d) and reused across heads.
// ---------------------------------------------------------------------------
__global__ __launch_bounds__(128)
void ln_rope_kernel(float* __restrict__ data,
                    const float* __restrict__ gw,
                    const float* __restrict__ bw,
                    int H)
{
    const int s = blockIdx.x;
    const int d = threadIdx.x;            // 0..127
    __shared__ float red[8];
    __shared__ float xs[HD_];

    const int dd = d & 63;
    const float inv = exp2f(-(float)dd * (LOG2_THETA / 64.0f));
    const float th = (float)s * inv;
    float sn, cs;
    sincosf(th, &sn, &cs);

    const float gv = gw[d];
    const float bv = bw[d];
    const int lane = d & 31;
    const int w = d >> 5;

    for (int h = 0; h < H; h++) {
        float* x = data + ((size_t)s * H + h) * HD_;
        const float v = x[d];
        float s1 = v, s2 = v * v;
#pragma unroll
        for (int off = 16; off > 0; off >>= 1) {
            s1 += __shfl_xor_sync(0xffffffffu, s1, off);
            s2 += __shfl_xor_sync(0xffffffffu, s2, off);
        }
        if (lane == 0) { red[w] = s1; red[4 + w] = s2; }
        __syncthreads();
        const float sum = red[0] + red[1] + red[2] + red[3];
        const float sq  = red[4] + red[5] + red[6] + red[7];
        const float mu  = sum * (1.0f / HD_);
        const float var = sq * (1.0f / HD_) - mu * mu;
        const float r   = rsqrtf(var + EPS_);
        const float xn  = (v - mu) * r * gv + bv;
        xs[d] = xn;
        __syncthreads();
        const float other = (d < 64) ? -xs[d + 64] : xs[d - 64];
        x[d] = xn * cs + other * sn;
        __syncthreads();
    }
}

// ---------------------------------------------------------------------------
// Causal GQA flash attention, fp32.
// Grid (S/64, NH), 128 threads. Br=Bc=64.
// Thread layout: ty=tid>>3 (0..15), tx=tid&7 (0..7).
//   rows:  i*16+ty (i<4)   cols: j*8+tx (j<8)   O dims: tx*16+c (c<16)
// ---------------------------------------------------------------------------
#define BR 64
#define BC 64
#define QSTR 132
#define PSTR 72
#define FLASH_SMEM ((3 * BC * QSTR + BR * PSTR) * 4)

__global__ __launch_bounds__(128)
void flash_kernel(const float* __restrict__ Q,
                  const float* __restrict__ K,
                  const float* __restrict__ V,
                  float* __restrict__ O)
{
    extern __shared__ float sh[];
    float* Qs = sh;                       // [64][QSTR]
    float* Ks = Qs + BR * QSTR;           // [64][QSTR]
    float* Vs = Ks + BC * QSTR;           // [64][QSTR]
    float* Ps = Vs + BC * QSTR;           // [64][PSTR]

    const int qb = blockIdx.x;
    const int h = blockIdx.y;
    const int kvh = h / (NH_ / NKV_);
    const int q0 = qb * BR;
    const int tid = threadIdx.x;
    const int ty = tid >> 3;
    const int tx = tid & 7;

    // load Q block (rows q0..q0+63)
    {
        const int r = tid >> 1;
        const int half = (tid & 1) * 64;
        const float* src = Q + ((size_t)(q0 + r) * NH_ + h) * HD_ + half;
        float* dst = Qs + r * QSTR + half;
#pragma unroll
        for (int i = 0; i < 16; i++)
            *(float4*)(dst + i * 4) = *(const float4*)(src + i * 4);
    }

    float m[4], l[4], o[4][16];
#pragma unroll
    for (int i = 0; i < 4; i++) {
        m[i] = -1e30f; l[i] = 0.f;
#pragma unroll
        for (int c = 0; c < 16; c++) o[i][c] = 0.f;
    }

    const int nkv = qb + 1;
    for (int kb = 0; kb < nkv; kb++) {
        const int k0 = kb * BC;
        __syncthreads();   // Qs loaded / previous PV done
        {
            const int r = tid >> 1;
            const int half = (tid & 1) * 64;
            const float* ks = K + ((size_t)(k0 + r) * NKV_ + kvh) * HD_ + half;
            const float* vs = V + ((size_t)(k0 + r) * NKV_ + kvh) * HD_ + half;
            float* kd = Ks + r * QSTR + half;
            float* vd = Vs + r * QSTR + half;
#pragma unroll
            for (int i = 0; i < 16; i++) {
                *(float4*)(kd + i * 4) = *(const float4*)(ks + i * 4);
                *(float4*)(vd + i * 4) = *(const float4*)(vs + i * 4);
            }
        }
        __syncthreads();

        // ---- scores: S = Q @ K^T ----
        float acc[4][8];
#pragma unroll
        for (int i = 0; i < 4; i++)
#pragma unroll
            for (int j = 0; j < 8; j++) acc[i][j] = 0.f;

#pragma unroll 2
        for (int d0 = 0; d0 < HD_; d0 += 4) {
            float4 qv[4], kv[8];
#pragma unroll
            for (int i = 0; i < 4; i++)
                qv[i] = *(const float4*)(Qs + (i * 16 + ty) * QSTR + d0);
#pragma unroll
            for (int j = 0; j < 8; j++)
                kv[j] = *(const float4*)(Ks + (j * 8 + tx) * QSTR + d0);
#pragma unroll
            for (int i = 0; i < 4; i++)
#pragma unroll
                for (int j = 0; j < 8; j++) {
                    acc[i][j] += qv[i].x * kv[j].x;
                    acc[i][j] += qv[i].y * kv[j].y;
                    acc[i][j] += qv[i].z * kv[j].z;
                    acc[i][j] += qv[i].w * kv[j].w;
                }
        }

        // ---- online softmax ----
        const bool diag = (kb == qb);
#pragma unroll
        for (int i = 0; i < 4; i++) {
            const int qr = q0 + i * 16 + ty;
            float mx = -1e30f;
#pragma unroll
            for (int j = 0; j < 8; j++) {
                float v = acc[i][j] * SCALE_;
                if (diag && (k0 + j * 8 + tx) > qr) v = -1e30f;
                acc[i][j] = v;
                mx = fmaxf(mx, v);
            }
            mx = fmaxf(mx, __shfl_xor_sync(0xffffffffu, mx, 1));
            mx = fmaxf(mx, __shfl_xor_sync(0xffffffffu, mx, 2));
            mx = fmaxf(mx, __shfl_xor_sync(0xffffffffu, mx, 4));
            const float mnew = fmaxf(m[i], mx);
            const float alpha = __expf(m[i] - mnew);
            m[i] = mnew;
            float rs = 0.f;
#pragma unroll
            for (int j = 0; j < 8; j++) {
                const float p = __expf(acc[i][j] - mnew);
                acc[i][j] = p;
                rs += p;
            }
            rs += __shfl_xor_sync(0xffffffffu, rs, 1);
            rs += __shfl_xor_sync(0xffffffffu, rs, 2);
            rs += __shfl_xor_sync(0xffffffffu, rs, 4);
            l[i] = l[i] * alpha + rs;
#pragma unroll
            for (int c = 0; c < 16; c++) o[i][c] *= alpha;
#pragma unroll
            for (int j = 0; j < 8; j++)
                Ps[(i * 16 + ty) * PSTR + j * 8 + tx] = acc[i][j];
        }
        __syncthreads();

        // ---- O += P @ V ----
#pragma unroll 2
        for (int j4 = 0; j4 < BC; j4 += 4) {
            float pr[4][4];
#pragma unroll
            for (int i = 0; i < 4; i++) {
                float4 pv = *(const float4*)(Ps + (i * 16 + ty) * PSTR + j4);
                pr[i][0] = pv.x; pr[i][1] = pv.y; pr[i][2] = pv.z; pr[i][3] = pv.w;
            }
#pragma unroll
            for (int jj = 0; jj < 4; jj++) {
                float4 vv[4];
#pragma unroll
                for (int c4 = 0; c4 < 4; c4++)
                    vv[c4] = *(const float4*)(Vs + (j4 + jj) * QSTR + tx * 16 + c4 * 4);
#pragma unroll
                for (int i = 0; i < 4; i++) {
                    const float p = pr[i][jj];
#pragma unroll
                    for (int c4 = 0; c4 < 4; c4++) {
                        o[i][c4 * 4 + 0] += p * vv[c4].x;
                        o[i][c4 * 4 + 1] += p * vv[c4].y;
                        o[i][c4 * 4 + 2] += p * vv[c4].z;
                        o[i][c4 * 4 + 3] += p * vv[c4].w;
                    }
                }
            }
        }
    }

    // ---- epilogue: O /= l, write [S][NH][HD] ----
#pragma unroll
    for (int i = 0; i < 4; i++) {
        const float inv = 1.0f / l[i];
        const int qr = q0 + i * 16 + ty;
        float* dst = O + ((size_t)qr * NH_ + h) * HD_ + tx * 16;
#pragma unroll
        for (int c4 = 0; c4 < 4; c4++) {
            float4 w;
            w.x = o[i][c4 * 4 + 0] * inv;
            w.y = o[i][c4 * 4 + 1] * inv;
            w.z = o[i][c4 * 4 + 2] * inv;
            w.w = o[i][c4 * 4 + 3] * inv;
            *(float4*)(dst + c4 * 4) = w;
        }
    }
}

// ---------------------------------------------------------------------------
// Launch
// ---------------------------------------------------------------------------
extern "C" void kernel_launch(void* const* d_in, const int* in_sizes, int n_in,
                              void* d_out, int out_size)
{
    const float* x   = (const float*)d_in[0];
    const float* Wq  = (const float*)d_in[1];
    const float* bq  = (const float*)d_in[2];
    const float* Wk  = (const float*)d_in[3];
    const float* bk  = (const float*)d_in[4];
    const float* Wv  = (const float*)d_in[5];
    const float* bv  = (const float*)d_in[6];
    const float* Wo  = (const float*)d_in[7];
    const float* bo  = (const float*)d_in[8];
    const float* qng = (const float*)d_in[9];
    const float* qnb = (const float*)d_in[10];
    const float* kng = (const float*)d_in[11];
    const float* knb = (const float*)d_in[12];
    float* out = (float*)d_out;

    float *qp, *kp, *vp, *ap;
    cudaGetSymbolAddress((void**)&qp, g_q);
    cudaGetSymbolAddress((void**)&kp, g_k);
    cudaGetSymbolAddress((void**)&vp, g_v);
    cudaGetSymbolAddress((void**)&ap, g_attn);

    // QKV projections
    sgemm_bias<<<dim3(HID_ / BN, S_ / BM), 256>>>(S_, NH_ * HD_, HID_, x, Wq, bq, qp);
    sgemm_bias<<<dim3((NKV_ * HD_) / BN, S_ / BM), 256>>>(S_, NKV_ * HD_, HID_, x, Wk, bk, kp);
    sgemm_bias<<<dim3((NKV_ * HD_) / BN, S_ / BM), 256>>>(S_, NKV_ * HD_, HID_, x, Wv, bv, vp);

    // per-head LayerNorm + RoPE (in place)
    ln_rope_kernel<<<S_, HD_>>>(qp, qng, qnb, NH_);
    ln_rope_kernel<<<S_, HD_>>>(kp, kng, knb, NKV_);

    // causal GQA flash attention
    cudaFuncSetAttribute(flash_kernel, cudaFuncAttributeMaxDynamicSharedMemorySize,
                         FLASH_SMEM);
    flash_kernel<<<dim3(S_ / BR, NH_), 128, FLASH_SMEM>>>(qp, kp, vp, ap);

    // output projection
    sgemm_bias<<<dim3(HID_ / BN, S_ / BM), 256>>>(S_, HID_, HID_, ap, Wo, bo, out);
}

// round 8
// speedup vs baseline: 1.6328x; 1.6328x over previous
#include <cuda_runtime.h>
#include <cuda_bf16.h>
#include <math.h>
#include <cstdint>

// Problem constants
#define S_    2048
#define HID_  4096
#define NH_   32
#define NKV_  8
#define HD_   128
#define EPS_  1e-5f
#define SCALE_ 0.088388347648318447f
#define LOG2_THETA 18.931568569324174f

// ---------------------------------------------------------------------------
// Scratch (device globals; no allocation allowed)
// ---------------------------------------------------------------------------
__device__ float g_q[S_ * NH_ * HD_];
__device__ float g_k[S_ * NKV_ * HD_];
__device__ float g_v[S_ * NKV_ * HD_];
__device__ float g_attn[S_ * NH_ * HD_];

// ---------------------------------------------------------------------------
// Helpers
// ---------------------------------------------------------------------------
__device__ __forceinline__ uint32_t smem_u32(const void* p) {
    uint32_t a;
    asm("{ .reg .u64 t; cvta.to.shared.u64 t, %1; cvt.u32.u64 %0, t; }"
        : "=r"(a) : "l"(p));
    return a;
}

__device__ __forceinline__ void ldsm4(uint32_t* r, uint32_t addr) {
    asm volatile("ldmatrix.sync.aligned.m8n8.x4.shared.b16 {%0,%1,%2,%3}, [%4];"
                 : "=r"(r[0]), "=r"(r[1]), "=r"(r[2]), "=r"(r[3]) : "r"(addr));
}

__device__ __forceinline__ void mma_bf16(float* d, const uint32_t* a, const uint32_t* b) {
    asm volatile(
        "mma.sync.aligned.m16n8k16.row.col.f32.bf16.bf16.f32 "
        "{%0,%1,%2,%3}, {%4,%5,%6,%7}, {%8,%9}, {%0,%1,%2,%3};"
        : "+f"(d[0]), "+f"(d[1]), "+f"(d[2]), "+f"(d[3])
        : "r"(a[0]), "r"(a[1]), "r"(a[2]), "r"(a[3]), "r"(b[0]), "r"(b[1]));
}

__device__ __forceinline__ uint32_t pk(__nv_bfloat16 a, __nv_bfloat16 b) {
    __nv_bfloat162 t = __halves2bfloat162(a, b);
    return *reinterpret_cast<uint32_t*>(&t);
}

// Split float4 into bf16 hi (8B) + bf16 lo (8B)
__device__ __forceinline__ void split4_bf(float4 v, uint2& hi, uint2& lo) {
    __nv_bfloat16 h0 = __float2bfloat16_rn(v.x);
    __nv_bfloat16 h1 = __float2bfloat16_rn(v.y);
    __nv_bfloat16 h2 = __float2bfloat16_rn(v.z);
    __nv_bfloat16 h3 = __float2bfloat16_rn(v.w);
    __nv_bfloat16 l0 = __float2bfloat16_rn(v.x - __bfloat162float(h0));
    __nv_bfloat16 l1 = __float2bfloat16_rn(v.y - __bfloat162float(h1));
    __nv_bfloat16 l2 = __float2bfloat16_rn(v.z - __bfloat162float(h2));
    __nv_bfloat16 l3 = __float2bfloat16_rn(v.w - __bfloat162float(h3));
    hi.x = pk(h0, h1); hi.y = pk(h2, h3);
    lo.x = pk(l0, l1); lo.y = pk(l2, l3);
}

// ---------------------------------------------------------------------------
// bf16 3-term split GEMM via mma.sync: C[M,N] = A[M,K] @ B[N,K]^T + bias
// CTA tile 128x128, BK=32, 256 threads (8 warps, 2x4, warp tile 64x32).
// SMEM per buffer: A_hi(8K) A_lo(8K) B_hi(8K) B_lo(8K); double buffered.
// Rows are 64B (32 bf16) with XOR swizzle: chunk ^= (row & 3).
// ---------------------------------------------------------------------------
#define GBM 128
#define GBN 128
#define GBK 32
#define REG_A_LO 8192
#define REG_B_HI 16384
#define REG_B_LO 24576
#define BUF_B    32768
#define GEMM_SMEM (2 * BUF_B)

__device__ __forceinline__ void stage_store(char* smem, uint32_t bufoff,
                                            const float4* va, const float4* vb,
                                            int tid) {
#pragma unroll
    for (int it = 0; it < 4; it++) {
        const int idx = it * 256 + tid;
        const int r = idx >> 3;
        const int c4 = idx & 7;
        const uint32_t sw =
            (uint32_t)r * 64 + ((((uint32_t)(c4 >> 1)) ^ (r & 3)) << 4) + (c4 & 1) * 8;
        uint2 hi, lo;
        split4_bf(va[it], hi, lo);
        *(uint2*)(smem + bufoff + sw) = hi;
        *(uint2*)(smem + bufoff + REG_A_LO + sw) = lo;
        split4_bf(vb[it], hi, lo);
        *(uint2*)(smem + bufoff + REG_B_HI + sw) = hi;
        *(uint2*)(smem + bufoff + REG_B_LO + sw) = lo;
    }
}

__global__ __launch_bounds__(256)
void gemm_bf16x3(int M, int N, int K,
                 const float* __restrict__ A,
                 const float* __restrict__ B,
                 const float* __restrict__ bias,
                 float* __restrict__ C)
{
    extern __shared__ __align__(1024) char smem[];
    const uint32_t sbase = smem_u32(smem);
    const int tid = threadIdx.x;
    const int wid = tid >> 5;
    const int lane = tid & 31;
    const int warp_m = wid >> 2;      // 0..1
    const int warp_n = wid & 3;       // 0..3
    const int bm = blockIdx.y * GBM;
    const int bn = blockIdx.x * GBN;

    // ldmatrix per-lane bases.
    // A (x4): mat = lane>>3; matrices: (rows0-7,kh0)(rows8-15,kh0)(rows0-7,kh1)(rows8-15,kh1)
    const int l7 = lane & 7;
    const int l3 = lane & 3;
    const int amat = lane >> 3;
    const uint32_t a_row64 = (uint32_t)(warp_m * 64 + ((amat & 1) << 3) + l7) * 64;
    const int a_kh = amat >> 1;
    // B (x4 over two n8 blocks): khalf = (lane>>3)&1, nt-pair select = lane>>4
    const int b_kh = (lane >> 3) & 1;
    const uint32_t b_row64 = (uint32_t)(warp_n * 32 + ((lane >> 4) << 3) + l7) * 64;

    const float* Abase = A + (size_t)bm * K;
    const float* Bbase = B + (size_t)bn * K;

    float acc[4][4][4];
#pragma unroll
    for (int i = 0; i < 4; i++)
#pragma unroll
        for (int j = 0; j < 4; j++)
#pragma unroll
            for (int c = 0; c < 4; c++) acc[i][j][c] = 0.f;

    const int NB = K / GBK;

    float4 va[4], vb[4];
    // prologue: load + stage kb=0
#pragma unroll
    for (int it = 0; it < 4; it++) {
        const int idx = it * 256 + tid;
        const int r = idx >> 3;
        const int c4 = idx & 7;
        va[it] = *(const float4*)(Abase + (size_t)r * K + c4 * 4);
        vb[it] = *(const float4*)(Bbase + (size_t)r * K + c4 * 4);
    }
    stage_store(smem, 0, va, vb, tid);
    __syncthreads();

    for (int kb = 0; kb < NB; kb++) {
        const uint32_t bufc = sbase + (kb & 1) * BUF_B;

        // prefetch next K-block into registers (latency hidden by MMA)
        if (kb + 1 < NB) {
            const int k0 = (kb + 1) * GBK;
#pragma unroll
            for (int it = 0; it < 4; it++) {
                const int idx = it * 256 + tid;
                const int r = idx >> 3;
                const int c4 = idx & 7;
                va[it] = *(const float4*)(Abase + (size_t)r * K + k0 + c4 * 4);
                vb[it] = *(const float4*)(Bbase + (size_t)r * K + k0 + c4 * 4);
            }
        }

        // MMA over this K-block (two k16 steps)
#pragma unroll
        for (int ks = 0; ks < 2; ks++) {
            uint32_t ah[4][4], al[4][4];
            const uint32_t a_swoff = (uint32_t)(((ks * 2 + a_kh) ^ l3) << 4);
#pragma unroll
            for (int mt = 0; mt < 4; mt++) {
                const uint32_t addr = bufc + a_row64 + (uint32_t)mt * 1024 + a_swoff;
                ldsm4(ah[mt], addr);
                ldsm4(al[mt], addr + REG_A_LO);
            }
            uint32_t bh[2][4], bl[2][4];
            const uint32_t b_swoff = (uint32_t)(((ks * 2 + b_kh) ^ l3) << 4);
#pragma unroll
            for (int p = 0; p < 2; p++) {
                const uint32_t addr = bufc + REG_B_HI + b_row64 + (uint32_t)p * 1024 + b_swoff;
                ldsm4(bh[p], addr);
                ldsm4(bl[p], addr + (REG_B_LO - REG_B_HI));
            }
#pragma unroll
            for (int mt = 0; mt < 4; mt++)
#pragma unroll
                for (int nt = 0; nt < 4; nt++) {
                    const uint32_t* bhp = &bh[nt >> 1][(nt & 1) * 2];
                    const uint32_t* blp = &bl[nt >> 1][(nt & 1) * 2];
                    mma_bf16(acc[mt][nt], ah[mt], bhp);   // hi*hi
                    mma_bf16(acc[mt][nt], ah[mt], blp);   // hi*lo
                    mma_bf16(acc[mt][nt], al[mt], bhp);   // lo*hi
                }
        }

        if (kb + 1 < NB)
            stage_store(smem, ((kb + 1) & 1) * BUF_B, va, vb, tid);
        __syncthreads();
    }

    // epilogue: + bias, store fp32
    const int g = lane >> 2;
    const int t = lane & 3;
#pragma unroll
    for (int nt = 0; nt < 4; nt++) {
        const int col = bn + warp_n * 32 + nt * 8 + 2 * t;
        const float b0 = bias[col];
        const float b1 = bias[col + 1];
#pragma unroll
        for (int mt = 0; mt < 4; mt++) {
            const int row = bm + warp_m * 64 + mt * 16 + g;
            float2 v0, v1;
            v0.x = acc[mt][nt][0] + b0;
            v0.y = acc[mt][nt][1] + b1;
            v1.x = acc[mt][nt][2] + b0;
            v1.y = acc[mt][nt][3] + b1;
            *(float2*)(C + (size_t)row * N + col) = v0;
            *(float2*)(C + (size_t)(row + 8) * N + col) = v1;
        }
    }
}

// ---------------------------------------------------------------------------
// Fused per-head LayerNorm + RoPE (unchanged, passing)
// ---------------------------------------------------------------------------
__global__ __launch_bounds__(128)
void ln_rope_kernel(float* __restrict__ data,
                    const float* __restrict__ gw,
                    const float* __restrict__ bw,
                    int H)
{
    const int s = blockIdx.x;
    const int d = threadIdx.x;
    __shared__ float red[8];
    __shared__ float xs[HD_];

    const int dd = d & 63;
    const float inv = exp2f(-(float)dd * (LOG2_THETA / 64.0f));
    const float th = (float)s * inv;
    float sn, cs;
    sincosf(th, &sn, &cs);

    const float gv = gw[d];
    const float bv = bw[d];
    const int lane = d & 31;
    const int w = d >> 5;

    for (int h = 0; h < H; h++) {
        float* x = data + ((size_t)s * H + h) * HD_;
        const float v = x[d];
        float s1 = v, s2 = v * v;
#pragma unroll
        for (int off = 16; off > 0; off >>= 1) {
            s1 += __shfl_xor_sync(0xffffffffu, s1, off);
            s2 += __shfl_xor_sync(0xffffffffu, s2, off);
        }
        if (lane == 0) { red[w] = s1; red[4 + w] = s2; }
        __syncthreads();
        const float sum = red[0] + red[1] + red[2] + red[3];
        const float sq  = red[4] + red[5] + red[6] + red[7];
        const float mu  = sum * (1.0f / HD_);
        const float var = sq * (1.0f / HD_) - mu * mu;
        const float r   = rsqrtf(var + EPS_);
        const float xn  = (v - mu) * r * gv + bv;
        xs[d] = xn;
        __syncthreads();
        const float other = (d < 64) ? -xs[d + 64] : xs[d - 64];
        x[d] = xn * cs + other * sn;
        __syncthreads();
    }
}

// ---------------------------------------------------------------------------
// Causal GQA flash attention, fp32 SIMT (unchanged, passing)
// ---------------------------------------------------------------------------
#define BR 64
#define BC 64
#define QSTR 132
#define PSTR 72
#define FLASH_SMEM ((3 * BC * QSTR + BR * PSTR) * 4)

__global__ __launch_bounds__(128)
void flash_kernel(const float* __restrict__ Q,
                  const float* __restrict__ K,
                  const float* __restrict__ V,
                  float* __restrict__ O)
{
    extern __shared__ float sh[];
    float* Qs = sh;
    float* Ks = Qs + BR * QSTR;
    float* Vs = Ks + BC * QSTR;
    float* Ps = Vs + BC * QSTR;

    const int qb = blockIdx.x;
    const int h = blockIdx.y;
    const int kvh = h / (NH_ / NKV_);
    const int q0 = qb * BR;
    const int tid = threadIdx.x;
    const int ty = tid >> 3;
    const int tx = tid & 7;

    {
        const int r = tid >> 1;
        const int half = (tid & 1) * 64;
        const float* src = Q + ((size_t)(q0 + r) * NH_ + h) * HD_ + half;
        float* dst = Qs + r * QSTR + half;
#pragma unroll
        for (int i = 0; i < 16; i++)
            *(float4*)(dst + i * 4) = *(const float4*)(src + i * 4);
    }

    float m[4], l[4], o[4][16];
#pragma unroll
    for (int i = 0; i < 4; i++) {
        m[i] = -1e30f; l[i] = 0.f;
#pragma unroll
        for (int c = 0; c < 16; c++) o[i][c] = 0.f;
    }

    const int nkv = qb + 1;
    for (int kb = 0; kb < nkv; kb++) {
        const int k0 = kb * BC;
        __syncthreads();
        {
            const int r = tid >> 1;
            const int half = (tid & 1) * 64;
            const float* ks = K + ((size_t)(k0 + r) * NKV_ + kvh) * HD_ + half;
            const float* vs = V + ((size_t)(k0 + r) * NKV_ + kvh) * HD_ + half;
            float* kd = Ks + r * QSTR + half;
            float* vd = Vs + r * QSTR + half;
#pragma unroll
            for (int i = 0; i < 16; i++) {
                *(float4*)(kd + i * 4) = *(const float4*)(ks + i * 4);
                *(float4*)(vd + i * 4) = *(const float4*)(vs + i * 4);
            }
        }
        __syncthreads();

        float acc[4][8];
#pragma unroll
        for (int i = 0; i < 4; i++)
#pragma unroll
            for (int j = 0; j < 8; j++) acc[i][j] = 0.f;

#pragma unroll 2
        for (int d0 = 0; d0 < HD_; d0 += 4) {
            float4 qv[4], kv[8];
#pragma unroll
            for (int i = 0; i < 4; i++)
                qv[i] = *(const float4*)(Qs + (i * 16 + ty) * QSTR + d0);
#pragma unroll
            for (int j = 0; j < 8; j++)
                kv[j] = *(const float4*)(Ks + (j * 8 + tx) * QSTR + d0);
#pragma unroll
            for (int i = 0; i < 4; i++)
#pragma unroll
                for (int j = 0; j < 8; j++) {
                    acc[i][j] += qv[i].x * kv[j].x;
                    acc[i][j] += qv[i].y * kv[j].y;
                    acc[i][j] += qv[i].z * kv[j].z;
                    acc[i][j] += qv[i].w * kv[j].w;
                }
        }

        const bool diag = (kb == qb);
#pragma unroll
        for (int i = 0; i < 4; i++) {
            const int qr = q0 + i * 16 + ty;
            float mx = -1e30f;
#pragma unroll
            for (int j = 0; j < 8; j++) {
                float v = acc[i][j] * SCALE_;
                if (diag && (k0 + j * 8 + tx) > qr) v = -1e30f;
                acc[i][j] = v;
                mx = fmaxf(mx, v);
            }
            mx = fmaxf(mx, __shfl_xor_sync(0xffffffffu, mx, 1));
            mx = fmaxf(mx, __shfl_xor_sync(0xffffffffu, mx, 2));
            mx = fmaxf(mx, __shfl_xor_sync(0xffffffffu, mx, 4));
            const float mnew = fmaxf(m[i], mx);
            const float alpha = __expf(m[i] - mnew);
            m[i] = mnew;
            float rs = 0.f;
#pragma unroll
            for (int j = 0; j < 8; j++) {
                const float p = __expf(acc[i][j] - mnew);
                acc[i][j] = p;
                rs += p;
            }
            rs += __shfl_xor_sync(0xffffffffu, rs, 1);
            rs += __shfl_xor_sync(0xffffffffu, rs, 2);
            rs += __shfl_xor_sync(0xffffffffu, rs, 4);
            l[i] = l[i] * alpha + rs;
#pragma unroll
            for (int c = 0; c < 16; c++) o[i][c] *= alpha;
#pragma unroll
            for (int j = 0; j < 8; j++)
                Ps[(i * 16 + ty) * PSTR + j * 8 + tx] = acc[i][j];
        }
        __syncthreads();

#pragma unroll 2
        for (int j4 = 0; j4 < BC; j4 += 4) {
            float pr[4][4];
#pragma unroll
            for (int i = 0; i < 4; i++) {
                float4 pv = *(const float4*)(Ps + (i * 16 + ty) * PSTR + j4);
                pr[i][0] = pv.x; pr[i][1] = pv.y; pr[i][2] = pv.z; pr[i][3] = pv.w;
            }
#pragma unroll
            for (int jj = 0; jj < 4; jj++) {
                float4 vv[4];
#pragma unroll
                for (int c4 = 0; c4 < 4; c4++)
                    vv[c4] = *(const float4*)(Vs + (j4 + jj) * QSTR + tx * 16 + c4 * 4);
#pragma unroll
                for (int i = 0; i < 4; i++) {
                    const float p = pr[i][jj];
#pragma unroll
                    for (int c4 = 0; c4 < 4; c4++) {
                        o[i][c4 * 4 + 0] += p * vv[c4].x;
                        o[i][c4 * 4 + 1] += p * vv[c4].y;
                        o[i][c4 * 4 + 2] += p * vv[c4].z;
                        o[i][c4 * 4 + 3] += p * vv[c4].w;
                    }
                }
            }
        }
    }

#pragma unroll
    for (int i = 0; i < 4; i++) {
        const float inv = 1.0f / l[i];
        float* dst = O + ((size_t)(q0 + i * 16 + ty) * NH_ + h) * HD_ + tx * 16;
#pragma unroll
        for (int c4 = 0; c4 < 4; c4++) {
            float4 w;
            w.x = o[i][c4 * 4 + 0] * inv;
            w.y = o[i][c4 * 4 + 1] * inv;
            w.z = o[i][c4 * 4 + 2] * inv;
            w.w = o[i][c4 * 4 + 3] * inv;
            *(float4*)(dst + c4 * 4) = w;
        }
    }
}

// ---------------------------------------------------------------------------
// Launch
// ---------------------------------------------------------------------------
extern "C" void kernel_launch(void* const* d_in, const int* in_sizes, int n_in,
                              void* d_out, int out_size)
{
    const float* x   = (const float*)d_in[0];
    const float* Wq  = (const float*)d_in[1];
    const float* bq  = (const float*)d_in[2];
    const float* Wk  = (const float*)d_in[3];
    const float* bk  = (const float*)d_in[4];
    const float* Wv  = (const float*)d_in[5];
    const float* bv  = (const float*)d_in[6];
    const float* Wo  = (const float*)d_in[7];
    const float* bo  = (const float*)d_in[8];
    const float* qng = (const float*)d_in[9];
    const float* qnb = (const float*)d_in[10];
    const float* kng = (const float*)d_in[11];
    const float* knb = (const float*)d_in[12];
    float* out = (float*)d_out;

    float *qp, *kp, *vp, *ap;
    cudaGetSymbolAddress((void**)&qp, g_q);
    cudaGetSymbolAddress((void**)&kp, g_k);
    cudaGetSymbolAddress((void**)&vp, g_v);
    cudaGetSymbolAddress((void**)&ap, g_attn);

    cudaFuncSetAttribute(gemm_bf16x3, cudaFuncAttributeMaxDynamicSharedMemorySize,
                         GEMM_SMEM);
    cudaFuncSetAttribute(flash_kernel, cudaFuncAttributeMaxDynamicSharedMemorySize,
                         FLASH_SMEM);

    // QKV projections (mma.sync bf16, 3-term split)
    gemm_bf16x3<<<dim3((NH_ * HD_) / GBN, S_ / GBM), 256, GEMM_SMEM>>>(
        S_, NH_ * HD_, HID_, x, Wq, bq, qp);
    gemm_bf16x3<<<dim3((NKV_ * HD_) / GBN, S_ / GBM), 256, GEMM_SMEM>>>(
        S_, NKV_ * HD_, HID_, x, Wk, bk, kp);
    gemm_bf16x3<<<dim3((NKV_ * HD_) / GBN, S_ / GBM), 256, GEMM_SMEM>>>(
        S_, NKV_ * HD_, HID_, x, Wv, bv, vp);

    // per-head LayerNorm + RoPE (in place)
    ln_rope_kernel<<<S_, HD_>>>(qp, qng, qnb, NH_);
    ln_rope_kernel<<<S_, HD_>>>(kp, kng, knb, NKV_);

    // causal GQA flash attention (fp32 SIMT)
    flash_kernel<<<dim3(S_ / BR, NH_), 128, FLASH_SMEM>>>(qp, kp, vp, ap);

    // output projection
    gemm_bf16x3<<<dim3(HID_ / GBN, S_ / GBM), 256, GEMM_SMEM>>>(
        S_, HID_, HID_, ap, Wo, bo, out);
}

// round 9
// speedup vs baseline: 1.7737x; 1.0863x over previous
#include <cuda_runtime.h>
#include <cuda_bf16.h>
#include <math.h>
#include <cstdint>

// Problem constants
#define S_    2048
#define HID_  4096
#define NH_   32
#define NKV_  8
#define HD_   128
#define EPS_  1e-5f
#define SCALE_ 0.088388347648318447f
#define LOG2_THETA 18.931568569324174f

// ---------------------------------------------------------------------------
// Scratch (device globals; no allocation allowed)
// ---------------------------------------------------------------------------
__device__ float g_q[S_ * NH_ * HD_];
__device__ float g_k[S_ * NKV_ * HD_];
__device__ float g_v[S_ * NKV_ * HD_];
// pre-split bf16 hi/lo operands
__device__ __nv_bfloat16 g_xh[S_ * HID_],  g_xl[S_ * HID_];
__device__ __nv_bfloat16 g_wqh[NH_ * HD_ * HID_],  g_wql[NH_ * HD_ * HID_];
__device__ __nv_bfloat16 g_wkh[NKV_ * HD_ * HID_], g_wkl[NKV_ * HD_ * HID_];
__device__ __nv_bfloat16 g_wvh[NKV_ * HD_ * HID_], g_wvl[NKV_ * HD_ * HID_];
__device__ __nv_bfloat16 g_woh[HID_ * HID_], g_wol[HID_ * HID_];
__device__ __nv_bfloat16 g_aoh[S_ * HID_],  g_aol[S_ * HID_];

// ---------------------------------------------------------------------------
// Helpers
// ---------------------------------------------------------------------------
__device__ __forceinline__ uint32_t smem_u32(const void* p) {
    uint32_t a;
    asm("{ .reg .u64 t; cvta.to.shared.u64 t, %1; cvt.u32.u64 %0, t; }"
        : "=r"(a) : "l"(p));
    return a;
}

__device__ __forceinline__ void ldsm4(uint32_t* r, uint32_t addr) {
    asm volatile("ldmatrix.sync.aligned.m8n8.x4.shared.b16 {%0,%1,%2,%3}, [%4];"
                 : "=r"(r[0]), "=r"(r[1]), "=r"(r[2]), "=r"(r[3]) : "r"(addr));
}

__device__ __forceinline__ void mma_bf16(float* d, const uint32_t* a, const uint32_t* b) {
    asm volatile(
        "mma.sync.aligned.m16n8k16.row.col.f32.bf16.bf16.f32 "
        "{%0,%1,%2,%3}, {%4,%5,%6,%7}, {%8,%9}, {%0,%1,%2,%3};"
        : "+f"(d[0]), "+f"(d[1]), "+f"(d[2]), "+f"(d[3])
        : "r"(a[0]), "r"(a[1]), "r"(a[2]), "r"(a[3]), "r"(b[0]), "r"(b[1]));
}

__device__ __forceinline__ uint32_t pk(__nv_bfloat16 a, __nv_bfloat16 b) {
    __nv_bfloat162 t = __halves2bfloat162(a, b);
    return *reinterpret_cast<uint32_t*>(&t);
}

__device__ __forceinline__ void split4_bf(float4 v, uint2& hi, uint2& lo) {
    __nv_bfloat16 h0 = __float2bfloat16_rn(v.x);
    __nv_bfloat16 h1 = __float2bfloat16_rn(v.y);
    __nv_bfloat16 h2 = __float2bfloat16_rn(v.z);
    __nv_bfloat16 h3 = __float2bfloat16_rn(v.w);
    __nv_bfloat16 l0 = __float2bfloat16_rn(v.x - __bfloat162float(h0));
    __nv_bfloat16 l1 = __float2bfloat16_rn(v.y - __bfloat162float(h1));
    __nv_bfloat16 l2 = __float2bfloat16_rn(v.z - __bfloat162float(h2));
    __nv_bfloat16 l3 = __float2bfloat16_rn(v.w - __bfloat162float(h3));
    hi.x = pk(h0, h1); hi.y = pk(h2, h3);
    lo.x = pk(l0, l1); lo.y = pk(l2, l3);
}

// ---------------------------------------------------------------------------
// fp32 -> bf16 hi/lo split (elementwise, vectorized)
// ---------------------------------------------------------------------------
__global__ __launch_bounds__(256)
void split_kernel(const float* __restrict__ in,
                  __nv_bfloat16* __restrict__ hi,
                  __nv_bfloat16* __restrict__ lo, int n4)
{
    const int idx = blockIdx.x * 256 + threadIdx.x;
    if (idx >= n4) return;
    float4 v = ((const float4*)in)[idx];
    uint2 h, l;
    split4_bf(v, h, l);
    ((uint2*)hi)[idx] = h;
    ((uint2*)lo)[idx] = l;
}

// ---------------------------------------------------------------------------
// Pure-bf16 3-term GEMM with cp.async 3-stage pipeline.
// C[M,N] = (Ah+Al)[M,K] @ (Bh+Bl)[N,K]^T + bias  (hi*hi + hi*lo + lo*hi)
// CTA 128x128, BK=32, 256 threads (8 warps 2x4, warp tile 64x32), 2 CTAs/SM.
// Stage: Ah(8K) Al(8K) Bh(8K) Bl(8K) = 32KB; rows 64B, swizzle chunk^= (row&3).
// ---------------------------------------------------------------------------
#define GBM 128
#define GBN 128
#define GBK 32
#define OFF_AL 8192
#define OFF_BH 16384
#define OFF_BL 24576
#define BUF_B  32768
#define NSTAGE 3
#define GEMM_SMEM (NSTAGE * BUF_B)

__device__ __forceinline__ void issue_stage(
    uint32_t sdst,
    const __nv_bfloat16* __restrict__ Ah, const __nv_bfloat16* __restrict__ Al,
    const __nv_bfloat16* __restrict__ Bh, const __nv_bfloat16* __restrict__ Bl,
    int K, int k0, int tid)
{
#pragma unroll
    for (int it = 0; it < 8; it++) {
        const int tile = it >> 1;                 // 0..3 (Ah,Al,Bh,Bl)
        const int c = (it & 1) * 256 + tid;       // 0..511
        const int row = c >> 2;                   // 0..127
        const int col = c & 3;                    // 16B chunk within 64B row
        const uint32_t dst = sdst + tile * 8192 + row * 64
                           + (uint32_t)((col ^ (row & 3)) << 4);
        const __nv_bfloat16* src;
        if (tile == 0)      src = Ah + (size_t)row * K + k0 + col * 8;
        else if (tile == 1) src = Al + (size_t)row * K + k0 + col * 8;
        else if (tile == 2) src = Bh + (size_t)row * K + k0 + col * 8;
        else                src = Bl + (size_t)row * K + k0 + col * 8;
        asm volatile("cp.async.cg.shared.global [%0], [%1], 16;"
                     :: "r"(dst), "l"(src));
    }
}

__global__ __launch_bounds__(256, 2)
void gemm_bf16_pipe(int M, int N, int K,
                    const __nv_bfloat16* __restrict__ Ah,
                    const __nv_bfloat16* __restrict__ Al,
                    const __nv_bfloat16* __restrict__ Bh,
                    const __nv_bfloat16* __restrict__ Bl,
                    const float* __restrict__ bias,
                    float* __restrict__ C)
{
    extern __shared__ __align__(1024) char smem[];
    const uint32_t sbase = smem_u32(smem);
    const int tid = threadIdx.x;
    const int wid = tid >> 5;
    const int lane = tid & 31;
    const int warp_m = wid >> 2;      // 0..1
    const int warp_n = wid & 3;       // 0..3
    const int bm = blockIdx.y * GBM;
    const int bn = blockIdx.x * GBN;

    const __nv_bfloat16* Ahb = Ah + (size_t)bm * K;
    const __nv_bfloat16* Alb = Al + (size_t)bm * K;
    const __nv_bfloat16* Bhb = Bh + (size_t)bn * K;
    const __nv_bfloat16* Blb = Bl + (size_t)bn * K;

    // ldmatrix per-lane bases (same layout as R8, validated)
    const int l7 = lane & 7;
    const int l3 = lane & 3;
    const int amat = lane >> 3;
    const uint32_t a_row64 = (uint32_t)(warp_m * 64 + ((amat & 1) << 3) + l7) * 64;
    const int a_kh = amat >> 1;
    const int b_kh = (lane >> 3) & 1;
    const uint32_t b_row64 = (uint32_t)(warp_n * 32 + ((lane >> 4) << 3) + l7) * 64;

    float acc[4][4][4];
#pragma unroll
    for (int i = 0; i < 4; i++)
#pragma unroll
        for (int j = 0; j < 4; j++)
#pragma unroll
            for (int c = 0; c < 4; c++) acc[i][j][c] = 0.f;

    const int NB = K / GBK;

    // prologue: stages 0,1
    issue_stage(sbase, Ahb, Alb, Bhb, Blb, K, 0, tid);
    asm volatile("cp.async.commit_group;");
    issue_stage(sbase + BUF_B, Ahb, Alb, Bhb, Blb, K, GBK, tid);
    asm volatile("cp.async.commit_group;");

    for (int kb = 0; kb < NB; kb++) {
        asm volatile("cp.async.wait_group 1;");
        __syncthreads();

        const int nk = kb + 2;
        if (nk < NB)
            issue_stage(sbase + (uint32_t)(nk % NSTAGE) * BUF_B,
                        Ahb, Alb, Bhb, Blb, K, nk * GBK, tid);
        asm volatile("cp.async.commit_group;");

        const uint32_t bufc = sbase + (uint32_t)(kb % NSTAGE) * BUF_B;

#pragma unroll
        for (int ks = 0; ks < 2; ks++) {
            const uint32_t a_swoff = (uint32_t)(((ks * 2 + a_kh) ^ l3) << 4);
            const uint32_t b_swoff = (uint32_t)(((ks * 2 + b_kh) ^ l3) << 4);

            uint32_t ah[4][4];
#pragma unroll
            for (int mt = 0; mt < 4; mt++)
                ldsm4(ah[mt], bufc + a_row64 + (uint32_t)mt * 1024 + a_swoff);

            uint32_t bh[2][4], bl[2][4];
#pragma unroll
            for (int p = 0; p < 2; p++) {
                const uint32_t baddr = bufc + OFF_BH + b_row64 + (uint32_t)p * 1024 + b_swoff;
                ldsm4(bh[p], baddr);
                ldsm4(bl[p], baddr + (OFF_BL - OFF_BH));
            }

            // hi*hi and hi*lo
#pragma unroll
            for (int mt = 0; mt < 4; mt++)
#pragma unroll
                for (int nt = 0; nt < 4; nt++) {
                    const uint32_t* bhp = &bh[nt >> 1][(nt & 1) * 2];
                    const uint32_t* blp = &bl[nt >> 1][(nt & 1) * 2];
                    mma_bf16(acc[mt][nt], ah[mt], bhp);
                    mma_bf16(acc[mt][nt], ah[mt], blp);
                }

            // lo*hi (ah dead -> registers reused for al)
            uint32_t al[4][4];
#pragma unroll
            for (int mt = 0; mt < 4; mt++)
                ldsm4(al[mt], bufc + OFF_AL + a_row64 + (uint32_t)mt * 1024 + a_swoff);
#pragma unroll
            for (int mt = 0; mt < 4; mt++)
#pragma unroll
                for (int nt = 0; nt < 4; nt++)
                    mma_bf16(acc[mt][nt], al[mt], &bh[nt >> 1][(nt & 1) * 2]);
        }
    }

    // epilogue: + bias, store fp32
    const int g = lane >> 2;
    const int t = lane & 3;
#pragma unroll
    for (int nt = 0; nt < 4; nt++) {
        const int col = bn + warp_n * 32 + nt * 8 + 2 * t;
        const float b0 = bias[col];
        const float b1 = bias[col + 1];
#pragma unroll
        for (int mt = 0; mt < 4; mt++) {
            const int row = bm + warp_m * 64 + mt * 16 + g;
            float2 v0, v1;
            v0.x = acc[mt][nt][0] + b0;
            v0.y = acc[mt][nt][1] + b1;
            v1.x = acc[mt][nt][2] + b0;
            v1.y = acc[mt][nt][3] + b1;
            *(float2*)(C + (size_t)row * N + col) = v0;
            *(float2*)(C + (size_t)(row + 8) * N + col) = v1;
        }
    }
}

// ---------------------------------------------------------------------------
// Fused per-head LayerNorm + RoPE (unchanged, passing)
// ---------------------------------------------------------------------------
__global__ __launch_bounds__(128)
void ln_rope_kernel(float* __restrict__ data,
                    const float* __restrict__ gw,
                    const float* __restrict__ bw,
                    int H)
{
    const int s = blockIdx.x;
    const int d = threadIdx.x;
    __shared__ float red[8];
    __shared__ float xs[HD_];

    const int dd = d & 63;
    const float inv = exp2f(-(float)dd * (LOG2_THETA / 64.0f));
    const float th = (float)s * inv;
    float sn, cs;
    sincosf(th, &sn, &cs);

    const float gv = gw[d];
    const float bv = bw[d];
    const int lane = d & 31;
    const int w = d >> 5;

    for (int h = 0; h < H; h++) {
        float* x = data + ((size_t)s * H + h) * HD_;
        const float v = x[d];
        float s1 = v, s2 = v * v;
#pragma unroll
        for (int off = 16; off > 0; off >>= 1) {
            s1 += __shfl_xor_sync(0xffffffffu, s1, off);
            s2 += __shfl_xor_sync(0xffffffffu, s2, off);
        }
        if (lane == 0) { red[w] = s1; red[4 + w] = s2; }
        __syncthreads();
        const float sum = red[0] + red[1] + red[2] + red[3];
        const float sq  = red[4] + red[5] + red[6] + red[7];
        const float mu  = sum * (1.0f / HD_);
        const float var = sq * (1.0f / HD_) - mu * mu;
        const float r   = rsqrtf(var + EPS_);
        const float xn  = (v - mu) * r * gv + bv;
        xs[d] = xn;
        __syncthreads();
        const float other = (d < 64) ? -xs[d + 64] : xs[d - 64];
        x[d] = xn * cs + other * sn;
        __syncthreads();
    }
}

// ---------------------------------------------------------------------------
// Causal GQA flash attention, fp32 SIMT; writes output as bf16 hi/lo directly
// ---------------------------------------------------------------------------
#define BR 64
#define BC 64
#define QSTR 132
#define PSTR 72
#define FLASH_SMEM ((3 * BC * QSTR + BR * PSTR) * 4)

__global__ __launch_bounds__(128)
void flash_kernel(const float* __restrict__ Q,
                  const float* __restrict__ K,
                  const float* __restrict__ V,
                  __nv_bfloat16* __restrict__ Oh,
                  __nv_bfloat16* __restrict__ Ol)
{
    extern __shared__ float sh[];
    float* Qs = sh;
    float* Ks = Qs + BR * QSTR;
    float* Vs = Ks + BC * QSTR;
    float* Ps = Vs + BC * QSTR;

    const int qb = blockIdx.x;
    const int h = blockIdx.y;
    const int kvh = h / (NH_ / NKV_);
    const int q0 = qb * BR;
    const int tid = threadIdx.x;
    const int ty = tid >> 3;
    const int tx = tid & 7;

    {
        const int r = tid >> 1;
        const int half = (tid & 1) * 64;
        const float* src = Q + ((size_t)(q0 + r) * NH_ + h) * HD_ + half;
        float* dst = Qs + r * QSTR + half;
#pragma unroll
        for (int i = 0; i < 16; i++)
            *(float4*)(dst + i * 4) = *(const float4*)(src + i * 4);
    }

    float m[4], l[4], o[4][16];
#pragma unroll
    for (int i = 0; i < 4; i++) {
        m[i] = -1e30f; l[i] = 0.f;
#pragma unroll
        for (int c = 0; c < 16; c++) o[i][c] = 0.f;
    }

    const int nkv = qb + 1;
    for (int kb = 0; kb < nkv; kb++) {
        const int k0 = kb * BC;
        __syncthreads();
        {
            const int r = tid >> 1;
            const int half = (tid & 1) * 64;
            const float* ks = K + ((size_t)(k0 + r) * NKV_ + kvh) * HD_ + half;
            const float* vs = V + ((size_t)(k0 + r) * NKV_ + kvh) * HD_ + half;
            float* kd = Ks + r * QSTR + half;
            float* vd = Vs + r * QSTR + half;
#pragma unroll
            for (int i = 0; i < 16; i++) {
                *(float4*)(kd + i * 4) = *(const float4*)(ks + i * 4);
                *(float4*)(vd + i * 4) = *(const float4*)(vs + i * 4);
            }
        }
        __syncthreads();

        float acc[4][8];
#pragma unroll
        for (int i = 0; i < 4; i++)
#pragma unroll
            for (int j = 0; j < 8; j++) acc[i][j] = 0.f;

#pragma unroll 2
        for (int d0 = 0; d0 < HD_; d0 += 4) {
            float4 qv[4], kv[8];
#pragma unroll
            for (int i = 0; i < 4; i++)
                qv[i] = *(const float4*)(Qs + (i * 16 + ty) * QSTR + d0);
#pragma unroll
            for (int j = 0; j < 8; j++)
                kv[j] = *(const float4*)(Ks + (j * 8 + tx) * QSTR + d0);
#pragma unroll
            for (int i = 0; i < 4; i++)
#pragma unroll
                for (int j = 0; j < 8; j++) {
                    acc[i][j] += qv[i].x * kv[j].x;
                    acc[i][j] += qv[i].y * kv[j].y;
                    acc[i][j] += qv[i].z * kv[j].z;
                    acc[i][j] += qv[i].w * kv[j].w;
                }
        }

        const bool diag = (kb == qb);
#pragma unroll
        for (int i = 0; i < 4; i++) {
            const int qr = q0 + i * 16 + ty;
            float mx = -1e30f;
#pragma unroll
            for (int j = 0; j < 8; j++) {
                float v = acc[i][j] * SCALE_;
                if (diag && (k0 + j * 8 + tx) > qr) v = -1e30f;
                acc[i][j] = v;
                mx = fmaxf(mx, v);
            }
            mx = fmaxf(mx, __shfl_xor_sync(0xffffffffu, mx, 1));
            mx = fmaxf(mx, __shfl_xor_sync(0xffffffffu, mx, 2));
            mx = fmaxf(mx, __shfl_xor_sync(0xffffffffu, mx, 4));
            const float mnew = fmaxf(m[i], mx);
            const float alpha = __expf(m[i] - mnew);
            m[i] = mnew;
            float rs = 0.f;
#pragma unroll
            for (int j = 0; j < 8; j++) {
                const float p = __expf(acc[i][j] - mnew);
                acc[i][j] = p;
                rs += p;
            }
            rs += __shfl_xor_sync(0xffffffffu, rs, 1);
            rs += __shfl_xor_sync(0xffffffffu, rs, 2);
            rs += __shfl_xor_sync(0xffffffffu, rs, 4);
            l[i] = l[i] * alpha + rs;
#pragma unroll
            for (int c = 0; c < 16; c++) o[i][c] *= alpha;
#pragma unroll
            for (int j = 0; j < 8; j++)
                Ps[(i * 16 + ty) * PSTR + j * 8 + tx] = acc[i][j];
        }
        __syncthreads();

#pragma unroll 2
        for (int j4 = 0; j4 < BC; j4 += 4) {
            float pr[4][4];
#pragma unroll
            for (int i = 0; i < 4; i++) {
                float4 pv = *(const float4*)(Ps + (i * 16 + ty) * PSTR + j4);
                pr[i][0] = pv.x; pr[i][1] = pv.y; pr[i][2] = pv.z; pr[i][3] = pv.w;
            }
#pragma unroll
            for (int jj = 0; jj < 4; jj++) {
                float4 vv[4];
#pragma unroll
                for (int c4 = 0; c4 < 4; c4++)
                    vv[c4] = *(const float4*)(Vs + (j4 + jj) * QSTR + tx * 16 + c4 * 4);
#pragma unroll
                for (int i = 0; i < 4; i++) {
                    const float p = pr[i][jj];
#pragma unroll
                    for (int c4 = 0; c4 < 4; c4++) {
                        o[i][c4 * 4 + 0] += p * vv[c4].x;
                        o[i][c4 * 4 + 1] += p * vv[c4].y;
                        o[i][c4 * 4 + 2] += p * vv[c4].z;
                        o[i][c4 * 4 + 3] += p * vv[c4].w;
                    }
                }
            }
        }
    }

    // epilogue: O /= l, split to bf16 hi/lo, write [S][NH*HD]
#pragma unroll
    for (int i = 0; i < 4; i++) {
        const float inv = 1.0f / l[i];
        const size_t off = ((size_t)(q0 + i * 16 + ty) * NH_ + h) * HD_ + tx * 16;
#pragma unroll
        for (int c4 = 0; c4 < 4; c4++) {
            float4 w;
            w.x = o[i][c4 * 4 + 0] * inv;
            w.y = o[i][c4 * 4 + 1] * inv;
            w.z = o[i][c4 * 4 + 2] * inv;
            w.w = o[i][c4 * 4 + 3] * inv;
            uint2 hh, ll;
            split4_bf(w, hh, ll);
            *(uint2*)(Oh + off + c4 * 4) = hh;
            *(uint2*)(Ol + off + c4 * 4) = ll;
        }
    }
}

// ---------------------------------------------------------------------------
// Launch
// ---------------------------------------------------------------------------
extern "C" void kernel_launch(void* const* d_in, const int* in_sizes, int n_in,
                              void* d_out, int out_size)
{
    const float* x   = (const float*)d_in[0];
    const float* Wq  = (const float*)d_in[1];
    const float* bq  = (const float*)d_in[2];
    const float* Wk  = (const float*)d_in[3];
    const float* bk  = (const float*)d_in[4];
    const float* Wv  = (const float*)d_in[5];
    const float* bv  = (const float*)d_in[6];
    const float* Wo  = (const float*)d_in[7];
    const float* bo  = (const float*)d_in[8];
    const float* qng = (const float*)d_in[9];
    const float* qnb = (const float*)d_in[10];
    const float* kng = (const float*)d_in[11];
    const float* knb = (const float*)d_in[12];
    float* out = (float*)d_out;

    float *qp, *kp, *vp;
    __nv_bfloat16 *xh, *xl, *wqh, *wql, *wkh, *wkl, *wvh, *wvl, *woh, *wol, *aoh, *aol;
    cudaGetSymbolAddress((void**)&qp, g_q);
    cudaGetSymbolAddress((void**)&kp, g_k);
    cudaGetSymbolAddress((void**)&vp, g_v);
    cudaGetSymbolAddress((void**)&xh, g_xh);   cudaGetSymbolAddress((void**)&xl, g_xl);
    cudaGetSymbolAddress((void**)&wqh, g_wqh); cudaGetSymbolAddress((void**)&wql, g_wql);
    cudaGetSymbolAddress((void**)&wkh, g_wkh); cudaGetSymbolAddress((void**)&wkl, g_wkl);
    cudaGetSymbolAddress((void**)&wvh, g_wvh); cudaGetSymbolAddress((void**)&wvl, g_wvl);
    cudaGetSymbolAddress((void**)&woh, g_woh); cudaGetSymbolAddress((void**)&wol, g_wol);
    cudaGetSymbolAddress((void**)&aoh, g_aoh); cudaGetSymbolAddress((void**)&aol, g_aol);

    cudaFuncSetAttribute(gemm_bf16_pipe, cudaFuncAttributeMaxDynamicSharedMemorySize,
                         GEMM_SMEM);
    cudaFuncSetAttribute(flash_kernel, cudaFuncAttributeMaxDynamicSharedMemorySize,
                         FLASH_SMEM);

    // pre-split operands to bf16 hi/lo
    const int n4_x  = S_ * HID_ / 4;
    const int n4_wq = NH_ * HD_ * HID_ / 4;
    const int n4_wk = NKV_ * HD_ * HID_ / 4;
    const int n4_wo = HID_ * HID_ / 4;
    split_kernel<<<n4_x  / 256, 256>>>(x,  xh,  xl,  n4_x);
    split_kernel<<<n4_wq / 256, 256>>>(Wq, wqh, wql, n4_wq);
    split_kernel<<<n4_wk / 256, 256>>>(Wk, wkh, wkl, n4_wk);
    split_kernel<<<n4_wk / 256, 256>>>(Wv, wvh, wvl, n4_wk);
    split_kernel<<<n4_wo / 256, 256>>>(Wo, woh, wol, n4_wo);

    // QKV projections (pipelined bf16 mma.sync, 3 terms)
    gemm_bf16_pipe<<<dim3((NH_ * HD_) / GBN, S_ / GBM), 256, GEMM_SMEM>>>(
        S_, NH_ * HD_, HID_, xh, xl, wqh, wql, bq, qp);
    gemm_bf16_pipe<<<dim3((NKV_ * HD_) / GBN, S_ / GBM), 256, GEMM_SMEM>>>(
        S_, NKV_ * HD_, HID_, xh, xl, wkh, wkl, bk, kp);
    gemm_bf16_pipe<<<dim3((NKV_ * HD_) / GBN, S_ / GBM), 256, GEMM_SMEM>>>(
        S_, NKV_ * HD_, HID_, xh, xl, wvh, wvl, bv, vp);

    // per-head LayerNorm + RoPE (in place)
    ln_rope_kernel<<<S_, HD_>>>(qp, qng, qnb, NH_);
    ln_rope_kernel<<<S_, HD_>>>(kp, kng, knb, NKV_);

    // causal GQA flash attention -> bf16 hi/lo output
    flash_kernel<<<dim3(S_ / BR, NH_), 128, FLASH_SMEM>>>(qp, kp, vp, aoh, aol);

    // output projection
    gemm_bf16_pipe<<<dim3(HID_ / GBN, S_ / GBM), 256, GEMM_SMEM>>>(
        S_, HID_, HID_, aoh, aol, woh, wol, bo, out);
}

// round 10
// speedup vs baseline: 1.8020x; 1.0159x over previous
#include <cuda_runtime.h>
#include <cuda_bf16.h>
#include <math.h>
#include <cstdint>

// Problem constants
#define S_    2048
#define HID_  4096
#define NH_   32
#define NKV_  8
#define HD_   128
#define EPS_  1e-5f
#define SCALE_ 0.088388347648318447f
#define LOG2_THETA 18.931568569324174f

// ---------------------------------------------------------------------------
// Scratch (device globals; no allocation allowed)
// ---------------------------------------------------------------------------
__device__ float g_q[S_ * NH_ * HD_];
__device__ float g_k[S_ * NKV_ * HD_];
__device__ float g_v[S_ * NKV_ * HD_];
__device__ __nv_bfloat16 g_xh[S_ * HID_],  g_xl[S_ * HID_];
__device__ __nv_bfloat16 g_wqh[NH_ * HD_ * HID_],  g_wql[NH_ * HD_ * HID_];
__device__ __nv_bfloat16 g_wkh[NKV_ * HD_ * HID_], g_wkl[NKV_ * HD_ * HID_];
__device__ __nv_bfloat16 g_wvh[NKV_ * HD_ * HID_], g_wvl[NKV_ * HD_ * HID_];
__device__ __nv_bfloat16 g_woh[HID_ * HID_], g_wol[HID_ * HID_];
__device__ __nv_bfloat16 g_aoh[S_ * HID_],  g_aol[S_ * HID_];

// ---------------------------------------------------------------------------
// Helpers
// ---------------------------------------------------------------------------
__device__ __forceinline__ uint32_t smem_u32(const void* p) {
    uint32_t a;
    asm("{ .reg .u64 t; cvta.to.shared.u64 t, %1; cvt.u32.u64 %0, t; }"
        : "=r"(a) : "l"(p));
    return a;
}

__device__ __forceinline__ void ldsm4(uint32_t* r, uint32_t addr) {
    asm volatile("ldmatrix.sync.aligned.m8n8.x4.shared.b16 {%0,%1,%2,%3}, [%4];"
                 : "=r"(r[0]), "=r"(r[1]), "=r"(r[2]), "=r"(r[3]) : "r"(addr));
}

__device__ __forceinline__ void mma_bf16(float* d, const uint32_t* a, const uint32_t* b) {
    asm volatile(
        "mma.sync.aligned.m16n8k16.row.col.f32.bf16.bf16.f32 "
        "{%0,%1,%2,%3}, {%4,%5,%6,%7}, {%8,%9}, {%0,%1,%2,%3};"
        : "+f"(d[0]), "+f"(d[1]), "+f"(d[2]), "+f"(d[3])
        : "r"(a[0]), "r"(a[1]), "r"(a[2]), "r"(a[3]), "r"(b[0]), "r"(b[1]));
}

__device__ __forceinline__ uint32_t pk(__nv_bfloat16 a, __nv_bfloat16 b) {
    __nv_bfloat162 t = __halves2bfloat162(a, b);
    return *reinterpret_cast<uint32_t*>(&t);
}

__device__ __forceinline__ void split4_bf(float4 v, uint2& hi, uint2& lo) {
    __nv_bfloat16 h0 = __float2bfloat16_rn(v.x);
    __nv_bfloat16 h1 = __float2bfloat16_rn(v.y);
    __nv_bfloat16 h2 = __float2bfloat16_rn(v.z);
    __nv_bfloat16 h3 = __float2bfloat16_rn(v.w);
    __nv_bfloat16 l0 = __float2bfloat16_rn(v.x - __bfloat162float(h0));
    __nv_bfloat16 l1 = __float2bfloat16_rn(v.y - __bfloat162float(h1));
    __nv_bfloat16 l2 = __float2bfloat16_rn(v.z - __bfloat162float(h2));
    __nv_bfloat16 l3 = __float2bfloat16_rn(v.w - __bfloat162float(h3));
    hi.x = pk(h0, h1); hi.y = pk(h2, h3);
    lo.x = pk(l0, l1); lo.y = pk(l2, l3);
}

// ---------------------------------------------------------------------------
// fp32 -> bf16 hi/lo split
// ---------------------------------------------------------------------------
__global__ __launch_bounds__(256)
void split_kernel(const float* __restrict__ in,
                  __nv_bfloat16* __restrict__ hi,
                  __nv_bfloat16* __restrict__ lo, int n4)
{
    const int idx = blockIdx.x * 256 + threadIdx.x;
    if (idx >= n4) return;
    float4 v = ((const float4*)in)[idx];
    uint2 h, l;
    split4_bf(v, h, l);
    ((uint2*)hi)[idx] = h;
    ((uint2*)lo)[idx] = l;
}

// ---------------------------------------------------------------------------
// bf16 3-term GEMM body with cp.async 3-stage pipeline.
// Tile 128x128, BK=32, 256 thr (8 warps 2x4), MMA terms reordered so each
// accumulator's dependent updates are 16 MMA instructions apart.
// ---------------------------------------------------------------------------
#define GBM 128
#define GBN 128
#define GBK 32
#define OFF_AL 8192
#define OFF_BH 16384
#define OFF_BL 24576
#define BUF_B  32768
#define NSTAGE 3
#define GEMM_SMEM (NSTAGE * BUF_B)

__device__ __forceinline__ void issue_stage(
    uint32_t sdst,
    const __nv_bfloat16* __restrict__ Ah, const __nv_bfloat16* __restrict__ Al,
    const __nv_bfloat16* __restrict__ Bh, const __nv_bfloat16* __restrict__ Bl,
    int K, int k0, int tid)
{
#pragma unroll
    for (int it = 0; it < 8; it++) {
        const int tile = it >> 1;
        const int c = (it & 1) * 256 + tid;
        const int row = c >> 2;
        const int col = c & 3;
        const uint32_t dst = sdst + tile * 8192 + row * 64
                           + (uint32_t)((col ^ (row & 3)) << 4);
        const __nv_bfloat16* src;
        if (tile == 0)      src = Ah + (size_t)row * K + k0 + col * 8;
        else if (tile == 1) src = Al + (size_t)row * K + k0 + col * 8;
        else if (tile == 2) src = Bh + (size_t)row * K + k0 + col * 8;
        else                src = Bl + (size_t)row * K + k0 + col * 8;
        asm volatile("cp.async.cg.shared.global [%0], [%1], 16;"
                     :: "r"(dst), "l"(src));
    }
}

__device__ __forceinline__ void gemm_body(
    const __nv_bfloat16* __restrict__ Ahb, const __nv_bfloat16* __restrict__ Alb,
    const __nv_bfloat16* __restrict__ Bhb, const __nv_bfloat16* __restrict__ Blb,
    const float* __restrict__ bias, float* __restrict__ C,
    int N, int K, int bm, int bn, char* smem)
{
    const uint32_t sbase = smem_u32(smem);
    const int tid = threadIdx.x;
    const int wid = tid >> 5;
    const int lane = tid & 31;
    const int warp_m = wid >> 2;
    const int warp_n = wid & 3;

    const int l7 = lane & 7;
    const int l3 = lane & 3;
    const int amat = lane >> 3;
    const uint32_t a_row64 = (uint32_t)(warp_m * 64 + ((amat & 1) << 3) + l7) * 64;
    const int a_kh = amat >> 1;
    const int b_kh = (lane >> 3) & 1;
    const uint32_t b_row64 = (uint32_t)(warp_n * 32 + ((lane >> 4) << 3) + l7) * 64;

    float acc[4][4][4];
#pragma unroll
    for (int i = 0; i < 4; i++)
#pragma unroll
        for (int j = 0; j < 4; j++)
#pragma unroll
            for (int c = 0; c < 4; c++) acc[i][j][c] = 0.f;

    const int NB = K / GBK;

    issue_stage(sbase, Ahb, Alb, Bhb, Blb, K, 0, tid);
    asm volatile("cp.async.commit_group;");
    issue_stage(sbase + BUF_B, Ahb, Alb, Bhb, Blb, K, GBK, tid);
    asm volatile("cp.async.commit_group;");

    for (int kb = 0; kb < NB; kb++) {
        asm volatile("cp.async.wait_group 1;");
        __syncthreads();

        const int nk = kb + 2;
        if (nk < NB)
            issue_stage(sbase + (uint32_t)(nk % NSTAGE) * BUF_B,
                        Ahb, Alb, Bhb, Blb, K, nk * GBK, tid);
        asm volatile("cp.async.commit_group;");

        const uint32_t bufc = sbase + (uint32_t)(kb % NSTAGE) * BUF_B;

#pragma unroll
        for (int ks = 0; ks < 2; ks++) {
            const uint32_t a_swoff = (uint32_t)(((ks * 2 + a_kh) ^ l3) << 4);
            const uint32_t b_swoff = (uint32_t)(((ks * 2 + b_kh) ^ l3) << 4);

            uint32_t ah[4][4];
#pragma unroll
            for (int mt = 0; mt < 4; mt++)
                ldsm4(ah[mt], bufc + a_row64 + (uint32_t)mt * 1024 + a_swoff);

            uint32_t bh[2][4], bl[2][4];
#pragma unroll
            for (int p = 0; p < 2; p++) {
                const uint32_t baddr = bufc + OFF_BH + b_row64 + (uint32_t)p * 1024 + b_swoff;
                ldsm4(bh[p], baddr);
                ldsm4(bl[p], baddr + (OFF_BL - OFF_BH));
            }

            // term 1: hi*hi — all 16 accumulators (dep distance 16)
#pragma unroll
            for (int mt = 0; mt < 4; mt++)
#pragma unroll
                for (int nt = 0; nt < 4; nt++)
                    mma_bf16(acc[mt][nt], ah[mt], &bh[nt >> 1][(nt & 1) * 2]);

            // term 2: hi*lo
#pragma unroll
            for (int mt = 0; mt < 4; mt++)
#pragma unroll
                for (int nt = 0; nt < 4; nt++)
                    mma_bf16(acc[mt][nt], ah[mt], &bl[nt >> 1][(nt & 1) * 2]);

            // term 3: lo*hi (ah dead -> regs reused)
            uint32_t al[4][4];
#pragma unroll
            for (int mt = 0; mt < 4; mt++)
                ldsm4(al[mt], bufc + OFF_AL + a_row64 + (uint32_t)mt * 1024 + a_swoff);
#pragma unroll
            for (int mt = 0; mt < 4; mt++)
#pragma unroll
                for (int nt = 0; nt < 4; nt++)
                    mma_bf16(acc[mt][nt], al[mt], &bh[nt >> 1][(nt & 1) * 2]);
        }
    }

    const int g = lane >> 2;
    const int t = lane & 3;
#pragma unroll
    for (int nt = 0; nt < 4; nt++) {
        const int col = bn + warp_n * 32 + nt * 8 + 2 * t;
        const float b0 = bias[col];
        const float b1 = bias[col + 1];
#pragma unroll
        for (int mt = 0; mt < 4; mt++) {
            const int row = bm + warp_m * 64 + mt * 16 + g;
            float2 v0, v1;
            v0.x = acc[mt][nt][0] + b0;
            v0.y = acc[mt][nt][1] + b1;
            v1.x = acc[mt][nt][2] + b0;
            v1.y = acc[mt][nt][3] + b1;
            *(float2*)(C + (size_t)row * N + col) = v0;
            *(float2*)(C + (size_t)(row + 8) * N + col) = v1;
        }
    }
}

// Fused Q/K/V projection: grid.x in [0,48): [0,32)->Q, [32,40)->K, [40,48)->V
__global__ __launch_bounds__(256, 2)
void gemm_qkv(const __nv_bfloat16* __restrict__ xh, const __nv_bfloat16* __restrict__ xl,
              const __nv_bfloat16* __restrict__ wqh, const __nv_bfloat16* __restrict__ wql,
              const __nv_bfloat16* __restrict__ wkh, const __nv_bfloat16* __restrict__ wkl,
              const __nv_bfloat16* __restrict__ wvh, const __nv_bfloat16* __restrict__ wvl,
              const float* __restrict__ bq, const float* __restrict__ bk,
              const float* __restrict__ bv,
              float* __restrict__ q, float* __restrict__ k, float* __restrict__ v)
{
    extern __shared__ __align__(1024) char smem[];
    const int bx = blockIdx.x;
    const int bm = blockIdx.y * GBM;

    const __nv_bfloat16 *Bh, *Bl;
    const float* bias;
    float* C;
    int N, bn;
    if (bx < 32) {
        Bh = wqh; Bl = wql; bias = bq; C = q; N = NH_ * HD_; bn = bx * GBN;
    } else if (bx < 40) {
        Bh = wkh; Bl = wkl; bias = bk; C = k; N = NKV_ * HD_; bn = (bx - 32) * GBN;
    } else {
        Bh = wvh; Bl = wvl; bias = bv; C = v; N = NKV_ * HD_; bn = (bx - 40) * GBN;
    }

    gemm_body(xh + (size_t)bm * HID_, xl + (size_t)bm * HID_,
              Bh + (size_t)bn * HID_, Bl + (size_t)bn * HID_,
              bias, C, N, HID_, bm, bn, smem);
}

// Generic GEMM (output projection)
__global__ __launch_bounds__(256, 2)
void gemm_bf16_pipe(int M, int N, int K,
                    const __nv_bfloat16* __restrict__ Ah,
                    const __nv_bfloat16* __restrict__ Al,
                    const __nv_bfloat16* __restrict__ Bh,
                    const __nv_bfloat16* __restrict__ Bl,
                    const float* __restrict__ bias,
                    float* __restrict__ C)
{
    extern __shared__ __align__(1024) char smem[];
    const int bm = blockIdx.y * GBM;
    const int bn = blockIdx.x * GBN;
    gemm_body(Ah + (size_t)bm * K, Al + (size_t)bm * K,
              Bh + (size_t)bn * K, Bl + (size_t)bn * K,
              bias, C, N, K, bm, bn, smem);
}

// ---------------------------------------------------------------------------
// Fused per-head LayerNorm + RoPE (unchanged, passing)
// ---------------------------------------------------------------------------
__global__ __launch_bounds__(128)
void ln_rope_kernel(float* __restrict__ data,
                    const float* __restrict__ gw,
                    const float* __restrict__ bw,
                    int H)
{
    const int s = blockIdx.x;
    const int d = threadIdx.x;
    __shared__ float red[8];
    __shared__ float xs[HD_];

    const int dd = d & 63;
    const float inv = exp2f(-(float)dd * (LOG2_THETA / 64.0f));
    const float th = (float)s * inv;
    float sn, cs;
    sincosf(th, &sn, &cs);

    const float gv = gw[d];
    const float bv = bw[d];
    const int lane = d & 31;
    const int w = d >> 5;

    for (int h = 0; h < H; h++) {
        float* x = data + ((size_t)s * H + h) * HD_;
        const float v = x[d];
        float s1 = v, s2 = v * v;
#pragma unroll
        for (int off = 16; off > 0; off >>= 1) {
            s1 += __shfl_xor_sync(0xffffffffu, s1, off);
            s2 += __shfl_xor_sync(0xffffffffu, s2, off);
        }
        if (lane == 0) { red[w] = s1; red[4 + w] = s2; }
        __syncthreads();
        const float sum = red[0] + red[1] + red[2] + red[3];
        const float sq  = red[4] + red[5] + red[6] + red[7];
        const float mu  = sum * (1.0f / HD_);
        const float var = sq * (1.0f / HD_) - mu * mu;
        const float r   = rsqrtf(var + EPS_);
        const float xn  = (v - mu) * r * gv + bv;
        xs[d] = xn;
        __syncthreads();
        const float other = (d < 64) ? -xs[d + 64] : xs[d - 64];
        x[d] = xn * cs + other * sn;
        __syncthreads();
    }
}

// ---------------------------------------------------------------------------
// Causal GQA flash attention, fp32 SIMT; writes output as bf16 hi/lo
// ---------------------------------------------------------------------------
#define BR 64
#define BC 64
#define QSTR 132
#define PSTR 72
#define FLASH_SMEM ((3 * BC * QSTR + BR * PSTR) * 4)

__global__ __launch_bounds__(128)
void flash_kernel(const float* __restrict__ Q,
                  const float* __restrict__ K,
                  const float* __restrict__ V,
                  __nv_bfloat16* __restrict__ Oh,
                  __nv_bfloat16* __restrict__ Ol)
{
    extern __shared__ float sh[];
    float* Qs = sh;
    float* Ks = Qs + BR * QSTR;
    float* Vs = Ks + BC * QSTR;
    float* Ps = Vs + BC * QSTR;

    const int qb = blockIdx.x;
    const int h = blockIdx.y;
    const int kvh = h / (NH_ / NKV_);
    const int q0 = qb * BR;
    const int tid = threadIdx.x;
    const int ty = tid >> 3;
    const int tx = tid & 7;

    {
        const int r = tid >> 1;
        const int half = (tid & 1) * 64;
        const float* src = Q + ((size_t)(q0 + r) * NH_ + h) * HD_ + half;
        float* dst = Qs + r * QSTR + half;
#pragma unroll
        for (int i = 0; i < 16; i++)
            *(float4*)(dst + i * 4) = *(const float4*)(src + i * 4);
    }

    float m[4], l[4], o[4][16];
#pragma unroll
    for (int i = 0; i < 4; i++) {
        m[i] = -1e30f; l[i] = 0.f;
#pragma unroll
        for (int c = 0; c < 16; c++) o[i][c] = 0.f;
    }

    const int nkv = qb + 1;
    for (int kb = 0; kb < nkv; kb++) {
        const int k0 = kb * BC;
        __syncthreads();
        {
            const int r = tid >> 1;
            const int half = (tid & 1) * 64;
            const float* ks = K + ((size_t)(k0 + r) * NKV_ + kvh) * HD_ + half;
            const float* vs = V + ((size_t)(k0 + r) * NKV_ + kvh) * HD_ + half;
            float* kd = Ks + r * QSTR + half;
            float* vd = Vs + r * QSTR + half;
#pragma unroll
            for (int i = 0; i < 16; i++) {
                *(float4*)(kd + i * 4) = *(const float4*)(ks + i * 4);
                *(float4*)(vd + i * 4) = *(const float4*)(vs + i * 4);
            }
        }
        __syncthreads();

        float acc[4][8];
#pragma unroll
        for (int i = 0; i < 4; i++)
#pragma unroll
            for (int j = 0; j < 8; j++) acc[i][j] = 0.f;

#pragma unroll 2
        for (int d0 = 0; d0 < HD_; d0 += 4) {
            float4 qv[4], kv[8];
#pragma unroll
            for (int i = 0; i < 4; i++)
                qv[i] = *(const float4*)(Qs + (i * 16 + ty) * QSTR + d0);
#pragma unroll
            for (int j = 0; j < 8; j++)
                kv[j] = *(const float4*)(Ks + (j * 8 + tx) * QSTR + d0);
#pragma unroll
            for (int i = 0; i < 4; i++)
#pragma unroll
                for (int j = 0; j < 8; j++) {
                    acc[i][j] += qv[i].x * kv[j].x;
                    acc[i][j] += qv[i].y * kv[j].y;
                    acc[i][j] += qv[i].z * kv[j].z;
                    acc[i][j] += qv[i].w * kv[j].w;
                }
        }

        const bool diag = (kb == qb);
#pragma unroll
        for (int i = 0; i < 4; i++) {
            const int qr = q0 + i * 16 + ty;
            float mx = -1e30f;
#pragma unroll
            for (int j = 0; j < 8; j++) {
                float v = acc[i][j] * SCALE_;
                if (diag && (k0 + j * 8 + tx) > qr) v = -1e30f;
                acc[i][j] = v;
                mx = fmaxf(mx, v);
            }
            mx = fmaxf(mx, __shfl_xor_sync(0xffffffffu, mx, 1));
            mx = fmaxf(mx, __shfl_xor_sync(0xffffffffu, mx, 2));
            mx = fmaxf(mx, __shfl_xor_sync(0xffffffffu, mx, 4));
            const float mnew = fmaxf(m[i], mx);
            const float alpha = __expf(m[i] - mnew);
            m[i] = mnew;
            float rs = 0.f;
#pragma unroll
            for (int j = 0; j < 8; j++) {
                const float p = __expf(acc[i][j] - mnew);
                acc[i][j] = p;
                rs += p;
            }
            rs += __shfl_xor_sync(0xffffffffu, rs, 1);
            rs += __shfl_xor_sync(0xffffffffu, rs, 2);
            rs += __shfl_xor_sync(0xffffffffu, rs, 4);
            l[i] = l[i] * alpha + rs;
#pragma unroll
            for (int c = 0; c < 16; c++) o[i][c] *= alpha;
#pragma unroll
            for (int j = 0; j < 8; j++)
                Ps[(i * 16 + ty) * PSTR + j * 8 + tx] = acc[i][j];
        }
        __syncthreads();

#pragma unroll 2
        for (int j4 = 0; j4 < BC; j4 += 4) {
            float pr[4][4];
#pragma unroll
            for (int i = 0; i < 4; i++) {
                float4 pv = *(const float4*)(Ps + (i * 16 + ty) * PSTR + j4);
                pr[i][0] = pv.x; pr[i][1] = pv.y; pr[i][2] = pv.z; pr[i][3] = pv.w;
            }
#pragma unroll
            for (int jj = 0; jj < 4; jj++) {
                float4 vv[4];
#pragma unroll
                for (int c4 = 0; c4 < 4; c4++)
                    vv[c4] = *(const float4*)(Vs + (j4 + jj) * QSTR + tx * 16 + c4 * 4);
#pragma unroll
                for (int i = 0; i < 4; i++) {
                    const float p = pr[i][jj];
#pragma unroll
                    for (int c4 = 0; c4 < 4; c4++) {
                        o[i][c4 * 4 + 0] += p * vv[c4].x;
                        o[i][c4 * 4 + 1] += p * vv[c4].y;
                        o[i][c4 * 4 + 2] += p * vv[c4].z;
                        o[i][c4 * 4 + 3] += p * vv[c4].w;
                    }
                }
            }
        }
    }

#pragma unroll
    for (int i = 0; i < 4; i++) {
        const float inv = 1.0f / l[i];
        const size_t off = ((size_t)(q0 + i * 16 + ty) * NH_ + h) * HD_ + tx * 16;
#pragma unroll
        for (int c4 = 0; c4 < 4; c4++) {
            float4 w;
            w.x = o[i][c4 * 4 + 0] * inv;
            w.y = o[i][c4 * 4 + 1] * inv;
            w.z = o[i][c4 * 4 + 2] * inv;
            w.w = o[i][c4 * 4 + 3] * inv;
            uint2 hh, ll;
            split4_bf(w, hh, ll);
            *(uint2*)(Oh + off + c4 * 4) = hh;
            *(uint2*)(Ol + off + c4 * 4) = ll;
        }
    }
}

// ---------------------------------------------------------------------------
// Launch
// ---------------------------------------------------------------------------
extern "C" void kernel_launch(void* const* d_in, const int* in_sizes, int n_in,
                              void* d_out, int out_size)
{
    const float* x   = (const float*)d_in[0];
    const float* Wq  = (const float*)d_in[1];
    const float* bq  = (const float*)d_in[2];
    const float* Wk  = (const float*)d_in[3];
    const float* bk  = (const float*)d_in[4];
    const float* Wv  = (const float*)d_in[5];
    const float* bv  = (const float*)d_in[6];
    const float* Wo  = (const float*)d_in[7];
    const float* bo  = (const float*)d_in[8];
    const float* qng = (const float*)d_in[9];
    const float* qnb = (const float*)d_in[10];
    const float* kng = (const float*)d_in[11];
    const float* knb = (const float*)d_in[12];
    float* out = (float*)d_out;

    float *qp, *kp, *vp;
    __nv_bfloat16 *xh, *xl, *wqh, *wql, *wkh, *wkl, *wvh, *wvl, *woh, *wol, *aoh, *aol;
    cudaGetSymbolAddress((void**)&qp, g_q);
    cudaGetSymbolAddress((void**)&kp, g_k);
    cudaGetSymbolAddress((void**)&vp, g_v);
    cudaGetSymbolAddress((void**)&xh, g_xh);   cudaGetSymbolAddress((void**)&xl, g_xl);
    cudaGetSymbolAddress((void**)&wqh, g_wqh); cudaGetSymbolAddress((void**)&wql, g_wql);
    cudaGetSymbolAddress((void**)&wkh, g_wkh); cudaGetSymbolAddress((void**)&wkl, g_wkl);
    cudaGetSymbolAddress((void**)&wvh, g_wvh); cudaGetSymbolAddress((void**)&wvl, g_wvl);
    cudaGetSymbolAddress((void**)&woh, g_woh); cudaGetSymbolAddress((void**)&wol, g_wol);
    cudaGetSymbolAddress((void**)&aoh, g_aoh); cudaGetSymbolAddress((void**)&aol, g_aol);

    cudaFuncSetAttribute(gemm_qkv, cudaFuncAttributeMaxDynamicSharedMemorySize,
                         GEMM_SMEM);
    cudaFuncSetAttribute(gemm_bf16_pipe, cudaFuncAttributeMaxDynamicSharedMemorySize,
                         GEMM_SMEM);
    cudaFuncSetAttribute(flash_kernel, cudaFuncAttributeMaxDynamicSharedMemorySize,
                         FLASH_SMEM);

    const int n4_x  = S_ * HID_ / 4;
    const int n4_wq = NH_ * HD_ * HID_ / 4;
    const int n4_wk = NKV_ * HD_ * HID_ / 4;
    const int n4_wo = HID_ * HID_ / 4;
    split_kernel<<<n4_x  / 256, 256>>>(x,  xh,  xl,  n4_x);
    split_kernel<<<n4_wq / 256, 256>>>(Wq, wqh, wql, n4_wq);
    split_kernel<<<n4_wk / 256, 256>>>(Wk, wkh, wkl, n4_wk);
    split_kernel<<<n4_wk / 256, 256>>>(Wv, wvh, wvl, n4_wk);
    split_kernel<<<n4_wo / 256, 256>>>(Wo, woh, wol, n4_wo);

    // fused QKV projection
    gemm_qkv<<<dim3(48, S_ / GBM), 256, GEMM_SMEM>>>(
        xh, xl, wqh, wql, wkh, wkl, wvh, wvl, bq, bk, bv, qp, kp, vp);

    // per-head LayerNorm + RoPE (in place)
    ln_rope_kernel<<<S_, HD_>>>(qp, qng, qnb, NH_);
    ln_rope_kernel<<<S_, HD_>>>(kp, kng, knb, NKV_);

    // causal GQA flash attention -> bf16 hi/lo output
    flash_kernel<<<dim3(S_ / BR, NH_), 128, FLASH_SMEM>>>(qp, kp, vp, aoh, aol);

    // output projection
    gemm_bf16_pipe<<<dim3(HID_ / GBN, S_ / GBM), 256, GEMM_SMEM>>>(
        S_, HID_, HID_, aoh, aol, woh, wol, bo, out);
}

// round 11
// speedup vs baseline: 1.8853x; 1.0462x over previous
#include <cuda_runtime.h>
#include <cuda_fp16.h>
#include <math.h>
#include <cstdint>

// Problem constants
#define S_    2048
#define HID_  4096
#define NH_   32
#define NKV_  8
#define HD_   128
#define EPS_  1e-5f
#define SCALE_ 0.088388347648318447f
#define LOG2_THETA 18.931568569324174f

// ---------------------------------------------------------------------------
// Scratch (device globals; no allocation allowed)
// ---------------------------------------------------------------------------
__device__ float g_q[S_ * NH_ * HD_];
__device__ float g_k[S_ * NKV_ * HD_];
__device__ float g_v[S_ * NKV_ * HD_];
// fp16 operands: activations split hi/lo, weights cast to fp16
__device__ __half g_xh[S_ * HID_],  g_xl[S_ * HID_];
__device__ __half g_wq16[NH_ * HD_ * HID_];
__device__ __half g_wk16[NKV_ * HD_ * HID_];
__device__ __half g_wv16[NKV_ * HD_ * HID_];
__device__ __half g_wo16[HID_ * HID_];
__device__ __half g_aoh[S_ * HID_], g_aol[S_ * HID_];

// ---------------------------------------------------------------------------
// Helpers
// ---------------------------------------------------------------------------
__device__ __forceinline__ uint32_t smem_u32(const void* p) {
    uint32_t a;
    asm("{ .reg .u64 t; cvta.to.shared.u64 t, %1; cvt.u32.u64 %0, t; }"
        : "=r"(a) : "l"(p));
    return a;
}

__device__ __forceinline__ void ldsm4(uint32_t* r, uint32_t addr) {
    asm volatile("ldmatrix.sync.aligned.m8n8.x4.shared.b16 {%0,%1,%2,%3}, [%4];"
                 : "=r"(r[0]), "=r"(r[1]), "=r"(r[2]), "=r"(r[3]) : "r"(addr));
}

__device__ __forceinline__ void mma_f16(float* d, const uint32_t* a, const uint32_t* b) {
    asm volatile(
        "mma.sync.aligned.m16n8k16.row.col.f32.f16.f16.f32 "
        "{%0,%1,%2,%3}, {%4,%5,%6,%7}, {%8,%9}, {%0,%1,%2,%3};"
        : "+f"(d[0]), "+f"(d[1]), "+f"(d[2]), "+f"(d[3])
        : "r"(a[0]), "r"(a[1]), "r"(a[2]), "r"(a[3]), "r"(b[0]), "r"(b[1]));
}

__device__ __forceinline__ uint32_t pkh(__half a, __half b) {
    __half2 t = __halves2half2(a, b);
    return *reinterpret_cast<uint32_t*>(&t);
}

// Split float4 into fp16 hi (8B) + fp16 lo (8B)
__device__ __forceinline__ void split4_h(float4 v, uint2& hi, uint2& lo) {
    __half h0 = __float2half_rn(v.x);
    __half h1 = __float2half_rn(v.y);
    __half h2 = __float2half_rn(v.z);
    __half h3 = __float2half_rn(v.w);
    __half l0 = __float2half_rn(v.x - __half2float(h0));
    __half l1 = __float2half_rn(v.y - __half2float(h1));
    __half l2 = __float2half_rn(v.z - __half2float(h2));
    __half l3 = __float2half_rn(v.w - __half2float(h3));
    hi.x = pkh(h0, h1); hi.y = pkh(h2, h3);
    lo.x = pkh(l0, l1); lo.y = pkh(l2, l3);
}

__device__ __forceinline__ uint2 cast4_h(float4 v) {
    uint2 r;
    r.x = pkh(__float2half_rn(v.x), __float2half_rn(v.y));
    r.y = pkh(__float2half_rn(v.z), __float2half_rn(v.w));
    return r;
}

// ---------------------------------------------------------------------------
// fp32 -> fp16 hi/lo split (activations)
// ---------------------------------------------------------------------------
__global__ __launch_bounds__(256)
void split_kernel(const float* __restrict__ in,
                  __half* __restrict__ hi,
                  __half* __restrict__ lo, int n4)
{
    const int idx = blockIdx.x * 256 + threadIdx.x;
    if (idx >= n4) return;
    float4 v = ((const float4*)in)[idx];
    uint2 h, l;
    split4_h(v, h, l);
    ((uint2*)hi)[idx] = h;
    ((uint2*)lo)[idx] = l;
}

// fp32 -> fp16 cast (weights)
__global__ __launch_bounds__(256)
void cast_kernel(const float* __restrict__ in, __half* __restrict__ out, int n4)
{
    const int idx = blockIdx.x * 256 + threadIdx.x;
    if (idx >= n4) return;
    ((uint2*)out)[idx] = cast4_h(((const float4*)in)[idx]);
}

// ---------------------------------------------------------------------------
// fp16 2-term GEMM: C = (Ah+Al)[M,K] @ B16[N,K]^T + bias
// CTA 128x128, BK=32, 256 thr (8 warps 2x4, warp tile 64x32), 2 CTAs/SM.
// Stage: Ah(8K) Al(8K) Bh(8K) = 24KB; 3-stage cp.async pipeline.
// ---------------------------------------------------------------------------
#define GBM 128
#define GBN 128
#define GBK 32
#define OFF_AL 8192
#define OFF_BH 16384
#define BUF_B  24576
#define NSTAGE 3
#define GEMM_SMEM (NSTAGE * BUF_B)

__device__ __forceinline__ void issue_stage(
    uint32_t sdst,
    const __half* __restrict__ Ah, const __half* __restrict__ Al,
    const __half* __restrict__ Bh,
    int K, int k0, int tid)
{
#pragma unroll
    for (int it = 0; it < 6; it++) {
        const int tile = it >> 1;                 // 0..2 (Ah, Al, Bh)
        const int c = (it & 1) * 256 + tid;       // 0..511
        const int row = c >> 2;                   // 0..127
        const int col = c & 3;                    // 16B chunk within 64B row
        const uint32_t dst = sdst + tile * 8192 + row * 64
                           + (uint32_t)((col ^ (row & 3)) << 4);
        const __half* src;
        if (tile == 0)      src = Ah + (size_t)row * K + k0 + col * 8;
        else if (tile == 1) src = Al + (size_t)row * K + k0 + col * 8;
        else                src = Bh + (size_t)row * K + k0 + col * 8;
        asm volatile("cp.async.cg.shared.global [%0], [%1], 16;"
                     :: "r"(dst), "l"(src));
    }
}

__device__ __forceinline__ void gemm_body(
    const __half* __restrict__ Ahb, const __half* __restrict__ Alb,
    const __half* __restrict__ Bhb,
    const float* __restrict__ bias, float* __restrict__ C,
    int N, int K, int bm, int bn, char* smem)
{
    const uint32_t sbase = smem_u32(smem);
    const int tid = threadIdx.x;
    const int wid = tid >> 5;
    const int lane = tid & 31;
    const int warp_m = wid >> 2;
    const int warp_n = wid & 3;

    const int l7 = lane & 7;
    const int l3 = lane & 3;
    const int amat = lane >> 3;
    const uint32_t a_row64 = (uint32_t)(warp_m * 64 + ((amat & 1) << 3) + l7) * 64;
    const int a_kh = amat >> 1;
    const int b_kh = (lane >> 3) & 1;
    const uint32_t b_row64 = (uint32_t)(warp_n * 32 + ((lane >> 4) << 3) + l7) * 64;

    float acc[4][4][4];
#pragma unroll
    for (int i = 0; i < 4; i++)
#pragma unroll
        for (int j = 0; j < 4; j++)
#pragma unroll
            for (int c = 0; c < 4; c++) acc[i][j][c] = 0.f;

    const int NB = K / GBK;

    issue_stage(sbase, Ahb, Alb, Bhb, K, 0, tid);
    asm volatile("cp.async.commit_group;");
    issue_stage(sbase + BUF_B, Ahb, Alb, Bhb, K, GBK, tid);
    asm volatile("cp.async.commit_group;");

    for (int kb = 0; kb < NB; kb++) {
        asm volatile("cp.async.wait_group 1;");
        __syncthreads();

        const int nk = kb + 2;
        if (nk < NB)
            issue_stage(sbase + (uint32_t)(nk % NSTAGE) * BUF_B,
                        Ahb, Alb, Bhb, K, nk * GBK, tid);
        asm volatile("cp.async.commit_group;");

        const uint32_t bufc = sbase + (uint32_t)(kb % NSTAGE) * BUF_B;

#pragma unroll
        for (int ks = 0; ks < 2; ks++) {
            const uint32_t a_swoff = (uint32_t)(((ks * 2 + a_kh) ^ l3) << 4);
            const uint32_t b_swoff = (uint32_t)(((ks * 2 + b_kh) ^ l3) << 4);

            uint32_t ah[4][4];
#pragma unroll
            for (int mt = 0; mt < 4; mt++)
                ldsm4(ah[mt], bufc + a_row64 + (uint32_t)mt * 1024 + a_swoff);

            uint32_t bh[2][4];
#pragma unroll
            for (int p = 0; p < 2; p++)
                ldsm4(bh[p], bufc + OFF_BH + b_row64 + (uint32_t)p * 1024 + b_swoff);

            // term 1: Ah * B
#pragma unroll
            for (int mt = 0; mt < 4; mt++)
#pragma unroll
                for (int nt = 0; nt < 4; nt++)
                    mma_f16(acc[mt][nt], ah[mt], &bh[nt >> 1][(nt & 1) * 2]);

            // term 2: Al * B (ah dead -> regs reused)
            uint32_t al[4][4];
#pragma unroll
            for (int mt = 0; mt < 4; mt++)
                ldsm4(al[mt], bufc + OFF_AL + a_row64 + (uint32_t)mt * 1024 + a_swoff);
#pragma unroll
            for (int mt = 0; mt < 4; mt++)
#pragma unroll
                for (int nt = 0; nt < 4; nt++)
                    mma_f16(acc[mt][nt], al[mt], &bh[nt >> 1][(nt & 1) * 2]);
        }
    }

    const int g = lane >> 2;
    const int t = lane & 3;
#pragma unroll
    for (int nt = 0; nt < 4; nt++) {
        const int col = bn + warp_n * 32 + nt * 8 + 2 * t;
        const float b0 = bias[col];
        const float b1 = bias[col + 1];
#pragma unroll
        for (int mt = 0; mt < 4; mt++) {
            const int row = bm + warp_m * 64 + mt * 16 + g;
            float2 v0, v1;
            v0.x = acc[mt][nt][0] + b0;
            v0.y = acc[mt][nt][1] + b1;
            v1.x = acc[mt][nt][2] + b0;
            v1.y = acc[mt][nt][3] + b1;
            *(float2*)(C + (size_t)row * N + col) = v0;
            *(float2*)(C + (size_t)(row + 8) * N + col) = v1;
        }
    }
}

// Fused Q/K/V projection: grid.x in [0,48): [0,32)->Q, [32,40)->K, [40,48)->V
__global__ __launch_bounds__(256, 2)
void gemm_qkv(const __half* __restrict__ xh, const __half* __restrict__ xl,
              const __half* __restrict__ wq, const __half* __restrict__ wk,
              const __half* __restrict__ wv,
              const float* __restrict__ bq, const float* __restrict__ bk,
              const float* __restrict__ bv,
              float* __restrict__ q, float* __restrict__ k, float* __restrict__ v)
{
    extern __shared__ __align__(1024) char smem[];
    const int bx = blockIdx.x;
    const int bm = blockIdx.y * GBM;

    const __half* Bh;
    const float* bias;
    float* C;
    int N, bn;
    if (bx < 32) {
        Bh = wq; bias = bq; C = q; N = NH_ * HD_; bn = bx * GBN;
    } else if (bx < 40) {
        Bh = wk; bias = bk; C = k; N = NKV_ * HD_; bn = (bx - 32) * GBN;
    } else {
        Bh = wv; bias = bv; C = v; N = NKV_ * HD_; bn = (bx - 40) * GBN;
    }

    gemm_body(xh + (size_t)bm * HID_, xl + (size_t)bm * HID_,
              Bh + (size_t)bn * HID_, bias, C, N, HID_, bm, bn, smem);
}

// Generic GEMM (output projection)
__global__ __launch_bounds__(256, 2)
void gemm_f16_pipe(int M, int N, int K,
                   const __half* __restrict__ Ah,
                   const __half* __restrict__ Al,
                   const __half* __restrict__ Bh,
                   const float* __restrict__ bias,
                   float* __restrict__ C)
{
    extern __shared__ __align__(1024) char smem[];
    const int bm = blockIdx.y * GBM;
    const int bn = blockIdx.x * GBN;
    gemm_body(Ah + (size_t)bm * K, Al + (size_t)bm * K,
              Bh + (size_t)bn * K, bias, C, N, K, bm, bn, smem);
}

// ---------------------------------------------------------------------------
// Fused per-head LayerNorm + RoPE (unchanged, passing)
// ---------------------------------------------------------------------------
__global__ __launch_bounds__(128)
void ln_rope_kernel(float* __restrict__ data,
                    const float* __restrict__ gw,
                    const float* __restrict__ bw,
                    int H)
{
    const int s = blockIdx.x;
    const int d = threadIdx.x;
    __shared__ float red[8];
    __shared__ float xs[HD_];

    const int dd = d & 63;
    const float inv = exp2f(-(float)dd * (LOG2_THETA / 64.0f));
    const float th = (float)s * inv;
    float sn, cs;
    sincosf(th, &sn, &cs);

    const float gv = gw[d];
    const float bv = bw[d];
    const int lane = d & 31;
    const int w = d >> 5;

    for (int h = 0; h < H; h++) {
        float* x = data + ((size_t)s * H + h) * HD_;
        const float v = x[d];
        float s1 = v, s2 = v * v;
#pragma unroll
        for (int off = 16; off > 0; off >>= 1) {
            s1 += __shfl_xor_sync(0xffffffffu, s1, off);
            s2 += __shfl_xor_sync(0xffffffffu, s2, off);
        }
        if (lane == 0) { red[w] = s1; red[4 + w] = s2; }
        __syncthreads();
        const float sum = red[0] + red[1] + red[2] + red[3];
        const float sq  = red[4] + red[5] + red[6] + red[7];
        const float mu  = sum * (1.0f / HD_);
        const float var = sq * (1.0f / HD_) - mu * mu;
        const float r   = rsqrtf(var + EPS_);
        const float xn  = (v - mu) * r * gv + bv;
        xs[d] = xn;
        __syncthreads();
        const float other = (d < 64) ? -xs[d + 64] : xs[d - 64];
        x[d] = xn * cs + other * sn;
        __syncthreads();
    }
}

// ---------------------------------------------------------------------------
// Causal GQA flash attention, fp32 SIMT; writes output as fp16 hi/lo
// ---------------------------------------------------------------------------
#define BR 64
#define BC 64
#define QSTR 132
#define PSTR 72
#define FLASH_SMEM ((3 * BC * QSTR + BR * PSTR) * 4)

__global__ __launch_bounds__(128)
void flash_kernel(const float* __restrict__ Q,
                  const float* __restrict__ K,
                  const float* __restrict__ V,
                  __half* __restrict__ Oh,
                  __half* __restrict__ Ol)
{
    extern __shared__ float sh[];
    float* Qs = sh;
    float* Ks = Qs + BR * QSTR;
    float* Vs = Ks + BC * QSTR;
    float* Ps = Vs + BC * QSTR;

    const int qb = blockIdx.x;
    const int h = blockIdx.y;
    const int kvh = h / (NH_ / NKV_);
    const int q0 = qb * BR;
    const int tid = threadIdx.x;
    const int ty = tid >> 3;
    const int tx = tid & 7;

    {
        const int r = tid >> 1;
        const int half = (tid & 1) * 64;
        const float* src = Q + ((size_t)(q0 + r) * NH_ + h) * HD_ + half;
        float* dst = Qs + r * QSTR + half;
#pragma unroll
        for (int i = 0; i < 16; i++)
            *(float4*)(dst + i * 4) = *(const float4*)(src + i * 4);
    }

    float m[4], l[4], o[4][16];
#pragma unroll
    for (int i = 0; i < 4; i++) {
        m[i] = -1e30f; l[i] = 0.f;
#pragma unroll
        for (int c = 0; c < 16; c++) o[i][c] = 0.f;
    }

    const int nkv = qb + 1;
    for (int kb = 0; kb < nkv; kb++) {
        const int k0 = kb * BC;
        __syncthreads();
        {
            const int r = tid >> 1;
            const int half = (tid & 1) * 64;
            const float* ks = K + ((size_t)(k0 + r) * NKV_ + kvh) * HD_ + half;
            const float* vs = V + ((size_t)(k0 + r) * NKV_ + kvh) * HD_ + half;
            float* kd = Ks + r * QSTR + half;
            float* vd = Vs + r * QSTR + half;
#pragma unroll
            for (int i = 0; i < 16; i++) {
                *(float4*)(kd + i * 4) = *(const float4*)(ks + i * 4);
                *(float4*)(vd + i * 4) = *(const float4*)(vs + i * 4);
            }
        }
        __syncthreads();

        float acc[4][8];
#pragma unroll
        for (int i = 0; i < 4; i++)
#pragma unroll
            for (int j = 0; j < 8; j++) acc[i][j] = 0.f;

#pragma unroll 2
        for (int d0 = 0; d0 < HD_; d0 += 4) {
            float4 qv[4], kv[8];
#pragma unroll
            for (int i = 0; i < 4; i++)
                qv[i] = *(const float4*)(Qs + (i * 16 + ty) * QSTR + d0);
#pragma unroll
            for (int j = 0; j < 8; j++)
                kv[j] = *(const float4*)(Ks + (j * 8 + tx) * QSTR + d0);
#pragma unroll
            for (int i = 0; i < 4; i++)
#pragma unroll
                for (int j = 0; j < 8; j++) {
                    acc[i][j] += qv[i].x * kv[j].x;
                    acc[i][j] += qv[i].y * kv[j].y;
                    acc[i][j] += qv[i].z * kv[j].z;
                    acc[i][j] += qv[i].w * kv[j].w;
                }
        }

        const bool diag = (kb == qb);
#pragma unroll
        for (int i = 0; i < 4; i++) {
            const int qr = q0 + i * 16 + ty;
            float mx = -1e30f;
#pragma unroll
            for (int j = 0; j < 8; j++) {
                float v = acc[i][j] * SCALE_;
                if (diag && (k0 + j * 8 + tx) > qr) v = -1e30f;
                acc[i][j] = v;
                mx = fmaxf(mx, v);
            }
            mx = fmaxf(mx, __shfl_xor_sync(0xffffffffu, mx, 1));
            mx = fmaxf(mx, __shfl_xor_sync(0xffffffffu, mx, 2));
            mx = fmaxf(mx, __shfl_xor_sync(0xffffffffu, mx, 4));
            const float mnew = fmaxf(m[i], mx);
            const float alpha = __expf(m[i] - mnew);
            m[i] = mnew;
            float rs = 0.f;
#pragma unroll
            for (int j = 0; j < 8; j++) {
                const float p = __expf(acc[i][j] - mnew);
                acc[i][j] = p;
                rs += p;
            }
            rs += __shfl_xor_sync(0xffffffffu, rs, 1);
            rs += __shfl_xor_sync(0xffffffffu, rs, 2);
            rs += __shfl_xor_sync(0xffffffffu, rs, 4);
            l[i] = l[i] * alpha + rs;
#pragma unroll
            for (int c = 0; c < 16; c++) o[i][c] *= alpha;
#pragma unroll
            for (int j = 0; j < 8; j++)
                Ps[(i * 16 + ty) * PSTR + j * 8 + tx] = acc[i][j];
        }
        __syncthreads();

#pragma unroll 2
        for (int j4 = 0; j4 < BC; j4 += 4) {
            float pr[4][4];
#pragma unroll
            for (int i = 0; i < 4; i++) {
                float4 pv = *(const float4*)(Ps + (i * 16 + ty) * PSTR + j4);
                pr[i][0] = pv.x; pr[i][1] = pv.y; pr[i][2] = pv.z; pr[i][3] = pv.w;
            }
#pragma unroll
            for (int jj = 0; jj < 4; jj++) {
                float4 vv[4];
#pragma unroll
                for (int c4 = 0; c4 < 4; c4++)
                    vv[c4] = *(const float4*)(Vs + (j4 + jj) * QSTR + tx * 16 + c4 * 4);
#pragma unroll
                for (int i = 0; i < 4; i++) {
                    const float p = pr[i][jj];
#pragma unroll
                    for (int c4 = 0; c4 < 4; c4++) {
                        o[i][c4 * 4 + 0] += p * vv[c4].x;
                        o[i][c4 * 4 + 1] += p * vv[c4].y;
                        o[i][c4 * 4 + 2] += p * vv[c4].z;
                        o[i][c4 * 4 + 3] += p * vv[c4].w;
                    }
                }
            }
        }
    }

    // epilogue: O /= l, split to fp16 hi/lo
#pragma unroll
    for (int i = 0; i < 4; i++) {
        const float inv = 1.0f / l[i];
        const size_t off = ((size_t)(q0 + i * 16 + ty) * NH_ + h) * HD_ + tx * 16;
#pragma unroll
        for (int c4 = 0; c4 < 4; c4++) {
            float4 w;
            w.x = o[i][c4 * 4 + 0] * inv;
            w.y = o[i][c4 * 4 + 1] * inv;
            w.z = o[i][c4 * 4 + 2] * inv;
            w.w = o[i][c4 * 4 + 3] * inv;
            uint2 hh, ll;
            split4_h(w, hh, ll);
            *(uint2*)(Oh + off + c4 * 4) = hh;
            *(uint2*)(Ol + off + c4 * 4) = ll;
        }
    }
}

// ---------------------------------------------------------------------------
// Launch
// ---------------------------------------------------------------------------
extern "C" void kernel_launch(void* const* d_in, const int* in_sizes, int n_in,
                              void* d_out, int out_size)
{
    const float* x   = (const float*)d_in[0];
    const float* Wq  = (const float*)d_in[1];
    const float* bq  = (const float*)d_in[2];
    const float* Wk  = (const float*)d_in[3];
    const float* bk  = (const float*)d_in[4];
    const float* Wv  = (const float*)d_in[5];
    const float* bv  = (const float*)d_in[6];
    const float* Wo  = (const float*)d_in[7];
    const float* bo  = (const float*)d_in[8];
    const float* qng = (const float*)d_in[9];
    const float* qnb = (const float*)d_in[10];
    const float* kng = (const float*)d_in[11];
    const float* knb = (const float*)d_in[12];
    float* out = (float*)d_out;

    float *qp, *kp, *vp;
    __half *xh, *xl, *wq16, *wk16, *wv16, *wo16, *aoh, *aol;
    cudaGetSymbolAddress((void**)&qp, g_q);
    cudaGetSymbolAddress((void**)&kp, g_k);
    cudaGetSymbolAddress((void**)&vp, g_v);
    cudaGetSymbolAddress((void**)&xh, g_xh);     cudaGetSymbolAddress((void**)&xl, g_xl);
    cudaGetSymbolAddress((void**)&wq16, g_wq16);
    cudaGetSymbolAddress((void**)&wk16, g_wk16);
    cudaGetSymbolAddress((void**)&wv16, g_wv16);
    cudaGetSymbolAddress((void**)&wo16, g_wo16);
    cudaGetSymbolAddress((void**)&aoh, g_aoh);   cudaGetSymbolAddress((void**)&aol, g_aol);

    cudaFuncSetAttribute(gemm_qkv, cudaFuncAttributeMaxDynamicSharedMemorySize,
                         GEMM_SMEM);
    cudaFuncSetAttribute(gemm_f16_pipe, cudaFuncAttributeMaxDynamicSharedMemorySize,
                         GEMM_SMEM);
    cudaFuncSetAttribute(flash_kernel, cudaFuncAttributeMaxDynamicSharedMemorySize,
                         FLASH_SMEM);

    const int n4_x  = S_ * HID_ / 4;
    const int n4_wq = NH_ * HD_ * HID_ / 4;
    const int n4_wk = NKV_ * HD_ * HID_ / 4;
    const int n4_wo = HID_ * HID_ / 4;
    split_kernel<<<n4_x / 256, 256>>>(x, xh, xl, n4_x);
    cast_kernel<<<n4_wq / 256, 256>>>(Wq, wq16, n4_wq);
    cast_kernel<<<n4_wk / 256, 256>>>(Wk, wk16, n4_wk);
    cast_kernel<<<n4_wk / 256, 256>>>(Wv, wv16, n4_wk);
    cast_kernel<<<n4_wo / 256, 256>>>(Wo, wo16, n4_wo);

    // fused QKV projection (fp16 2-term)
    gemm_qkv<<<dim3(48, S_ / GBM), 256, GEMM_SMEM>>>(
        xh, xl, wq16, wk16, wv16, bq, bk, bv, qp, kp, vp);

    // per-head LayerNorm + RoPE (in place)
    ln_rope_kernel<<<S_, HD_>>>(qp, qng, qnb, NH_);
    ln_rope_kernel<<<S_, HD_>>>(kp, kng, knb, NKV_);

    // causal GQA flash attention -> fp16 hi/lo output
    flash_kernel<<<dim3(S_ / BR, NH_), 128, FLASH_SMEM>>>(qp, kp, vp, aoh, aol);

    // output projection (fp16 2-term)
    gemm_f16_pipe<<<dim3(HID_ / GBN, S_ / GBM), 256, GEMM_SMEM>>>(
        S_, HID_, HID_, aoh, aol, wo16, bo, out);
}

// round 12
// speedup vs baseline: 3.9565x; 2.0986x over previous
#include <cuda_runtime.h>
#include <cuda_fp16.h>
#include <math.h>
#include <cstdint>

// Problem constants
#define S_    2048
#define HID_  4096
#define NH_   32
#define NKV_  8
#define HD_   128
#define EPS_  1e-5f
#define SCALE_ 0.088388347648318447f
// SCALE_ * log2(e)  (softmax done in exp2 domain)
#define SC2_  (SCALE_ * 1.4426950408889634f)
#define LOG2_THETA 18.931568569324174f

// ---------------------------------------------------------------------------
// Scratch (device globals; no allocation allowed)
// ---------------------------------------------------------------------------
__device__ float g_q[S_ * NH_ * HD_];
__device__ float g_k[S_ * NKV_ * HD_];
__device__ float g_v[S_ * NKV_ * HD_];
__device__ __half g_xh[S_ * HID_],  g_xl[S_ * HID_];
__device__ __half g_wq16[NH_ * HD_ * HID_];
__device__ __half g_wk16[NKV_ * HD_ * HID_];
__device__ __half g_wv16[NKV_ * HD_ * HID_];
__device__ __half g_wo16[HID_ * HID_];
__device__ __half g_aoh[S_ * HID_], g_aol[S_ * HID_];
// fp16 attention operands
__device__ __half g_q16[S_ * NH_ * HD_], g_ql16[S_ * NH_ * HD_];
__device__ __half g_kh16[S_ * NKV_ * HD_], g_kl16[S_ * NKV_ * HD_];
__device__ __half g_vh16[S_ * NKV_ * HD_], g_vl16[S_ * NKV_ * HD_];

// ---------------------------------------------------------------------------
// Helpers
// ---------------------------------------------------------------------------
__device__ __forceinline__ uint32_t smem_u32(const void* p) {
    uint32_t a;
    asm("{ .reg .u64 t; cvta.to.shared.u64 t, %1; cvt.u32.u64 %0, t; }"
        : "=r"(a) : "l"(p));
    return a;
}

__device__ __forceinline__ void ldsm4(uint32_t* r, uint32_t addr) {
    asm volatile("ldmatrix.sync.aligned.m8n8.x4.shared.b16 {%0,%1,%2,%3}, [%4];"
                 : "=r"(r[0]), "=r"(r[1]), "=r"(r[2]), "=r"(r[3]) : "r"(addr));
}

__device__ __forceinline__ void ldsm4t(uint32_t* r, uint32_t addr) {
    asm volatile("ldmatrix.sync.aligned.m8n8.x4.trans.shared.b16 {%0,%1,%2,%3}, [%4];"
                 : "=r"(r[0]), "=r"(r[1]), "=r"(r[2]), "=r"(r[3]) : "r"(addr));
}

__device__ __forceinline__ void mma_f16(float* d, const uint32_t* a, const uint32_t* b) {
    asm volatile(
        "mma.sync.aligned.m16n8k16.row.col.f32.f16.f16.f32 "
        "{%0,%1,%2,%3}, {%4,%5,%6,%7}, {%8,%9}, {%0,%1,%2,%3};"
        : "+f"(d[0]), "+f"(d[1]), "+f"(d[2]), "+f"(d[3])
        : "r"(a[0]), "r"(a[1]), "r"(a[2]), "r"(a[3]), "r"(b[0]), "r"(b[1]));
}

__device__ __forceinline__ void cpa16(uint32_t dst, const void* src) {
    asm volatile("cp.async.cg.shared.global [%0], [%1], 16;" :: "r"(dst), "l"(src));
}

__device__ __forceinline__ uint32_t pkh(__half a, __half b) {
    __half2 t = __halves2half2(a, b);
    return *reinterpret_cast<uint32_t*>(&t);
}

__device__ __forceinline__ void split4_h(float4 v, uint2& hi, uint2& lo) {
    __half h0 = __float2half_rn(v.x);
    __half h1 = __float2half_rn(v.y);
    __half h2 = __float2half_rn(v.z);
    __half h3 = __float2half_rn(v.w);
    __half l0 = __float2half_rn(v.x - __half2float(h0));
    __half l1 = __float2half_rn(v.y - __half2float(h1));
    __half l2 = __float2half_rn(v.z - __half2float(h2));
    __half l3 = __float2half_rn(v.w - __half2float(h3));
    hi.x = pkh(h0, h1); hi.y = pkh(h2, h3);
    lo.x = pkh(l0, l1); lo.y = pkh(l2, l3);
}

__device__ __forceinline__ uint2 cast4_h(float4 v) {
    uint2 r;
    r.x = pkh(__float2half_rn(v.x), __float2half_rn(v.y));
    r.y = pkh(__float2half_rn(v.z), __float2half_rn(v.w));
    return r;
}

// ---------------------------------------------------------------------------
// fp32 -> fp16 hi/lo split, and plain cast
// ---------------------------------------------------------------------------
__global__ __launch_bounds__(256)
void split_kernel(const float* __restrict__ in,
                  __half* __restrict__ hi,
                  __half* __restrict__ lo, int n4)
{
    const int idx = blockIdx.x * 256 + threadIdx.x;
    if (idx >= n4) return;
    float4 v = ((const float4*)in)[idx];
    uint2 h, l;
    split4_h(v, h, l);
    ((uint2*)hi)[idx] = h;
    ((uint2*)lo)[idx] = l;
}

__global__ __launch_bounds__(256)
void cast_kernel(const float* __restrict__ in, __half* __restrict__ out, int n4)
{
    const int idx = blockIdx.x * 256 + threadIdx.x;
    if (idx >= n4) return;
    ((uint2*)out)[idx] = cast4_h(((const float4*)in)[idx]);
}

// ---------------------------------------------------------------------------
// fp16 2-term GEMM (unchanged math; pipeline deepened to 4 stages)
// ---------------------------------------------------------------------------
#define GBM 128
#define GBN 128
#define GBK 32
#define OFF_AL 8192
#define OFF_BH 16384
#define BUF_B  24576
#define NSTAGE 4
#define GEMM_SMEM (NSTAGE * BUF_B)

__device__ __forceinline__ void issue_stage(
    uint32_t sdst,
    const __half* __restrict__ Ah, const __half* __restrict__ Al,
    const __half* __restrict__ Bh,
    int K, int k0, int tid)
{
#pragma unroll
    for (int it = 0; it < 6; it++) {
        const int tile = it >> 1;
        const int c = (it & 1) * 256 + tid;
        const int row = c >> 2;
        const int col = c & 3;
        const uint32_t dst = sdst + tile * 8192 + row * 64
                           + (uint32_t)((col ^ (row & 3)) << 4);
        const __half* src;
        if (tile == 0)      src = Ah + (size_t)row * K + k0 + col * 8;
        else if (tile == 1) src = Al + (size_t)row * K + k0 + col * 8;
        else                src = Bh + (size_t)row * K + k0 + col * 8;
        cpa16(dst, src);
    }
}

__device__ __forceinline__ void gemm_body(
    const __half* __restrict__ Ahb, const __half* __restrict__ Alb,
    const __half* __restrict__ Bhb,
    const float* __restrict__ bias, float* __restrict__ C,
    int N, int K, int bm, int bn, char* smem)
{
    const uint32_t sbase = smem_u32(smem);
    const int tid = threadIdx.x;
    const int wid = tid >> 5;
    const int lane = tid & 31;
    const int warp_m = wid >> 2;
    const int warp_n = wid & 3;

    const int l7 = lane & 7;
    const int l3 = lane & 3;
    const int amat = lane >> 3;
    const uint32_t a_row64 = (uint32_t)(warp_m * 64 + ((amat & 1) << 3) + l7) * 64;
    const int a_kh = amat >> 1;
    const int b_kh = (lane >> 3) & 1;
    const uint32_t b_row64 = (uint32_t)(warp_n * 32 + ((lane >> 4) << 3) + l7) * 64;

    float acc[4][4][4];
#pragma unroll
    for (int i = 0; i < 4; i++)
#pragma unroll
        for (int j = 0; j < 4; j++)
#pragma unroll
            for (int c = 0; c < 4; c++) acc[i][j][c] = 0.f;

    const int NB = K / GBK;

    issue_stage(sbase, Ahb, Alb, Bhb, K, 0, tid);
    asm volatile("cp.async.commit_group;");
    issue_stage(sbase + BUF_B, Ahb, Alb, Bhb, K, GBK, tid);
    asm volatile("cp.async.commit_group;");
    issue_stage(sbase + 2 * BUF_B, Ahb, Alb, Bhb, K, 2 * GBK, tid);
    asm volatile("cp.async.commit_group;");

    for (int kb = 0; kb < NB; kb++) {
        asm volatile("cp.async.wait_group 2;");
        __syncthreads();

        const int nk = kb + 3;
        if (nk < NB)
            issue_stage(sbase + (uint32_t)(nk % NSTAGE) * BUF_B,
                        Ahb, Alb, Bhb, K, nk * GBK, tid);
        asm volatile("cp.async.commit_group;");

        const uint32_t bufc = sbase + (uint32_t)(kb % NSTAGE) * BUF_B;

#pragma unroll
        for (int ks = 0; ks < 2; ks++) {
            const uint32_t a_swoff = (uint32_t)(((ks * 2 + a_kh) ^ l3) << 4);
            const uint32_t b_swoff = (uint32_t)(((ks * 2 + b_kh) ^ l3) << 4);

            uint32_t ah[4][4];
#pragma unroll
            for (int mt = 0; mt < 4; mt++)
                ldsm4(ah[mt], bufc + a_row64 + (uint32_t)mt * 1024 + a_swoff);

            uint32_t bh[2][4];
#pragma unroll
            for (int p = 0; p < 2; p++)
                ldsm4(bh[p], bufc + OFF_BH + b_row64 + (uint32_t)p * 1024 + b_swoff);

#pragma unroll
            for (int mt = 0; mt < 4; mt++)
#pragma unroll
                for (int nt = 0; nt < 4; nt++)
                    mma_f16(acc[mt][nt], ah[mt], &bh[nt >> 1][(nt & 1) * 2]);

            uint32_t al[4][4];
#pragma unroll
            for (int mt = 0; mt < 4; mt++)
                ldsm4(al[mt], bufc + OFF_AL + a_row64 + (uint32_t)mt * 1024 + a_swoff);
#pragma unroll
            for (int mt = 0; mt < 4; mt++)
#pragma unroll
                for (int nt = 0; nt < 4; nt++)
                    mma_f16(acc[mt][nt], al[mt], &bh[nt >> 1][(nt & 1) * 2]);
        }
    }

    const int g = lane >> 2;
    const int t = lane & 3;
#pragma unroll
    for (int nt = 0; nt < 4; nt++) {
        const int col = bn + warp_n * 32 + nt * 8 + 2 * t;
        const float b0 = bias[col];
        const float b1 = bias[col + 1];
#pragma unroll
        for (int mt = 0; mt < 4; mt++) {
            const int row = bm + warp_m * 64 + mt * 16 + g;
            float2 v0, v1;
            v0.x = acc[mt][nt][0] + b0;
            v0.y = acc[mt][nt][1] + b1;
            v1.x = acc[mt][nt][2] + b0;
            v1.y = acc[mt][nt][3] + b1;
            *(float2*)(C + (size_t)row * N + col) = v0;
            *(float2*)(C + (size_t)(row + 8) * N + col) = v1;
        }
    }
}

__global__ __launch_bounds__(256, 2)
void gemm_qkv(const __half* __restrict__ xh, const __half* __restrict__ xl,
              const __half* __restrict__ wq, const __half* __restrict__ wk,
              const __half* __restrict__ wv,
              const float* __restrict__ bq, const float* __restrict__ bk,
              const float* __restrict__ bv,
              float* __restrict__ q, float* __restrict__ k, float* __restrict__ v)
{
    extern __shared__ __align__(1024) char smem[];
    const int bx = blockIdx.x;
    const int bm = blockIdx.y * GBM;

    const __half* Bh;
    const float* bias;
    float* C;
    int N, bn;
    if (bx < 32) {
        Bh = wq; bias = bq; C = q; N = NH_ * HD_; bn = bx * GBN;
    } else if (bx < 40) {
        Bh = wk; bias = bk; C = k; N = NKV_ * HD_; bn = (bx - 32) * GBN;
    } else {
        Bh = wv; bias = bv; C = v; N = NKV_ * HD_; bn = (bx - 40) * GBN;
    }

    gemm_body(xh + (size_t)bm * HID_, xl + (size_t)bm * HID_,
              Bh + (size_t)bn * HID_, bias, C, N, HID_, bm, bn, smem);
}

__global__ __launch_bounds__(256, 2)
void gemm_f16_pipe(int M, int N, int K,
                   const __half* __restrict__ Ah,
                   const __half* __restrict__ Al,
                   const __half* __restrict__ Bh,
                   const float* __restrict__ bias,
                   float* __restrict__ C)
{
    extern __shared__ __align__(1024) char smem[];
    const int bm = blockIdx.y * GBM;
    const int bn = blockIdx.x * GBN;
    gemm_body(Ah + (size_t)bm * K, Al + (size_t)bm * K,
              Bh + (size_t)bn * K, bias, C, N, K, bm, bn, smem);
}

// ---------------------------------------------------------------------------
// Fused per-head LayerNorm + RoPE; reads fp32, writes fp16 hi/lo
// ---------------------------------------------------------------------------
__global__ __launch_bounds__(128)
void ln_rope16(const float* __restrict__ in,
               __half* __restrict__ oh, __half* __restrict__ ol,
               const float* __restrict__ gw,
               const float* __restrict__ bw,
               int H)
{
    const int s = blockIdx.x;
    const int d = threadIdx.x;
    __shared__ float red[8];
    __shared__ float xs[HD_];

    const int dd = d & 63;
    const float inv = exp2f(-(float)dd * (LOG2_THETA / 64.0f));
    const float th = (float)s * inv;
    float sn, cs;
    sincosf(th, &sn, &cs);

    const float gv = gw[d];
    const float bv = bw[d];
    const int lane = d & 31;
    const int w = d >> 5;

    for (int h = 0; h < H; h++) {
        const float* x = in + ((size_t)s * H + h) * HD_;
        const float v = x[d];
        float s1 = v, s2 = v * v;
#pragma unroll
        for (int off = 16; off > 0; off >>= 1) {
            s1 += __shfl_xor_sync(0xffffffffu, s1, off);
            s2 += __shfl_xor_sync(0xffffffffu, s2, off);
        }
        if (lane == 0) { red[w] = s1; red[4 + w] = s2; }
        __syncthreads();
        const float sum = red[0] + red[1] + red[2] + red[3];
        const float sq  = red[4] + red[5] + red[6] + red[7];
        const float mu  = sum * (1.0f / HD_);
        const float var = sq * (1.0f / HD_) - mu * mu;
        const float r   = rsqrtf(var + EPS_);
        const float xn  = (v - mu) * r * gv + bv;
        xs[d] = xn;
        __syncthreads();
        const float other = (d < 64) ? -xs[d + 64] : xs[d - 64];
        const float res = xn * cs + other * sn;
        const size_t idx = ((size_t)s * H + h) * HD_ + d;
        const __half rh = __float2half_rn(res);
        oh[idx] = rh;
        ol[idx] = __float2half_rn(res - __half2float(rh));
        __syncthreads();
    }
}

// ---------------------------------------------------------------------------
// Flash attention on mma.sync fp16.
// BR=128 (8 warps x m16), BC=64, 256 threads, 1 CTA/SM.
// Q plain fp16; K split hi/lo (QK 2-term); P split in-register, V split
// hi/lo (PV 3-term: PhVh + PhVl + PlVh).
// SMEM: Q (4 chunks x 8KB) + 2 KV buffers of [Kh|Kl|Vh|Vl] 16KB tiles.
// Chunked layout: [row][64B] rows, 16B unit u swizzled by u ^= (row&3).
// ---------------------------------------------------------------------------
#define FBR 128
#define FBC 64
#define FQ_CH 8192
#define FKV_CH 4096
#define FKV_TILE 16384
#define FBUF 65536
#define FSMEM (32768 + 2 * FBUF)

__device__ __forceinline__ void kv_stage(
    uint32_t dstbase,
    const __half* __restrict__ Kh, const __half* __restrict__ Kl,
    const __half* __restrict__ Vh, const __half* __restrict__ Vl,
    int kvh, int k0, int tid)
{
#pragma unroll
    for (int it = 0; it < 16; it++) {
        const int idx = it * 256 + tid;
        const int tile = idx >> 10;             // 0..3 = Kh,Kl,Vh,Vl
        const int sub = idx & 1023;
        const int row = sub >> 4;               // 0..63
        const int u8 = sub & 15;
        const __half* base = (tile == 0) ? Kh : (tile == 1) ? Kl
                           : (tile == 2) ? Vh : Vl;
        const __half* src = base + ((size_t)(k0 + row) * NKV_ + kvh) * HD_ + u8 * 8;
        const uint32_t dst = dstbase + tile * FKV_TILE + (u8 >> 2) * FKV_CH
                           + row * 64 + (uint32_t)(((u8 & 3) ^ (row & 3)) << 4);
        cpa16(dst, src);
    }
}

__global__ __launch_bounds__(256, 1)
void flash_mma(const __half* __restrict__ Q16,
               const __half* __restrict__ Kh16, const __half* __restrict__ Kl16,
               const __half* __restrict__ Vh16, const __half* __restrict__ Vl16,
               __half* __restrict__ Oh, __half* __restrict__ Ol)
{
    extern __shared__ __align__(1024) char smem[];
    const uint32_t sbase = smem_u32(smem);
    const int qb = (int)gridDim.x - 1 - (int)blockIdx.x;   // big tiles first
    const int h = blockIdx.y;
    const int kvh = h >> 2;
    const int q0 = qb * FBR;
    const int tid = threadIdx.x;
    const int w = tid >> 5;
    const int lane = tid & 31;

    // prologue: Q + KV block 0
#pragma unroll
    for (int it = 0; it < 8; it++) {
        const int idx = it * 256 + tid;
        const int row = idx >> 4;
        const int u8 = idx & 15;
        const __half* src = Q16 + ((size_t)(q0 + row) * NH_ + h) * HD_ + u8 * 8;
        const uint32_t dst = sbase + (u8 >> 2) * FQ_CH + row * 64
                           + (uint32_t)(((u8 & 3) ^ (row & 3)) << 4);
        cpa16(dst, src);
    }
    kv_stage(sbase + 32768, Kh16, Kl16, Vh16, Vl16, kvh, 0, tid);
    asm volatile("cp.async.commit_group;");

    float o[16][4];
#pragma unroll
    for (int i = 0; i < 16; i++)
#pragma unroll
        for (int c = 0; c < 4; c++) o[i][c] = 0.f;
    float m0 = -1e30f, m1 = -1e30f, l0 = 0.f, l1 = 0.f;

    // per-lane fragment bases
    const int l7 = lane & 7;
    const int qrow = w * 16 + ((lane >> 3) & 1) * 8 + l7;
    const int qm2 = lane >> 4;
    const int krow_base = ((lane >> 4) << 3) + l7;
    const int kh_sel = (lane >> 3) & 1;
    const int vrow_base = ((lane >> 3) & 1) * 8 + l7;
    const int vm2 = lane >> 4;

    const int nb = 2 * qb + 2;
    for (int kb = 0; kb < nb; kb++) {
        if (kb + 1 < nb)
            kv_stage(sbase + 32768 + ((kb + 1) & 1) * FBUF,
                     Kh16, Kl16, Vh16, Vl16, kvh, (kb + 1) * FBC, tid);
        asm volatile("cp.async.commit_group;");
        asm volatile("cp.async.wait_group 1;");
        __syncthreads();

        const uint32_t B = sbase + 32768 + (uint32_t)(kb & 1) * FBUF;

        // ---- QK: sc = Q (Kh + Kl)^T ----
        float sc[8][4];
#pragma unroll
        for (int i = 0; i < 8; i++)
#pragma unroll
            for (int c = 0; c < 4; c++) sc[i][c] = 0.f;

#pragma unroll
        for (int kd = 0; kd < 8; kd++) {
            uint32_t qa[4];
            {
                const int u8 = kd * 2 + qm2;
                ldsm4(qa, sbase + (u8 >> 2) * FQ_CH + qrow * 64
                          + (uint32_t)(((u8 & 3) ^ (qrow & 3)) << 4));
            }
            const int u8k = kd * 2 + kh_sel;
#pragma unroll
            for (int j = 0; j < 4; j++) {
                const int krow = j * 16 + krow_base;
                const uint32_t koff = (u8k >> 2) * FKV_CH + krow * 64
                                    + (uint32_t)(((u8k & 3) ^ (krow & 3)) << 4);
                uint32_t kbh[4], kbl[4];
                ldsm4(kbh, B + koff);
                ldsm4(kbl, B + FKV_TILE + koff);
                mma_f16(sc[2 * j],     qa, &kbh[0]);
                mma_f16(sc[2 * j + 1], qa, &kbh[2]);
                mma_f16(sc[2 * j],     qa, &kbl[0]);
                mma_f16(sc[2 * j + 1], qa, &kbl[2]);
            }
        }

        // ---- softmax (exp2 domain) ----
        const int row0 = q0 + w * 16 + (lane >> 2);
        const int col_base = kb * FBC + (lane & 3) * 2;
        const bool maybe_mask = (kb * FBC + FBC - 1) > (q0 + w * 16);
        float mx0 = -1e30f, mx1 = -1e30f;
#pragma unroll
        for (int nt = 0; nt < 8; nt++) {
            float v0 = sc[nt][0] * SC2_;
            float v1 = sc[nt][1] * SC2_;
            float v2 = sc[nt][2] * SC2_;
            float v3 = sc[nt][3] * SC2_;
            if (maybe_mask) {
                const int c0 = col_base + nt * 8;
                if (c0 > row0)         v0 = -1e30f;
                if (c0 + 1 > row0)     v1 = -1e30f;
                if (c0 > row0 + 8)     v2 = -1e30f;
                if (c0 + 1 > row0 + 8) v3 = -1e30f;
            }
            sc[nt][0] = v0; sc[nt][1] = v1; sc[nt][2] = v2; sc[nt][3] = v3;
            mx0 = fmaxf(mx0, fmaxf(v0, v1));
            mx1 = fmaxf(mx1, fmaxf(v2, v3));
        }
        mx0 = fmaxf(mx0, __shfl_xor_sync(0xffffffffu, mx0, 1));
        mx0 = fmaxf(mx0, __shfl_xor_sync(0xffffffffu, mx0, 2));
        mx1 = fmaxf(mx1, __shfl_xor_sync(0xffffffffu, mx1, 1));
        mx1 = fmaxf(mx1, __shfl_xor_sync(0xffffffffu, mx1, 2));
        const float mn0 = fmaxf(m0, mx0);
        const float mn1 = fmaxf(m1, mx1);
        const float al0 = exp2f(m0 - mn0);
        const float al1 = exp2f(m1 - mn1);
        m0 = mn0; m1 = mn1;

        uint32_t ph[8][2], pl[8][2];
        float rs0 = 0.f, rs1 = 0.f;
#pragma unroll
        for (int nt = 0; nt < 8; nt++) {
            const float p0 = exp2f(sc[nt][0] - mn0);
            const float p1 = exp2f(sc[nt][1] - mn0);
            const float p2 = exp2f(sc[nt][2] - mn1);
            const float p3 = exp2f(sc[nt][3] - mn1);
            rs0 += p0 + p1; rs1 += p2 + p3;
            const __half h0 = __float2half_rn(p0), h1 = __float2half_rn(p1);
            const __half h2 = __float2half_rn(p2), h3 = __float2half_rn(p3);
            ph[nt][0] = pkh(h0, h1);
            ph[nt][1] = pkh(h2, h3);
            pl[nt][0] = pkh(__float2half_rn(p0 - __half2float(h0)),
                            __float2half_rn(p1 - __half2float(h1)));
            pl[nt][1] = pkh(__float2half_rn(p2 - __half2float(h2)),
                            __float2half_rn(p3 - __half2float(h3)));
        }
        rs0 += __shfl_xor_sync(0xffffffffu, rs0, 1);
        rs0 += __shfl_xor_sync(0xffffffffu, rs0, 2);
        rs1 += __shfl_xor_sync(0xffffffffu, rs1, 1);
        rs1 += __shfl_xor_sync(0xffffffffu, rs1, 2);
        l0 = l0 * al0 + rs0;
        l1 = l1 * al1 + rs1;
#pragma unroll
        for (int j = 0; j < 16; j++) {
            o[j][0] *= al0; o[j][1] *= al0;
            o[j][2] *= al1; o[j][3] *= al1;
        }

        // ---- PV: o += Ph Vh + Ph Vl + Pl Vh ----
#pragma unroll
        for (int ks = 0; ks < 4; ks++) {
            uint32_t aph[4] = { ph[2 * ks][0], ph[2 * ks][1],
                                ph[2 * ks + 1][0], ph[2 * ks + 1][1] };
            uint32_t apl[4] = { pl[2 * ks][0], pl[2 * ks][1],
                                pl[2 * ks + 1][0], pl[2 * ks + 1][1] };
            const int vrow = ks * 16 + vrow_base;
#pragma unroll
            for (int j = 0; j < 8; j++) {
                const int u8 = 2 * j + vm2;
                const uint32_t voff = (u8 >> 2) * FKV_CH + vrow * 64
                                    + (uint32_t)(((u8 & 3) ^ (vrow & 3)) << 4);
                uint32_t vh4[4], vl4[4];
                ldsm4t(vh4, B + 2 * FKV_TILE + voff);
                ldsm4t(vl4, B + 3 * FKV_TILE + voff);
                mma_f16(o[2 * j],     aph, &vh4[0]);
                mma_f16(o[2 * j + 1], aph, &vh4[2]);
                mma_f16(o[2 * j],     aph, &vl4[0]);
                mma_f16(o[2 * j + 1], aph, &vl4[2]);
                mma_f16(o[2 * j],     apl, &vh4[0]);
                mma_f16(o[2 * j + 1], apl, &vh4[2]);
            }
        }
        __syncthreads();
    }

    // ---- epilogue: O /= l, split fp16 hi/lo, store ----
    const float inv0 = 1.f / l0;
    const float inv1 = 1.f / l1;
    const int r0 = q0 + w * 16 + (lane >> 2);
    const size_t base0 = ((size_t)r0 * NH_ + h) * HD_ + (lane & 3) * 2;
    const size_t base1 = ((size_t)(r0 + 8) * NH_ + h) * HD_ + (lane & 3) * 2;
#pragma unroll
    for (int nt = 0; nt < 16; nt++) {
        const float x0 = o[nt][0] * inv0, x1 = o[nt][1] * inv0;
        const float x2 = o[nt][2] * inv1, x3 = o[nt][3] * inv1;
        const __half h0 = __float2half_rn(x0), h1 = __float2half_rn(x1);
        const __half h2 = __float2half_rn(x2), h3 = __float2half_rn(x3);
        *(uint32_t*)(Oh + base0 + nt * 8) = pkh(h0, h1);
        *(uint32_t*)(Ol + base0 + nt * 8) =
            pkh(__float2half_rn(x0 - __half2float(h0)),
                __float2half_rn(x1 - __half2float(h1)));
        *(uint32_t*)(Oh + base1 + nt * 8) = pkh(h2, h3);
        *(uint32_t*)(Ol + base1 + nt * 8) =
            pkh(__float2half_rn(x2 - __half2float(h2)),
                __float2half_rn(x3 - __half2float(h3)));
    }
}

// ---------------------------------------------------------------------------
// Launch
// ---------------------------------------------------------------------------
extern "C" void kernel_launch(void* const* d_in, const int* in_sizes, int n_in,
                              void* d_out, int out_size)
{
    const float* x   = (const float*)d_in[0];
    const float* Wq  = (const float*)d_in[1];
    const float* bq  = (const float*)d_in[2];
    const float* Wk  = (const float*)d_in[3];
    const float* bk  = (const float*)d_in[4];
    const float* Wv  = (const float*)d_in[5];
    const float* bv  = (const float*)d_in[6];
    const float* Wo  = (const float*)d_in[7];
    const float* bo  = (const float*)d_in[8];
    const float* qng = (const float*)d_in[9];
    const float* qnb = (const float*)d_in[10];
    const float* kng = (const float*)d_in[11];
    const float* knb = (const float*)d_in[12];
    float* out = (float*)d_out;

    float *qp, *kp, *vp;
    __half *xh, *xl, *wq16, *wk16, *wv16, *wo16, *aoh, *aol;
    __half *q16, *ql16, *kh16, *kl16, *vh16, *vl16;
    cudaGetSymbolAddress((void**)&qp, g_q);
    cudaGetSymbolAddress((void**)&kp, g_k);
    cudaGetSymbolAddress((void**)&vp, g_v);
    cudaGetSymbolAddress((void**)&xh, g_xh);     cudaGetSymbolAddress((void**)&xl, g_xl);
    cudaGetSymbolAddress((void**)&wq16, g_wq16);
    cudaGetSymbolAddress((void**)&wk16, g_wk16);
    cudaGetSymbolAddress((void**)&wv16, g_wv16);
    cudaGetSymbolAddress((void**)&wo16, g_wo16);
    cudaGetSymbolAddress((void**)&aoh, g_aoh);   cudaGetSymbolAddress((void**)&aol, g_aol);
    cudaGetSymbolAddress((void**)&q16, g_q16);   cudaGetSymbolAddress((void**)&ql16, g_ql16);
    cudaGetSymbolAddress((void**)&kh16, g_kh16); cudaGetSymbolAddress((void**)&kl16, g_kl16);
    cudaGetSymbolAddress((void**)&vh16, g_vh16); cudaGetSymbolAddress((void**)&vl16, g_vl16);

    cudaFuncSetAttribute(gemm_qkv, cudaFuncAttributeMaxDynamicSharedMemorySize,
                         GEMM_SMEM);
    cudaFuncSetAttribute(gemm_f16_pipe, cudaFuncAttributeMaxDynamicSharedMemorySize,
                         GEMM_SMEM);
    cudaFuncSetAttribute(flash_mma, cudaFuncAttributeMaxDynamicSharedMemorySize,
                         FSMEM);

    const int n4_x  = S_ * HID_ / 4;
    const int n4_wq = NH_ * HD_ * HID_ / 4;
    const int n4_wk = NKV_ * HD_ * HID_ / 4;
    const int n4_wo = HID_ * HID_ / 4;
    const int n4_v  = S_ * NKV_ * HD_ / 4;
    split_kernel<<<n4_x / 256, 256>>>(x, xh, xl, n4_x);
    cast_kernel<<<n4_wq / 256, 256>>>(Wq, wq16, n4_wq);
    cast_kernel<<<n4_wk / 256, 256>>>(Wk, wk16, n4_wk);
    cast_kernel<<<n4_wk / 256, 256>>>(Wv, wv16, n4_wk);
    cast_kernel<<<n4_wo / 256, 256>>>(Wo, wo16, n4_wo);

    // fused QKV projection (fp16 2-term)
    gemm_qkv<<<dim3(48, S_ / GBM), 256, GEMM_SMEM>>>(
        xh, xl, wq16, wk16, wv16, bq, bk, bv, qp, kp, vp);

    // LayerNorm + RoPE -> fp16 (Q plain + unused lo; K split)
    ln_rope16<<<S_, HD_>>>(qp, q16, ql16, qng, qnb, NH_);
    ln_rope16<<<S_, HD_>>>(kp, kh16, kl16, kng, knb, NKV_);
    // V -> fp16 split
    split_kernel<<<n4_v / 256, 256>>>(vp, vh16, vl16, n4_v);

    // flash attention on tensor cores -> fp16 hi/lo output
    flash_mma<<<dim3(S_ / FBR, NH_), 256, FSMEM>>>(
        q16, kh16, kl16, vh16, vl16, aoh, aol);

    // output projection (fp16 2-term)
    gemm_f16_pipe<<<dim3(HID_ / GBN, S_ / GBM), 256, GEMM_SMEM>>>(
        S_, HID_, HID_, aoh, aol, wo16, bo, out);
}

// round 13
// speedup vs baseline: 4.2412x; 1.0719x over previous
#include <cuda_runtime.h>
#include <cuda_fp16.h>
#include <math.h>
#include <cstdint>

// Problem constants
#define S_    2048
#define HID_  4096
#define NH_   32
#define NKV_  8
#define HD_   128
#define EPS_  1e-5f
#define SCALE_ 0.088388347648318447f
#define SC2_  (SCALE_ * 1.4426950408889634f)
#define LOG2_THETA 18.931568569324174f

// ---------------------------------------------------------------------------
// Scratch (device globals; no allocation allowed)
// ---------------------------------------------------------------------------
__device__ float g_q[S_ * NH_ * HD_];
__device__ float g_k[S_ * NKV_ * HD_];
__device__ float g_v[S_ * NKV_ * HD_];
__device__ __half g_xh[S_ * HID_],  g_xl[S_ * HID_];
__device__ __half g_wq16[NH_ * HD_ * HID_];
__device__ __half g_wk16[NKV_ * HD_ * HID_];
__device__ __half g_wv16[NKV_ * HD_ * HID_];
__device__ __half g_wo16[HID_ * HID_];
__device__ __half g_aoh[S_ * HID_], g_aol[S_ * HID_];
// fp16 attention operands (Q, K plain; V split)
__device__ __half g_q16[S_ * NH_ * HD_];
__device__ __half g_k16[S_ * NKV_ * HD_];
__device__ __half g_vh16[S_ * NKV_ * HD_], g_vl16[S_ * NKV_ * HD_];

// ---------------------------------------------------------------------------
// Helpers
// ---------------------------------------------------------------------------
__device__ __forceinline__ uint32_t smem_u32(const void* p) {
    uint32_t a;
    asm("{ .reg .u64 t; cvta.to.shared.u64 t, %1; cvt.u32.u64 %0, t; }"
        : "=r"(a) : "l"(p));
    return a;
}

__device__ __forceinline__ void ldsm4(uint32_t* r, uint32_t addr) {
    asm volatile("ldmatrix.sync.aligned.m8n8.x4.shared.b16 {%0,%1,%2,%3}, [%4];"
                 : "=r"(r[0]), "=r"(r[1]), "=r"(r[2]), "=r"(r[3]) : "r"(addr));
}

__device__ __forceinline__ void ldsm4t(uint32_t* r, uint32_t addr) {
    asm volatile("ldmatrix.sync.aligned.m8n8.x4.trans.shared.b16 {%0,%1,%2,%3}, [%4];"
                 : "=r"(r[0]), "=r"(r[1]), "=r"(r[2]), "=r"(r[3]) : "r"(addr));
}

__device__ __forceinline__ void mma_f16(float* d, const uint32_t* a, const uint32_t* b) {
    asm volatile(
        "mma.sync.aligned.m16n8k16.row.col.f32.f16.f16.f32 "
        "{%0,%1,%2,%3}, {%4,%5,%6,%7}, {%8,%9}, {%0,%1,%2,%3};"
        : "+f"(d[0]), "+f"(d[1]), "+f"(d[2]), "+f"(d[3])
        : "r"(a[0]), "r"(a[1]), "r"(a[2]), "r"(a[3]), "r"(b[0]), "r"(b[1]));
}

__device__ __forceinline__ void cpa16(uint32_t dst, const void* src) {
    asm volatile("cp.async.cg.shared.global [%0], [%1], 16;" :: "r"(dst), "l"(src));
}

__device__ __forceinline__ uint32_t pkh(__half a, __half b) {
    __half2 t = __halves2half2(a, b);
    return *reinterpret_cast<uint32_t*>(&t);
}

__device__ __forceinline__ void split4_h(float4 v, uint2& hi, uint2& lo) {
    __half h0 = __float2half_rn(v.x);
    __half h1 = __float2half_rn(v.y);
    __half h2 = __float2half_rn(v.z);
    __half h3 = __float2half_rn(v.w);
    __half l0 = __float2half_rn(v.x - __half2float(h0));
    __half l1 = __float2half_rn(v.y - __half2float(h1));
    __half l2 = __float2half_rn(v.z - __half2float(h2));
    __half l3 = __float2half_rn(v.w - __half2float(h3));
    hi.x = pkh(h0, h1); hi.y = pkh(h2, h3);
    lo.x = pkh(l0, l1); lo.y = pkh(l2, l3);
}

__device__ __forceinline__ uint2 cast4_h(float4 v) {
    uint2 r;
    r.x = pkh(__float2half_rn(v.x), __float2half_rn(v.y));
    r.y = pkh(__float2half_rn(v.z), __float2half_rn(v.w));
    return r;
}

// ---------------------------------------------------------------------------
// fp32 -> fp16 hi/lo split, and plain cast
// ---------------------------------------------------------------------------
__global__ __launch_bounds__(256)
void split_kernel(const float* __restrict__ in,
                  __half* __restrict__ hi,
                  __half* __restrict__ lo, int n4)
{
    const int idx = blockIdx.x * 256 + threadIdx.x;
    if (idx >= n4) return;
    float4 v = ((const float4*)in)[idx];
    uint2 h, l;
    split4_h(v, h, l);
    ((uint2*)hi)[idx] = h;
    ((uint2*)lo)[idx] = l;
}

__global__ __launch_bounds__(256)
void cast_kernel(const float* __restrict__ in, __half* __restrict__ out, int n4)
{
    const int idx = blockIdx.x * 256 + threadIdx.x;
    if (idx >= n4) return;
    ((uint2*)out)[idx] = cast4_h(((const float4*)in)[idx]);
}

// ---------------------------------------------------------------------------
// fp16 2-term GEMM, 4-stage cp.async pipeline (unchanged from R12 — passing)
// ---------------------------------------------------------------------------
#define GBM 128
#define GBN 128
#define GBK 32
#define OFF_AL 8192
#define OFF_BH 16384
#define BUF_B  24576
#define NSTAGE 4
#define GEMM_SMEM (NSTAGE * BUF_B)

__device__ __forceinline__ void issue_stage(
    uint32_t sdst,
    const __half* __restrict__ Ah, const __half* __restrict__ Al,
    const __half* __restrict__ Bh,
    int K, int k0, int tid)
{
#pragma unroll
    for (int it = 0; it < 6; it++) {
        const int tile = it >> 1;
        const int c = (it & 1) * 256 + tid;
        const int row = c >> 2;
        const int col = c & 3;
        const uint32_t dst = sdst + tile * 8192 + row * 64
                           + (uint32_t)((col ^ (row & 3)) << 4);
        const __half* src;
        if (tile == 0)      src = Ah + (size_t)row * K + k0 + col * 8;
        else if (tile == 1) src = Al + (size_t)row * K + k0 + col * 8;
        else                src = Bh + (size_t)row * K + k0 + col * 8;
        cpa16(dst, src);
    }
}

__device__ __forceinline__ void gemm_body(
    const __half* __restrict__ Ahb, const __half* __restrict__ Alb,
    const __half* __restrict__ Bhb,
    const float* __restrict__ bias, float* __restrict__ C,
    int N, int K, int bm, int bn, char* smem)
{
    const uint32_t sbase = smem_u32(smem);
    const int tid = threadIdx.x;
    const int wid = tid >> 5;
    const int lane = tid & 31;
    const int warp_m = wid >> 2;
    const int warp_n = wid & 3;

    const int l7 = lane & 7;
    const int l3 = lane & 3;
    const int amat = lane >> 3;
    const uint32_t a_row64 = (uint32_t)(warp_m * 64 + ((amat & 1) << 3) + l7) * 64;
    const int a_kh = amat >> 1;
    const int b_kh = (lane >> 3) & 1;
    const uint32_t b_row64 = (uint32_t)(warp_n * 32 + ((lane >> 4) << 3) + l7) * 64;

    float acc[4][4][4];
#pragma unroll
    for (int i = 0; i < 4; i++)
#pragma unroll
        for (int j = 0; j < 4; j++)
#pragma unroll
            for (int c = 0; c < 4; c++) acc[i][j][c] = 0.f;

    const int NB = K / GBK;

    issue_stage(sbase, Ahb, Alb, Bhb, K, 0, tid);
    asm volatile("cp.async.commit_group;");
    issue_stage(sbase + BUF_B, Ahb, Alb, Bhb, K, GBK, tid);
    asm volatile("cp.async.commit_group;");
    issue_stage(sbase + 2 * BUF_B, Ahb, Alb, Bhb, K, 2 * GBK, tid);
    asm volatile("cp.async.commit_group;");

    for (int kb = 0; kb < NB; kb++) {
        asm volatile("cp.async.wait_group 2;");
        __syncthreads();

        const int nk = kb + 3;
        if (nk < NB)
            issue_stage(sbase + (uint32_t)(nk % NSTAGE) * BUF_B,
                        Ahb, Alb, Bhb, K, nk * GBK, tid);
        asm volatile("cp.async.commit_group;");

        const uint32_t bufc = sbase + (uint32_t)(kb % NSTAGE) * BUF_B;

#pragma unroll
        for (int ks = 0; ks < 2; ks++) {
            const uint32_t a_swoff = (uint32_t)(((ks * 2 + a_kh) ^ l3) << 4);
            const uint32_t b_swoff = (uint32_t)(((ks * 2 + b_kh) ^ l3) << 4);

            uint32_t ah[4][4];
#pragma unroll
            for (int mt = 0; mt < 4; mt++)
                ldsm4(ah[mt], bufc + a_row64 + (uint32_t)mt * 1024 + a_swoff);

            uint32_t bh[2][4];
#pragma unroll
            for (int p = 0; p < 2; p++)
                ldsm4(bh[p], bufc + OFF_BH + b_row64 + (uint32_t)p * 1024 + b_swoff);

#pragma unroll
            for (int mt = 0; mt < 4; mt++)
#pragma unroll
                for (int nt = 0; nt < 4; nt++)
                    mma_f16(acc[mt][nt], ah[mt], &bh[nt >> 1][(nt & 1) * 2]);

            uint32_t al[4][4];
#pragma unroll
            for (int mt = 0; mt < 4; mt++)
                ldsm4(al[mt], bufc + OFF_AL + a_row64 + (uint32_t)mt * 1024 + a_swoff);
#pragma unroll
            for (int mt = 0; mt < 4; mt++)
#pragma unroll
                for (int nt = 0; nt < 4; nt++)
                    mma_f16(acc[mt][nt], al[mt], &bh[nt >> 1][(nt & 1) * 2]);
        }
    }

    const int g = lane >> 2;
    const int t = lane & 3;
#pragma unroll
    for (int nt = 0; nt < 4; nt++) {
        const int col = bn + warp_n * 32 + nt * 8 + 2 * t;
        const float b0 = bias[col];
        const float b1 = bias[col + 1];
#pragma unroll
        for (int mt = 0; mt < 4; mt++) {
            const int row = bm + warp_m * 64 + mt * 16 + g;
            float2 v0, v1;
            v0.x = acc[mt][nt][0] + b0;
            v0.y = acc[mt][nt][1] + b1;
            v1.x = acc[mt][nt][2] + b0;
            v1.y = acc[mt][nt][3] + b1;
            *(float2*)(C + (size_t)row * N + col) = v0;
            *(float2*)(C + (size_t)(row + 8) * N + col) = v1;
        }
    }
}

__global__ __launch_bounds__(256, 2)
void gemm_qkv(const __half* __restrict__ xh, const __half* __restrict__ xl,
              const __half* __restrict__ wq, const __half* __restrict__ wk,
              const __half* __restrict__ wv,
              const float* __restrict__ bq, const float* __restrict__ bk,
              const float* __restrict__ bv,
              float* __restrict__ q, float* __restrict__ k, float* __restrict__ v)
{
    extern __shared__ __align__(1024) char smem[];
    const int bx = blockIdx.x;
    const int bm = blockIdx.y * GBM;

    const __half* Bh;
    const float* bias;
    float* C;
    int N, bn;
    if (bx < 32) {
        Bh = wq; bias = bq; C = q; N = NH_ * HD_; bn = bx * GBN;
    } else if (bx < 40) {
        Bh = wk; bias = bk; C = k; N = NKV_ * HD_; bn = (bx - 32) * GBN;
    } else {
        Bh = wv; bias = bv; C = v; N = NKV_ * HD_; bn = (bx - 40) * GBN;
    }

    gemm_body(xh + (size_t)bm * HID_, xl + (size_t)bm * HID_,
              Bh + (size_t)bn * HID_, bias, C, N, HID_, bm, bn, smem);
}

__global__ __launch_bounds__(256, 2)
void gemm_f16_pipe(int M, int N, int K,
                   const __half* __restrict__ Ah,
                   const __half* __restrict__ Al,
                   const __half* __restrict__ Bh,
                   const float* __restrict__ bias,
                   float* __restrict__ C)
{
    extern __shared__ __align__(1024) char smem[];
    const int bm = blockIdx.y * GBM;
    const int bn = blockIdx.x * GBN;
    gemm_body(Ah + (size_t)bm * K, Al + (size_t)bm * K,
              Bh + (size_t)bn * K, bias, C, N, K, bm, bn, smem);
}

// ---------------------------------------------------------------------------
// Fused per-head LayerNorm + RoPE; reads fp32, writes plain fp16
// ---------------------------------------------------------------------------
__global__ __launch_bounds__(128)
void ln_rope_h(const float* __restrict__ in,
               __half* __restrict__ oh,
               const float* __restrict__ gw,
               const float* __restrict__ bw,
               int H)
{
    const int s = blockIdx.x;
    const int d = threadIdx.x;
    __shared__ float red[8];
    __shared__ float xs[HD_];

    const int dd = d & 63;
    const float inv = exp2f(-(float)dd * (LOG2_THETA / 64.0f));
    const float th = (float)s * inv;
    float sn, cs;
    sincosf(th, &sn, &cs);

    const float gv = gw[d];
    const float bv = bw[d];
    const int lane = d & 31;
    const int w = d >> 5;

    for (int h = 0; h < H; h++) {
        const float* x = in + ((size_t)s * H + h) * HD_;
        const float v = x[d];
        float s1 = v, s2 = v * v;
#pragma unroll
        for (int off = 16; off > 0; off >>= 1) {
            s1 += __shfl_xor_sync(0xffffffffu, s1, off);
            s2 += __shfl_xor_sync(0xffffffffu, s2, off);
        }
        if (lane == 0) { red[w] = s1; red[4 + w] = s2; }
        __syncthreads();
        const float sum = red[0] + red[1] + red[2] + red[3];
        const float sq  = red[4] + red[5] + red[6] + red[7];
        const float mu  = sum * (1.0f / HD_);
        const float var = sq * (1.0f / HD_) - mu * mu;
        const float r   = rsqrtf(var + EPS_);
        const float xn  = (v - mu) * r * gv + bv;
        xs[d] = xn;
        __syncthreads();
        const float other = (d < 64) ? -xs[d + 64] : xs[d - 64];
        const float res = xn * cs + other * sn;
        oh[((size_t)s * H + h) * HD_ + d] = __float2half_rn(res);
        __syncthreads();
    }
}

// ---------------------------------------------------------------------------
// Flash attention on mma.sync fp16.
// BR=128 (8 warps x m16), BC=64, 256 threads.
// Q plain; K plain (QK 1 term); P plain, V split hi/lo (PV 2 terms).
// SMEM: Q 32KB + 2 KV buffers of [K|Vh|Vl] 16KB tiles = 128KB total.
// ---------------------------------------------------------------------------
#define FBR 128
#define FBC 64
#define FQ_CH 8192
#define FKV_CH 4096
#define FKV_TILE 16384
#define FBUF 49152
#define FSMEM (32768 + 2 * FBUF)

__device__ __forceinline__ void kv_stage(
    uint32_t dstbase,
    const __half* __restrict__ Kp,
    const __half* __restrict__ Vh, const __half* __restrict__ Vl,
    int kvh, int k0, int tid)
{
#pragma unroll
    for (int it = 0; it < 12; it++) {
        const int idx = it * 256 + tid;
        const int tile = idx >> 10;             // 0..2 = K, Vh, Vl
        const int sub = idx & 1023;
        const int row = sub >> 4;               // 0..63
        const int u8 = sub & 15;
        const __half* base = (tile == 0) ? Kp : (tile == 1) ? Vh : Vl;
        const __half* src = base + ((size_t)(k0 + row) * NKV_ + kvh) * HD_ + u8 * 8;
        const uint32_t dst = dstbase + tile * FKV_TILE + (u8 >> 2) * FKV_CH
                           + row * 64 + (uint32_t)(((u8 & 3) ^ (row & 3)) << 4);
        cpa16(dst, src);
    }
}

__global__ __launch_bounds__(256, 1)
void flash_mma(const __half* __restrict__ Q16,
               const __half* __restrict__ K16,
               const __half* __restrict__ Vh16, const __half* __restrict__ Vl16,
               __half* __restrict__ Oh, __half* __restrict__ Ol)
{
    extern __shared__ __align__(1024) char smem[];
    const uint32_t sbase = smem_u32(smem);
    const int qb = (int)gridDim.x - 1 - (int)blockIdx.x;   // big tiles first
    const int h = blockIdx.y;
    const int kvh = h >> 2;
    const int q0 = qb * FBR;
    const int tid = threadIdx.x;
    const int w = tid >> 5;
    const int lane = tid & 31;

    // prologue: Q + KV block 0
#pragma unroll
    for (int it = 0; it < 8; it++) {
        const int idx = it * 256 + tid;
        const int row = idx >> 4;
        const int u8 = idx & 15;
        const __half* src = Q16 + ((size_t)(q0 + row) * NH_ + h) * HD_ + u8 * 8;
        const uint32_t dst = sbase + (u8 >> 2) * FQ_CH + row * 64
                           + (uint32_t)(((u8 & 3) ^ (row & 3)) << 4);
        cpa16(dst, src);
    }
    kv_stage(sbase + 32768, K16, Vh16, Vl16, kvh, 0, tid);
    asm volatile("cp.async.commit_group;");

    float o[16][4];
#pragma unroll
    for (int i = 0; i < 16; i++)
#pragma unroll
        for (int c = 0; c < 4; c++) o[i][c] = 0.f;
    float m0 = -1e30f, m1 = -1e30f, l0 = 0.f, l1 = 0.f;

    const int l7 = lane & 7;
    const int qrow = w * 16 + ((lane >> 3) & 1) * 8 + l7;
    const int qm2 = lane >> 4;
    const int krow_base = ((lane >> 4) << 3) + l7;
    const int kh_sel = (lane >> 3) & 1;
    const int vrow_base = ((lane >> 3) & 1) * 8 + l7;
    const int vm2 = lane >> 4;

    const int nb = 2 * qb + 2;
    for (int kb = 0; kb < nb; kb++) {
        if (kb + 1 < nb)
            kv_stage(sbase + 32768 + ((kb + 1) & 1) * FBUF,
                     K16, Vh16, Vl16, kvh, (kb + 1) * FBC, tid);
        asm volatile("cp.async.commit_group;");
        asm volatile("cp.async.wait_group 1;");
        __syncthreads();

        const uint32_t B = sbase + 32768 + (uint32_t)(kb & 1) * FBUF;

        // ---- QK: sc = Q K^T ----
        float sc[8][4];
#pragma unroll
        for (int i = 0; i < 8; i++)
#pragma unroll
            for (int c = 0; c < 4; c++) sc[i][c] = 0.f;

#pragma unroll
        for (int kd = 0; kd < 8; kd++) {
            uint32_t qa[4];
            {
                const int u8 = kd * 2 + qm2;
                ldsm4(qa, sbase + (u8 >> 2) * FQ_CH + qrow * 64
                          + (uint32_t)(((u8 & 3) ^ (qrow & 3)) << 4));
            }
            const int u8k = kd * 2 + kh_sel;
#pragma unroll
            for (int j = 0; j < 4; j++) {
                const int krow = j * 16 + krow_base;
                const uint32_t koff = (u8k >> 2) * FKV_CH + krow * 64
                                    + (uint32_t)(((u8k & 3) ^ (krow & 3)) << 4);
                uint32_t kb4[4];
                ldsm4(kb4, B + koff);
                mma_f16(sc[2 * j],     qa, &kb4[0]);
                mma_f16(sc[2 * j + 1], qa, &kb4[2]);
            }
        }

        // ---- softmax (exp2 domain) ----
        const int row0 = q0 + w * 16 + (lane >> 2);
        const int col_base = kb * FBC + (lane & 3) * 2;
        const bool maybe_mask = (kb * FBC + FBC - 1) > (q0 + w * 16);
        float mx0 = -1e30f, mx1 = -1e30f;
#pragma unroll
        for (int nt = 0; nt < 8; nt++) {
            float v0 = sc[nt][0] * SC2_;
            float v1 = sc[nt][1] * SC2_;
            float v2 = sc[nt][2] * SC2_;
            float v3 = sc[nt][3] * SC2_;
            if (maybe_mask) {
                const int c0 = col_base + nt * 8;
                if (c0 > row0)         v0 = -1e30f;
                if (c0 + 1 > row0)     v1 = -1e30f;
                if (c0 > row0 + 8)     v2 = -1e30f;
                if (c0 + 1 > row0 + 8) v3 = -1e30f;
            }
            sc[nt][0] = v0; sc[nt][1] = v1; sc[nt][2] = v2; sc[nt][3] = v3;
            mx0 = fmaxf(mx0, fmaxf(v0, v1));
            mx1 = fmaxf(mx1, fmaxf(v2, v3));
        }
        mx0 = fmaxf(mx0, __shfl_xor_sync(0xffffffffu, mx0, 1));
        mx0 = fmaxf(mx0, __shfl_xor_sync(0xffffffffu, mx0, 2));
        mx1 = fmaxf(mx1, __shfl_xor_sync(0xffffffffu, mx1, 1));
        mx1 = fmaxf(mx1, __shfl_xor_sync(0xffffffffu, mx1, 2));
        const float mn0 = fmaxf(m0, mx0);
        const float mn1 = fmaxf(m1, mx1);
        const float al0 = exp2f(m0 - mn0);
        const float al1 = exp2f(m1 - mn1);
        m0 = mn0; m1 = mn1;

        uint32_t ph[8][2];
        float rs0 = 0.f, rs1 = 0.f;
#pragma unroll
        for (int nt = 0; nt < 8; nt++) {
            const float p0 = exp2f(sc[nt][0] - mn0);
            const float p1 = exp2f(sc[nt][1] - mn0);
            const float p2 = exp2f(sc[nt][2] - mn1);
            const float p3 = exp2f(sc[nt][3] - mn1);
            rs0 += p0 + p1; rs1 += p2 + p3;
            ph[nt][0] = pkh(__float2half_rn(p0), __float2half_rn(p1));
            ph[nt][1] = pkh(__float2half_rn(p2), __float2half_rn(p3));
        }
        rs0 += __shfl_xor_sync(0xffffffffu, rs0, 1);
        rs0 += __shfl_xor_sync(0xffffffffu, rs0, 2);
        rs1 += __shfl_xor_sync(0xffffffffu, rs1, 1);
        rs1 += __shfl_xor_sync(0xffffffffu, rs1, 2);
        l0 = l0 * al0 + rs0;
        l1 = l1 * al1 + rs1;
#pragma unroll
        for (int j = 0; j < 16; j++) {
            o[j][0] *= al0; o[j][1] *= al0;
            o[j][2] *= al1; o[j][3] *= al1;
        }

        // ---- PV: o += P Vh + P Vl ----
#pragma unroll
        for (int ks = 0; ks < 4; ks++) {
            uint32_t aph[4] = { ph[2 * ks][0], ph[2 * ks][1],
                                ph[2 * ks + 1][0], ph[2 * ks + 1][1] };
            const int vrow = ks * 16 + vrow_base;
#pragma unroll
            for (int j = 0; j < 8; j++) {
                const int u8 = 2 * j + vm2;
                const uint32_t voff = (u8 >> 2) * FKV_CH + vrow * 64
                                    + (uint32_t)(((u8 & 3) ^ (vrow & 3)) << 4);
                uint32_t vh4[4], vl4[4];
                ldsm4t(vh4, B + FKV_TILE + voff);
                ldsm4t(vl4, B + 2 * FKV_TILE + voff);
                mma_f16(o[2 * j],     aph, &vh4[0]);
                mma_f16(o[2 * j + 1], aph, &vh4[2]);
                mma_f16(o[2 * j],     aph, &vl4[0]);
                mma_f16(o[2 * j + 1], aph, &vl4[2]);
            }
        }
        __syncthreads();
    }

    // ---- epilogue: O /= l, split fp16 hi/lo, store ----
    const float inv0 = 1.f / l0;
    const float inv1 = 1.f / l1;
    const int r0 = q0 + w * 16 + (lane >> 2);
    const size_t base0 = ((size_t)r0 * NH_ + h) * HD_ + (lane & 3) * 2;
    const size_t base1 = ((size_t)(r0 + 8) * NH_ + h) * HD_ + (lane & 3) * 2;
#pragma unroll
    for (int nt = 0; nt < 16; nt++) {
        const float x0 = o[nt][0] * inv0, x1 = o[nt][1] * inv0;
        const float x2 = o[nt][2] * inv1, x3 = o[nt][3] * inv1;
        const __half h0 = __float2half_rn(x0), h1 = __float2half_rn(x1);
        const __half h2 = __float2half_rn(x2), h3 = __float2half_rn(x3);
        *(uint32_t*)(Oh + base0 + nt * 8) = pkh(h0, h1);
        *(uint32_t*)(Ol + base0 + nt * 8) =
            pkh(__float2half_rn(x0 - __half2float(h0)),
                __float2half_rn(x1 - __half2float(h1)));
        *(uint32_t*)(Oh + base1 + nt * 8) = pkh(h2, h3);
        *(uint32_t*)(Ol + base1 + nt * 8) =
            pkh(__float2half_rn(x2 - __half2float(h2)),
                __float2half_rn(x3 - __half2float(h3)));
    }
}

// ---------------------------------------------------------------------------
// Launch
// ---------------------------------------------------------------------------
extern "C" void kernel_launch(void* const* d_in, const int* in_sizes, int n_in,
                              void* d_out, int out_size)
{
    const float* x   = (const float*)d_in[0];
    const float* Wq  = (const float*)d_in[1];
    const float* bq  = (const float*)d_in[2];
    const float* Wk  = (const float*)d_in[3];
    const float* bk  = (const float*)d_in[4];
    const float* Wv  = (const float*)d_in[5];
    const float* bv  = (const float*)d_in[6];
    const float* Wo  = (const float*)d_in[7];
    const float* bo  = (const float*)d_in[8];
    const float* qng = (const float*)d_in[9];
    const float* qnb = (const float*)d_in[10];
    const float* kng = (const float*)d_in[11];
    const float* knb = (const float*)d_in[12];
    float* out = (float*)d_out;

    float *qp, *kp, *vp;
    __half *xh, *xl, *wq16, *wk16, *wv16, *wo16, *aoh, *aol;
    __half *q16, *k16, *vh16, *vl16;
    cudaGetSymbolAddress((void**)&qp, g_q);
    cudaGetSymbolAddress((void**)&kp, g_k);
    cudaGetSymbolAddress((void**)&vp, g_v);
    cudaGetSymbolAddress((void**)&xh, g_xh);     cudaGetSymbolAddress((void**)&xl, g_xl);
    cudaGetSymbolAddress((void**)&wq16, g_wq16);
    cudaGetSymbolAddress((void**)&wk16, g_wk16);
    cudaGetSymbolAddress((void**)&wv16, g_wv16);
    cudaGetSymbolAddress((void**)&wo16, g_wo16);
    cudaGetSymbolAddress((void**)&aoh, g_aoh);   cudaGetSymbolAddress((void**)&aol, g_aol);
    cudaGetSymbolAddress((void**)&q16, g_q16);
    cudaGetSymbolAddress((void**)&k16, g_k16);
    cudaGetSymbolAddress((void**)&vh16, g_vh16); cudaGetSymbolAddress((void**)&vl16, g_vl16);

    cudaFuncSetAttribute(gemm_qkv, cudaFuncAttributeMaxDynamicSharedMemorySize,
                         GEMM_SMEM);
    cudaFuncSetAttribute(gemm_f16_pipe, cudaFuncAttributeMaxDynamicSharedMemorySize,
                         GEMM_SMEM);
    cudaFuncSetAttribute(flash_mma, cudaFuncAttributeMaxDynamicSharedMemorySize,
                         FSMEM);

    const int n4_x  = S_ * HID_ / 4;
    const int n4_wq = NH_ * HD_ * HID_ / 4;
    const int n4_wk = NKV_ * HD_ * HID_ / 4;
    const int n4_wo = HID_ * HID_ / 4;
    const int n4_v  = S_ * NKV_ * HD_ / 4;
    split_kernel<<<n4_x / 256, 256>>>(x, xh, xl, n4_x);
    cast_kernel<<<n4_wq / 256, 256>>>(Wq, wq16, n4_wq);
    cast_kernel<<<n4_wk / 256, 256>>>(Wk, wk16, n4_wk);
    cast_kernel<<<n4_wk / 256, 256>>>(Wv, wv16, n4_wk);
    cast_kernel<<<n4_wo / 256, 256>>>(Wo, wo16, n4_wo);

    // fused QKV projection (fp16 2-term)
    gemm_qkv<<<dim3(48, S_ / GBM), 256, GEMM_SMEM>>>(
        xh, xl, wq16, wk16, wv16, bq, bk, bv, qp, kp, vp);

    // LayerNorm + RoPE -> plain fp16
    ln_rope_h<<<S_, HD_>>>(qp, q16, qng, qnb, NH_);
    ln_rope_h<<<S_, HD_>>>(kp, k16, kng, knb, NKV_);
    // V -> fp16 split
    split_kernel<<<n4_v / 256, 256>>>(vp, vh16, vl16, n4_v);

    // flash attention on tensor cores -> fp16 hi/lo output
    flash_mma<<<dim3(S_ / FBR, NH_), 256, FSMEM>>>(
        q16, k16, vh16, vl16, aoh, aol);

    // output projection (fp16 2-term)
    gemm_f16_pipe<<<dim3(HID_ / GBN, S_ / GBM), 256, GEMM_SMEM>>>(
        S_, HID_, HID_, aoh, aol, wo16, bo, out);
}

// round 14
// speedup vs baseline: 5.8006x; 1.3677x over previous
#include <cuda_runtime.h>
#include <cuda_fp16.h>
#include <math.h>
#include <cstdint>

// Problem constants
#define S_    2048
#define HID_  4096
#define NH_   32
#define NKV_  8
#define HD_   128
#define EPS_  1e-5f
#define SCALE_ 0.088388347648318447f
#define SC2_  (SCALE_ * 1.4426950408889634f)
#define LOG2_THETA 18.931568569324174f

// ---------------------------------------------------------------------------
// Scratch (device globals; no allocation allowed)
// ---------------------------------------------------------------------------
__device__ float g_q[S_ * NH_ * HD_];
__device__ float g_k[S_ * NKV_ * HD_];
__device__ float g_v[S_ * NKV_ * HD_];
__device__ __half g_x16[S_ * HID_];
__device__ __half g_wq16[NH_ * HD_ * HID_];
__device__ __half g_wk16[NKV_ * HD_ * HID_];
__device__ __half g_wv16[NKV_ * HD_ * HID_];
__device__ __half g_wo16[HID_ * HID_];
__device__ __half g_ao16[S_ * HID_];
// fp16 attention operands (Q, K plain; V split)
__device__ __half g_q16[S_ * NH_ * HD_];
__device__ __half g_k16[S_ * NKV_ * HD_];
__device__ __half g_vh16[S_ * NKV_ * HD_], g_vl16[S_ * NKV_ * HD_];

// ---------------------------------------------------------------------------
// Helpers
// ---------------------------------------------------------------------------
__device__ __forceinline__ uint32_t smem_u32(const void* p) {
    uint32_t a;
    asm("{ .reg .u64 t; cvta.to.shared.u64 t, %1; cvt.u32.u64 %0, t; }"
        : "=r"(a) : "l"(p));
    return a;
}

__device__ __forceinline__ void ldsm4(uint32_t* r, uint32_t addr) {
    asm volatile("ldmatrix.sync.aligned.m8n8.x4.shared.b16 {%0,%1,%2,%3}, [%4];"
                 : "=r"(r[0]), "=r"(r[1]), "=r"(r[2]), "=r"(r[3]) : "r"(addr));
}

__device__ __forceinline__ void ldsm4t(uint32_t* r, uint32_t addr) {
    asm volatile("ldmatrix.sync.aligned.m8n8.x4.trans.shared.b16 {%0,%1,%2,%3}, [%4];"
                 : "=r"(r[0]), "=r"(r[1]), "=r"(r[2]), "=r"(r[3]) : "r"(addr));
}

__device__ __forceinline__ void mma_f16(float* d, const uint32_t* a, const uint32_t* b) {
    asm volatile(
        "mma.sync.aligned.m16n8k16.row.col.f32.f16.f16.f32 "
        "{%0,%1,%2,%3}, {%4,%5,%6,%7}, {%8,%9}, {%0,%1,%2,%3};"
        : "+f"(d[0]), "+f"(d[1]), "+f"(d[2]), "+f"(d[3])
        : "r"(a[0]), "r"(a[1]), "r"(a[2]), "r"(a[3]), "r"(b[0]), "r"(b[1]));
}

__device__ __forceinline__ void cpa16(uint32_t dst, const void* src) {
    asm volatile("cp.async.cg.shared.global [%0], [%1], 16;" :: "r"(dst), "l"(src));
}

__device__ __forceinline__ uint32_t pkh(__half a, __half b) {
    __half2 t = __halves2half2(a, b);
    return *reinterpret_cast<uint32_t*>(&t);
}

__device__ __forceinline__ void split4_h(float4 v, uint2& hi, uint2& lo) {
    __half h0 = __float2half_rn(v.x);
    __half h1 = __float2half_rn(v.y);
    __half h2 = __float2half_rn(v.z);
    __half h3 = __float2half_rn(v.w);
    __half l0 = __float2half_rn(v.x - __half2float(h0));
    __half l1 = __float2half_rn(v.y - __half2float(h1));
    __half l2 = __float2half_rn(v.z - __half2float(h2));
    __half l3 = __float2half_rn(v.w - __half2float(h3));
    hi.x = pkh(h0, h1); hi.y = pkh(h2, h3);
    lo.x = pkh(l0, l1); lo.y = pkh(l2, l3);
}

__device__ __forceinline__ uint2 cast4_h(float4 v) {
    uint2 r;
    r.x = pkh(__float2half_rn(v.x), __float2half_rn(v.y));
    r.y = pkh(__float2half_rn(v.z), __float2half_rn(v.w));
    return r;
}

// ---------------------------------------------------------------------------
// fp32 -> fp16 hi/lo split, and plain cast
// ---------------------------------------------------------------------------
__global__ __launch_bounds__(256)
void split_kernel(const float* __restrict__ in,
                  __half* __restrict__ hi,
                  __half* __restrict__ lo, int n4)
{
    const int idx = blockIdx.x * 256 + threadIdx.x;
    if (idx >= n4) return;
    float4 v = ((const float4*)in)[idx];
    uint2 h, l;
    split4_h(v, h, l);
    ((uint2*)hi)[idx] = h;
    ((uint2*)lo)[idx] = l;
}

__global__ __launch_bounds__(256)
void cast_kernel(const float* __restrict__ in, __half* __restrict__ out, int n4)
{
    const int idx = blockIdx.x * 256 + threadIdx.x;
    if (idx >= n4) return;
    ((uint2*)out)[idx] = cast4_h(((const float4*)in)[idx]);
}

// ---------------------------------------------------------------------------
// Plain fp16 GEMM: C = A16[M,K] @ B16[N,K]^T + bias
// CTA 128x128, BK=32, 256 thr (8 warps 2x4, warp tile 64x32), 2 CTAs/SM.
// Stage: A(8K) B(8K) = 16KB; 5-stage cp.async pipeline.
// ---------------------------------------------------------------------------
#define GBM 128
#define GBN 128
#define GBK 32
#define OFF_B  8192
#define BUF_B  16384
#define NSTAGE 5
#define GEMM_SMEM (NSTAGE * BUF_B)

__device__ __forceinline__ void issue_stage(
    uint32_t sdst,
    const __half* __restrict__ A, const __half* __restrict__ B,
    int K, int k0, int tid)
{
#pragma unroll
    for (int it = 0; it < 4; it++) {
        const int tile = it >> 1;                 // 0=A, 1=B
        const int c = (it & 1) * 256 + tid;       // 0..511
        const int row = c >> 2;                   // 0..127
        const int col = c & 3;                    // 16B chunk within 64B row
        const uint32_t dst = sdst + tile * 8192 + row * 64
                           + (uint32_t)((col ^ (row & 3)) << 4);
        const __half* src = (tile == 0)
            ? A + (size_t)row * K + k0 + col * 8
            : B + (size_t)row * K + k0 + col * 8;
        cpa16(dst, src);
    }
}

__device__ __forceinline__ void gemm_body(
    const __half* __restrict__ Ab, const __half* __restrict__ Bb,
    const float* __restrict__ bias, float* __restrict__ C,
    int N, int K, int bm, int bn, char* smem)
{
    const uint32_t sbase = smem_u32(smem);
    const int tid = threadIdx.x;
    const int wid = tid >> 5;
    const int lane = tid & 31;
    const int warp_m = wid >> 2;
    const int warp_n = wid & 3;

    const int l7 = lane & 7;
    const int l3 = lane & 3;
    const int amat = lane >> 3;
    const uint32_t a_row64 = (uint32_t)(warp_m * 64 + ((amat & 1) << 3) + l7) * 64;
    const int a_kh = amat >> 1;
    const int b_kh = (lane >> 3) & 1;
    const uint32_t b_row64 = (uint32_t)(warp_n * 32 + ((lane >> 4) << 3) + l7) * 64;

    float acc[4][4][4];
#pragma unroll
    for (int i = 0; i < 4; i++)
#pragma unroll
        for (int j = 0; j < 4; j++)
#pragma unroll
            for (int c = 0; c < 4; c++) acc[i][j][c] = 0.f;

    const int NB = K / GBK;

    issue_stage(sbase, Ab, Bb, K, 0, tid);
    asm volatile("cp.async.commit_group;");
    issue_stage(sbase + BUF_B, Ab, Bb, K, GBK, tid);
    asm volatile("cp.async.commit_group;");
    issue_stage(sbase + 2 * BUF_B, Ab, Bb, K, 2 * GBK, tid);
    asm volatile("cp.async.commit_group;");
    issue_stage(sbase + 3 * BUF_B, Ab, Bb, K, 3 * GBK, tid);
    asm volatile("cp.async.commit_group;");

    for (int kb = 0; kb < NB; kb++) {
        asm volatile("cp.async.wait_group 3;");
        __syncthreads();

        const int nk = kb + 4;
        if (nk < NB)
            issue_stage(sbase + (uint32_t)(nk % NSTAGE) * BUF_B,
                        Ab, Bb, K, nk * GBK, tid);
        asm volatile("cp.async.commit_group;");

        const uint32_t bufc = sbase + (uint32_t)(kb % NSTAGE) * BUF_B;

#pragma unroll
        for (int ks = 0; ks < 2; ks++) {
            const uint32_t a_swoff = (uint32_t)(((ks * 2 + a_kh) ^ l3) << 4);
            const uint32_t b_swoff = (uint32_t)(((ks * 2 + b_kh) ^ l3) << 4);

            uint32_t ah[4][4];
#pragma unroll
            for (int mt = 0; mt < 4; mt++)
                ldsm4(ah[mt], bufc + a_row64 + (uint32_t)mt * 1024 + a_swoff);

            uint32_t bh[2][4];
#pragma unroll
            for (int p = 0; p < 2; p++)
                ldsm4(bh[p], bufc + OFF_B + b_row64 + (uint32_t)p * 1024 + b_swoff);

#pragma unroll
            for (int mt = 0; mt < 4; mt++)
#pragma unroll
                for (int nt = 0; nt < 4; nt++)
                    mma_f16(acc[mt][nt], ah[mt], &bh[nt >> 1][(nt & 1) * 2]);
        }
    }

    const int g = lane >> 2;
    const int t = lane & 3;
#pragma unroll
    for (int nt = 0; nt < 4; nt++) {
        const int col = bn + warp_n * 32 + nt * 8 + 2 * t;
        const float b0 = bias[col];
        const float b1 = bias[col + 1];
#pragma unroll
        for (int mt = 0; mt < 4; mt++) {
            const int row = bm + warp_m * 64 + mt * 16 + g;
            float2 v0, v1;
            v0.x = acc[mt][nt][0] + b0;
            v0.y = acc[mt][nt][1] + b1;
            v1.x = acc[mt][nt][2] + b0;
            v1.y = acc[mt][nt][3] + b1;
            *(float2*)(C + (size_t)row * N + col) = v0;
            *(float2*)(C + (size_t)(row + 8) * N + col) = v1;
        }
    }
}

__global__ __launch_bounds__(256, 2)
void gemm_qkv(const __half* __restrict__ x16,
              const __half* __restrict__ wq, const __half* __restrict__ wk,
              const __half* __restrict__ wv,
              const float* __restrict__ bq, const float* __restrict__ bk,
              const float* __restrict__ bv,
              float* __restrict__ q, float* __restrict__ k, float* __restrict__ v)
{
    extern __shared__ __align__(1024) char smem[];
    const int bx = blockIdx.x;
    const int bm = blockIdx.y * GBM;

    const __half* Bh;
    const float* bias;
    float* C;
    int N, bn;
    if (bx < 32) {
        Bh = wq; bias = bq; C = q; N = NH_ * HD_; bn = bx * GBN;
    } else if (bx < 40) {
        Bh = wk; bias = bk; C = k; N = NKV_ * HD_; bn = (bx - 32) * GBN;
    } else {
        Bh = wv; bias = bv; C = v; N = NKV_ * HD_; bn = (bx - 40) * GBN;
    }

    gemm_body(x16 + (size_t)bm * HID_, Bh + (size_t)bn * HID_,
              bias, C, N, HID_, bm, bn, smem);
}

__global__ __launch_bounds__(256, 2)
void gemm_f16_pipe(int M, int N, int K,
                   const __half* __restrict__ A16,
                   const __half* __restrict__ B16,
                   const float* __restrict__ bias,
                   float* __restrict__ C)
{
    extern __shared__ __align__(1024) char smem[];
    const int bm = blockIdx.y * GBM;
    const int bn = blockIdx.x * GBN;
    gemm_body(A16 + (size_t)bm * K, B16 + (size_t)bn * K,
              bias, C, N, K, bm, bn, smem);
}

// ---------------------------------------------------------------------------
// Fused per-head LayerNorm + RoPE; reads fp32, writes plain fp16
// ---------------------------------------------------------------------------
__global__ __launch_bounds__(128)
void ln_rope_h(const float* __restrict__ in,
               __half* __restrict__ oh,
               const float* __restrict__ gw,
               const float* __restrict__ bw,
               int H)
{
    const int s = blockIdx.x;
    const int d = threadIdx.x;
    __shared__ float red[8];
    __shared__ float xs[HD_];

    const int dd = d & 63;
    const float inv = exp2f(-(float)dd * (LOG2_THETA / 64.0f));
    const float th = (float)s * inv;
    float sn, cs;
    sincosf(th, &sn, &cs);

    const float gv = gw[d];
    const float bv = bw[d];
    const int lane = d & 31;
    const int w = d >> 5;

    for (int h = 0; h < H; h++) {
        const float* x = in + ((size_t)s * H + h) * HD_;
        const float v = x[d];
        float s1 = v, s2 = v * v;
#pragma unroll
        for (int off = 16; off > 0; off >>= 1) {
            s1 += __shfl_xor_sync(0xffffffffu, s1, off);
            s2 += __shfl_xor_sync(0xffffffffu, s2, off);
        }
        if (lane == 0) { red[w] = s1; red[4 + w] = s2; }
        __syncthreads();
        const float sum = red[0] + red[1] + red[2] + red[3];
        const float sq  = red[4] + red[5] + red[6] + red[7];
        const float mu  = sum * (1.0f / HD_);
        const float var = sq * (1.0f / HD_) - mu * mu;
        const float r   = rsqrtf(var + EPS_);
        const float xn  = (v - mu) * r * gv + bv;
        xs[d] = xn;
        __syncthreads();
        const float other = (d < 64) ? -xs[d + 64] : xs[d - 64];
        const float res = xn * cs + other * sn;
        oh[((size_t)s * H + h) * HD_ + d] = __float2half_rn(res);
        __syncthreads();
    }
}

// ---------------------------------------------------------------------------
// Flash attention on mma.sync fp16 (unchanged math; plain fp16 output).
// BR=128 (8 warps x m16), BC=64, 256 threads.
// Q plain; K plain (QK 1 term); P plain, V split hi/lo (PV 2 terms).
// ---------------------------------------------------------------------------
#define FBR 128
#define FBC 64
#define FQ_CH 8192
#define FKV_CH 4096
#define FKV_TILE 16384
#define FBUF 49152
#define FSMEM (32768 + 2 * FBUF)

__device__ __forceinline__ void kv_stage(
    uint32_t dstbase,
    const __half* __restrict__ Kp,
    const __half* __restrict__ Vh, const __half* __restrict__ Vl,
    int kvh, int k0, int tid)
{
#pragma unroll
    for (int it = 0; it < 12; it++) {
        const int idx = it * 256 + tid;
        const int tile = idx >> 10;             // 0..2 = K, Vh, Vl
        const int sub = idx & 1023;
        const int row = sub >> 4;               // 0..63
        const int u8 = sub & 15;
        const __half* base = (tile == 0) ? Kp : (tile == 1) ? Vh : Vl;
        const __half* src = base + ((size_t)(k0 + row) * NKV_ + kvh) * HD_ + u8 * 8;
        const uint32_t dst = dstbase + tile * FKV_TILE + (u8 >> 2) * FKV_CH
                           + row * 64 + (uint32_t)(((u8 & 3) ^ (row & 3)) << 4);
        cpa16(dst, src);
    }
}

__global__ __launch_bounds__(256, 1)
void flash_mma(const __half* __restrict__ Q16,
               const __half* __restrict__ K16,
               const __half* __restrict__ Vh16, const __half* __restrict__ Vl16,
               __half* __restrict__ O16)
{
    extern __shared__ __align__(1024) char smem[];
    const uint32_t sbase = smem_u32(smem);
    const int qb = (int)gridDim.x - 1 - (int)blockIdx.x;   // big tiles first
    const int h = blockIdx.y;
    const int kvh = h >> 2;
    const int q0 = qb * FBR;
    const int tid = threadIdx.x;
    const int w = tid >> 5;
    const int lane = tid & 31;

    // prologue: Q + KV block 0
#pragma unroll
    for (int it = 0; it < 8; it++) {
        const int idx = it * 256 + tid;
        const int row = idx >> 4;
        const int u8 = idx & 15;
        const __half* src = Q16 + ((size_t)(q0 + row) * NH_ + h) * HD_ + u8 * 8;
        const uint32_t dst = sbase + (u8 >> 2) * FQ_CH + row * 64
                           + (uint32_t)(((u8 & 3) ^ (row & 3)) << 4);
        cpa16(dst, src);
    }
    kv_stage(sbase + 32768, K16, Vh16, Vl16, kvh, 0, tid);
    asm volatile("cp.async.commit_group;");

    float o[16][4];
#pragma unroll
    for (int i = 0; i < 16; i++)
#pragma unroll
        for (int c = 0; c < 4; c++) o[i][c] = 0.f;
    float m0 = -1e30f, m1 = -1e30f, l0 = 0.f, l1 = 0.f;

    const int l7 = lane & 7;
    const int qrow = w * 16 + ((lane >> 3) & 1) * 8 + l7;
    const int qm2 = lane >> 4;
    const int krow_base = ((lane >> 4) << 3) + l7;
    const int kh_sel = (lane >> 3) & 1;
    const int vrow_base = ((lane >> 3) & 1) * 8 + l7;
    const int vm2 = lane >> 4;

    const int nb = 2 * qb + 2;
    for (int kb = 0; kb < nb; kb++) {
        if (kb + 1 < nb)
            kv_stage(sbase + 32768 + ((kb + 1) & 1) * FBUF,
                     K16, Vh16, Vl16, kvh, (kb + 1) * FBC, tid);
        asm volatile("cp.async.commit_group;");
        asm volatile("cp.async.wait_group 1;");
        __syncthreads();

        const uint32_t B = sbase + 32768 + (uint32_t)(kb & 1) * FBUF;

        // ---- QK: sc = Q K^T ----
        float sc[8][4];
#pragma unroll
        for (int i = 0; i < 8; i++)
#pragma unroll
            for (int c = 0; c < 4; c++) sc[i][c] = 0.f;

#pragma unroll
        for (int kd = 0; kd < 8; kd++) {
            uint32_t qa[4];
            {
                const int u8 = kd * 2 + qm2;
                ldsm4(qa, sbase + (u8 >> 2) * FQ_CH + qrow * 64
                          + (uint32_t)(((u8 & 3) ^ (qrow & 3)) << 4));
            }
            const int u8k = kd * 2 + kh_sel;
#pragma unroll
            for (int j = 0; j < 4; j++) {
                const int krow = j * 16 + krow_base;
                const uint32_t koff = (u8k >> 2) * FKV_CH + krow * 64
                                    + (uint32_t)(((u8k & 3) ^ (krow & 3)) << 4);
                uint32_t kb4[4];
                ldsm4(kb4, B + koff);
                mma_f16(sc[2 * j],     qa, &kb4[0]);
                mma_f16(sc[2 * j + 1], qa, &kb4[2]);
            }
        }

        // ---- softmax (exp2 domain) ----
        const int row0 = q0 + w * 16 + (lane >> 2);
        const int col_base = kb * FBC + (lane & 3) * 2;
        const bool maybe_mask = (kb * FBC + FBC - 1) > (q0 + w * 16);
        float mx0 = -1e30f, mx1 = -1e30f;
#pragma unroll
        for (int nt = 0; nt < 8; nt++) {
            float v0 = sc[nt][0] * SC2_;
            float v1 = sc[nt][1] * SC2_;
            float v2 = sc[nt][2] * SC2_;
            float v3 = sc[nt][3] * SC2_;
            if (maybe_mask) {
                const int c0 = col_base + nt * 8;
                if (c0 > row0)         v0 = -1e30f;
                if (c0 + 1 > row0)     v1 = -1e30f;
                if (c0 > row0 + 8)     v2 = -1e30f;
                if (c0 + 1 > row0 + 8) v3 = -1e30f;
            }
            sc[nt][0] = v0; sc[nt][1] = v1; sc[nt][2] = v2; sc[nt][3] = v3;
            mx0 = fmaxf(mx0, fmaxf(v0, v1));
            mx1 = fmaxf(mx1, fmaxf(v2, v3));
        }
        mx0 = fmaxf(mx0, __shfl_xor_sync(0xffffffffu, mx0, 1));
        mx0 = fmaxf(mx0, __shfl_xor_sync(0xffffffffu, mx0, 2));
        mx1 = fmaxf(mx1, __shfl_xor_sync(0xffffffffu, mx1, 1));
        mx1 = fmaxf(mx1, __shfl_xor_sync(0xffffffffu, mx1, 2));
        const float mn0 = fmaxf(m0, mx0);
        const float mn1 = fmaxf(m1, mx1);
        const float al0 = exp2f(m0 - mn0);
        const float al1 = exp2f(m1 - mn1);
        m0 = mn0; m1 = mn1;

        uint32_t ph[8][2];
        float rs0 = 0.f, rs1 = 0.f;
#pragma unroll
        for (int nt = 0; nt < 8; nt++) {
            const float p0 = exp2f(sc[nt][0] - mn0);
            const float p1 = exp2f(sc[nt][1] - mn0);
            const float p2 = exp2f(sc[nt][2] - mn1);
            const float p3 = exp2f(sc[nt][3] - mn1);
            rs0 += p0 + p1; rs1 += p2 + p3;
            ph[nt][0] = pkh(__float2half_rn(p0), __float2half_rn(p1));
            ph[nt][1] = pkh(__float2half_rn(p2), __float2half_rn(p3));
        }
        rs0 += __shfl_xor_sync(0xffffffffu, rs0, 1);
        rs0 += __shfl_xor_sync(0xffffffffu, rs0, 2);
        rs1 += __shfl_xor_sync(0xffffffffu, rs1, 1);
        rs1 += __shfl_xor_sync(0xffffffffu, rs1, 2);
        l0 = l0 * al0 + rs0;
        l1 = l1 * al1 + rs1;
#pragma unroll
        for (int j = 0; j < 16; j++) {
            o[j][0] *= al0; o[j][1] *= al0;
            o[j][2] *= al1; o[j][3] *= al1;
        }

        // ---- PV: o += P Vh + P Vl ----
#pragma unroll
        for (int ks = 0; ks < 4; ks++) {
            uint32_t aph[4] = { ph[2 * ks][0], ph[2 * ks][1],
                                ph[2 * ks + 1][0], ph[2 * ks + 1][1] };
            const int vrow = ks * 16 + vrow_base;
#pragma unroll
            for (int j = 0; j < 8; j++) {
                const int u8 = 2 * j + vm2;
                const uint32_t voff = (u8 >> 2) * FKV_CH + vrow * 64
                                    + (uint32_t)(((u8 & 3) ^ (vrow & 3)) << 4);
                uint32_t vh4[4], vl4[4];
                ldsm4t(vh4, B + FKV_TILE + voff);
                ldsm4t(vl4, B + 2 * FKV_TILE + voff);
                mma_f16(o[2 * j],     aph, &vh4[0]);
                mma_f16(o[2 * j + 1], aph, &vh4[2]);
                mma_f16(o[2 * j],     aph, &vl4[0]);
                mma_f16(o[2 * j + 1], aph, &vl4[2]);
            }
        }
        __syncthreads();
    }

    // ---- epilogue: O /= l, store plain fp16 ----
    const float inv0 = 1.f / l0;
    const float inv1 = 1.f / l1;
    const int r0 = q0 + w * 16 + (lane >> 2);
    const size_t base0 = ((size_t)r0 * NH_ + h) * HD_ + (lane & 3) * 2;
    const size_t base1 = ((size_t)(r0 + 8) * NH_ + h) * HD_ + (lane & 3) * 2;
#pragma unroll
    for (int nt = 0; nt < 16; nt++) {
        *(uint32_t*)(O16 + base0 + nt * 8) =
            pkh(__float2half_rn(o[nt][0] * inv0), __float2half_rn(o[nt][1] * inv0));
        *(uint32_t*)(O16 + base1 + nt * 8) =
            pkh(__float2half_rn(o[nt][2] * inv1), __float2half_rn(o[nt][3] * inv1));
    }
}

// ---------------------------------------------------------------------------
// Launch
// ---------------------------------------------------------------------------
extern "C" void kernel_launch(void* const* d_in, const int* in_sizes, int n_in,
                              void* d_out, int out_size)
{
    const float* x   = (const float*)d_in[0];
    const float* Wq  = (const float*)d_in[1];
    const float* bq  = (const float*)d_in[2];
    const float* Wk  = (const float*)d_in[3];
    const float* bk  = (const float*)d_in[4];
    const float* Wv  = (const float*)d_in[5];
    const float* bv  = (const float*)d_in[6];
    const float* Wo  = (const float*)d_in[7];
    const float* bo  = (const float*)d_in[8];
    const float* qng = (const float*)d_in[9];
    const float* qnb = (const float*)d_in[10];
    const float* kng = (const float*)d_in[11];
    const float* knb = (const float*)d_in[12];
    float* out = (float*)d_out;

    float *qp, *kp, *vp;
    __half *x16, *wq16, *wk16, *wv16, *wo16, *ao16;
    __half *q16, *k16, *vh16, *vl16;
    cudaGetSymbolAddress((void**)&qp, g_q);
    cudaGetSymbolAddress((void**)&kp, g_k);
    cudaGetSymbolAddress((void**)&vp, g_v);
    cudaGetSymbolAddress((void**)&x16, g_x16);
    cudaGetSymbolAddress((void**)&wq16, g_wq16);
    cudaGetSymbolAddress((void**)&wk16, g_wk16);
    cudaGetSymbolAddress((void**)&wv16, g_wv16);
    cudaGetSymbolAddress((void**)&wo16, g_wo16);
    cudaGetSymbolAddress((void**)&ao16, g_ao16);
    cudaGetSymbolAddress((void**)&q16, g_q16);
    cudaGetSymbolAddress((void**)&k16, g_k16);
    cudaGetSymbolAddress((void**)&vh16, g_vh16);
    cudaGetSymbolAddress((void**)&vl16, g_vl16);

    cudaFuncSetAttribute(gemm_qkv, cudaFuncAttributeMaxDynamicSharedMemorySize,
                         GEMM_SMEM);
    cudaFuncSetAttribute(gemm_f16_pipe, cudaFuncAttributeMaxDynamicSharedMemorySize,
                         GEMM_SMEM);
    cudaFuncSetAttribute(flash_mma, cudaFuncAttributeMaxDynamicSharedMemorySize,
                         FSMEM);

    const int n4_x  = S_ * HID_ / 4;
    const int n4_wq = NH_ * HD_ * HID_ / 4;
    const int n4_wk = NKV_ * HD_ * HID_ / 4;
    const int n4_wo = HID_ * HID_ / 4;
    const int n4_v  = S_ * NKV_ * HD_ / 4;
    cast_kernel<<<n4_x / 256, 256>>>(x, x16, n4_x);
    cast_kernel<<<n4_wq / 256, 256>>>(Wq, wq16, n4_wq);
    cast_kernel<<<n4_wk / 256, 256>>>(Wk, wk16, n4_wk);
    cast_kernel<<<n4_wk / 256, 256>>>(Wv, wv16, n4_wk);
    cast_kernel<<<n4_wo / 256, 256>>>(Wo, wo16, n4_wo);

    // fused QKV projection (plain fp16)
    gemm_qkv<<<dim3(48, S_ / GBM), 256, GEMM_SMEM>>>(
        x16, wq16, wk16, wv16, bq, bk, bv, qp, kp, vp);

    // LayerNorm + RoPE -> plain fp16
    ln_rope_h<<<S_, HD_>>>(qp, q16, qng, qnb, NH_);
    ln_rope_h<<<S_, HD_>>>(kp, k16, kng, knb, NKV_);
    // V -> fp16 split (kept: PV stays 2-term)
    split_kernel<<<n4_v / 256, 256>>>(vp, vh16, vl16, n4_v);

    // flash attention on tensor cores -> plain fp16 output
    flash_mma<<<dim3(S_ / FBR, NH_), 256, FSMEM>>>(
        q16, k16, vh16, vl16, ao16);

    // output projection (plain fp16)
    gemm_f16_pipe<<<dim3(HID_ / GBN, S_ / GBM), 256, GEMM_SMEM>>>(
        S_, HID_, HID_, ao16, wo16, bo, out);
}

// round 15
// speedup vs baseline: 6.3110x; 1.0880x over previous
#include <cuda_runtime.h>
#include <cuda_fp16.h>
#include <math.h>
#include <cstdint>

// Problem constants
#define S_    2048
#define HID_  4096
#define NH_   32
#define NKV_  8
#define HD_   128
#define EPS_  1e-5f
#define SCALE_ 0.088388347648318447f
#define SC2_  (SCALE_ * 1.4426950408889634f)
#define LOG2_THETA 18.931568569324174f

// ---------------------------------------------------------------------------
// Scratch (device globals; no allocation allowed)
// ---------------------------------------------------------------------------
__device__ float g_q[S_ * NH_ * HD_];
__device__ float g_k[S_ * NKV_ * HD_];
__device__ float g_v[S_ * NKV_ * HD_];
__device__ __half g_x16[S_ * HID_];
__device__ __half g_wq16[NH_ * HD_ * HID_];
__device__ __half g_wk16[NKV_ * HD_ * HID_];
__device__ __half g_wv16[NKV_ * HD_ * HID_];
__device__ __half g_wo16[HID_ * HID_];
__device__ __half g_ao16[S_ * HID_];
// fp16 attention operands (all plain)
__device__ __half g_q16[S_ * NH_ * HD_];
__device__ __half g_k16[S_ * NKV_ * HD_];
__device__ __half g_v16[S_ * NKV_ * HD_];

// ---------------------------------------------------------------------------
// Helpers
// ---------------------------------------------------------------------------
__device__ __forceinline__ uint32_t smem_u32(const void* p) {
    uint32_t a;
    asm("{ .reg .u64 t; cvta.to.shared.u64 t, %1; cvt.u32.u64 %0, t; }"
        : "=r"(a) : "l"(p));
    return a;
}

__device__ __forceinline__ void ldsm4(uint32_t* r, uint32_t addr) {
    asm volatile("ldmatrix.sync.aligned.m8n8.x4.shared.b16 {%0,%1,%2,%3}, [%4];"
                 : "=r"(r[0]), "=r"(r[1]), "=r"(r[2]), "=r"(r[3]) : "r"(addr));
}

__device__ __forceinline__ void ldsm4t(uint32_t* r, uint32_t addr) {
    asm volatile("ldmatrix.sync.aligned.m8n8.x4.trans.shared.b16 {%0,%1,%2,%3}, [%4];"
                 : "=r"(r[0]), "=r"(r[1]), "=r"(r[2]), "=r"(r[3]) : "r"(addr));
}

__device__ __forceinline__ void mma_f16(float* d, const uint32_t* a, const uint32_t* b) {
    asm volatile(
        "mma.sync.aligned.m16n8k16.row.col.f32.f16.f16.f32 "
        "{%0,%1,%2,%3}, {%4,%5,%6,%7}, {%8,%9}, {%0,%1,%2,%3};"
        : "+f"(d[0]), "+f"(d[1]), "+f"(d[2]), "+f"(d[3])
        : "r"(a[0]), "r"(a[1]), "r"(a[2]), "r"(a[3]), "r"(b[0]), "r"(b[1]));
}

__device__ __forceinline__ void cpa16(uint32_t dst, const void* src) {
    asm volatile("cp.async.cg.shared.global [%0], [%1], 16;" :: "r"(dst), "l"(src));
}

__device__ __forceinline__ uint32_t pkh(__half a, __half b) {
    __half2 t = __halves2half2(a, b);
    return *reinterpret_cast<uint32_t*>(&t);
}

__device__ __forceinline__ uint2 cast4_h(float4 v) {
    uint2 r;
    r.x = pkh(__float2half_rn(v.x), __float2half_rn(v.y));
    r.y = pkh(__float2half_rn(v.z), __float2half_rn(v.w));
    return r;
}

// ---------------------------------------------------------------------------
// fp32 -> fp16 cast, 32 bytes per thread (2x float4 in, 1x uint4 out)
// ---------------------------------------------------------------------------
__global__ __launch_bounds__(256)
void cast_kernel(const float* __restrict__ in, __half* __restrict__ out, int n8)
{
    const int idx = blockIdx.x * 256 + threadIdx.x;
    if (idx >= n8) return;
    float4 a = ((const float4*)in)[2 * idx];
    float4 b = ((const float4*)in)[2 * idx + 1];
    uint2 ra = cast4_h(a);
    uint2 rb = cast4_h(b);
    uint4 o;
    o.x = ra.x; o.y = ra.y; o.z = rb.x; o.w = rb.y;
    ((uint4*)out)[idx] = o;
}

// ---------------------------------------------------------------------------
// Plain fp16 GEMM (unchanged from R14 — passing):
// CTA 128x128, BK=32, 256 thr (8 warps 2x4), 2 CTAs/SM, 5-stage cp.async.
// ---------------------------------------------------------------------------
#define GBM 128
#define GBN 128
#define GBK 32
#define OFF_B  8192
#define BUF_B  16384
#define NSTAGE 5
#define GEMM_SMEM (NSTAGE * BUF_B)

__device__ __forceinline__ void issue_stage(
    uint32_t sdst,
    const __half* __restrict__ A, const __half* __restrict__ B,
    int K, int k0, int tid)
{
#pragma unroll
    for (int it = 0; it < 4; it++) {
        const int tile = it >> 1;
        const int c = (it & 1) * 256 + tid;
        const int row = c >> 2;
        const int col = c & 3;
        const uint32_t dst = sdst + tile * 8192 + row * 64
                           + (uint32_t)((col ^ (row & 3)) << 4);
        const __half* src = (tile == 0)
            ? A + (size_t)row * K + k0 + col * 8
            : B + (size_t)row * K + k0 + col * 8;
        cpa16(dst, src);
    }
}

__device__ __forceinline__ void gemm_body(
    const __half* __restrict__ Ab, const __half* __restrict__ Bb,
    const float* __restrict__ bias, float* __restrict__ C,
    int N, int K, int bm, int bn, char* smem)
{
    const uint32_t sbase = smem_u32(smem);
    const int tid = threadIdx.x;
    const int wid = tid >> 5;
    const int lane = tid & 31;
    const int warp_m = wid >> 2;
    const int warp_n = wid & 3;

    const int l7 = lane & 7;
    const int l3 = lane & 3;
    const int amat = lane >> 3;
    const uint32_t a_row64 = (uint32_t)(warp_m * 64 + ((amat & 1) << 3) + l7) * 64;
    const int a_kh = amat >> 1;
    const int b_kh = (lane >> 3) & 1;
    const uint32_t b_row64 = (uint32_t)(warp_n * 32 + ((lane >> 4) << 3) + l7) * 64;

    float acc[4][4][4];
#pragma unroll
    for (int i = 0; i < 4; i++)
#pragma unroll
        for (int j = 0; j < 4; j++)
#pragma unroll
            for (int c = 0; c < 4; c++) acc[i][j][c] = 0.f;

    const int NB = K / GBK;

    issue_stage(sbase, Ab, Bb, K, 0, tid);
    asm volatile("cp.async.commit_group;");
    issue_stage(sbase + BUF_B, Ab, Bb, K, GBK, tid);
    asm volatile("cp.async.commit_group;");
    issue_stage(sbase + 2 * BUF_B, Ab, Bb, K, 2 * GBK, tid);
    asm volatile("cp.async.commit_group;");
    issue_stage(sbase + 3 * BUF_B, Ab, Bb, K, 3 * GBK, tid);
    asm volatile("cp.async.commit_group;");

    for (int kb = 0; kb < NB; kb++) {
        asm volatile("cp.async.wait_group 3;");
        __syncthreads();

        const int nk = kb + 4;
        if (nk < NB)
            issue_stage(sbase + (uint32_t)(nk % NSTAGE) * BUF_B,
                        Ab, Bb, K, nk * GBK, tid);
        asm volatile("cp.async.commit_group;");

        const uint32_t bufc = sbase + (uint32_t)(kb % NSTAGE) * BUF_B;

#pragma unroll
        for (int ks = 0; ks < 2; ks++) {
            const uint32_t a_swoff = (uint32_t)(((ks * 2 + a_kh) ^ l3) << 4);
            const uint32_t b_swoff = (uint32_t)(((ks * 2 + b_kh) ^ l3) << 4);

            uint32_t ah[4][4];
#pragma unroll
            for (int mt = 0; mt < 4; mt++)
                ldsm4(ah[mt], bufc + a_row64 + (uint32_t)mt * 1024 + a_swoff);

            uint32_t bh[2][4];
#pragma unroll
            for (int p = 0; p < 2; p++)
                ldsm4(bh[p], bufc + OFF_B + b_row64 + (uint32_t)p * 1024 + b_swoff);

#pragma unroll
            for (int mt = 0; mt < 4; mt++)
#pragma unroll
                for (int nt = 0; nt < 4; nt++)
                    mma_f16(acc[mt][nt], ah[mt], &bh[nt >> 1][(nt & 1) * 2]);
        }
    }

    const int g = lane >> 2;
    const int t = lane & 3;
#pragma unroll
    for (int nt = 0; nt < 4; nt++) {
        const int col = bn + warp_n * 32 + nt * 8 + 2 * t;
        const float b0 = bias[col];
        const float b1 = bias[col + 1];
#pragma unroll
        for (int mt = 0; mt < 4; mt++) {
            const int row = bm + warp_m * 64 + mt * 16 + g;
            float2 v0, v1;
            v0.x = acc[mt][nt][0] + b0;
            v0.y = acc[mt][nt][1] + b1;
            v1.x = acc[mt][nt][2] + b0;
            v1.y = acc[mt][nt][3] + b1;
            *(float2*)(C + (size_t)row * N + col) = v0;
            *(float2*)(C + (size_t)(row + 8) * N + col) = v1;
        }
    }
}

__global__ __launch_bounds__(256, 2)
void gemm_qkv(const __half* __restrict__ x16,
              const __half* __restrict__ wq, const __half* __restrict__ wk,
              const __half* __restrict__ wv,
              const float* __restrict__ bq, const float* __restrict__ bk,
              const float* __restrict__ bv,
              float* __restrict__ q, float* __restrict__ k, float* __restrict__ v)
{
    extern __shared__ __align__(1024) char smem[];
    const int bx = blockIdx.x;
    const int bm = blockIdx.y * GBM;

    const __half* Bh;
    const float* bias;
    float* C;
    int N, bn;
    if (bx < 32) {
        Bh = wq; bias = bq; C = q; N = NH_ * HD_; bn = bx * GBN;
    } else if (bx < 40) {
        Bh = wk; bias = bk; C = k; N = NKV_ * HD_; bn = (bx - 32) * GBN;
    } else {
        Bh = wv; bias = bv; C = v; N = NKV_ * HD_; bn = (bx - 40) * GBN;
    }

    gemm_body(x16 + (size_t)bm * HID_, Bh + (size_t)bn * HID_,
              bias, C, N, HID_, bm, bn, smem);
}

__global__ __launch_bounds__(256, 2)
void gemm_f16_pipe(int M, int N, int K,
                   const __half* __restrict__ A16,
                   const __half* __restrict__ B16,
                   const float* __restrict__ bias,
                   float* __restrict__ C)
{
    extern __shared__ __align__(1024) char smem[];
    const int bm = blockIdx.y * GBM;
    const int bn = blockIdx.x * GBN;
    gemm_body(A16 + (size_t)bm * K, B16 + (size_t)bn * K,
              bias, C, N, K, bm, bn, smem);
}

// ---------------------------------------------------------------------------
// Fused per-head LayerNorm + RoPE; one block per (token, head).
// ---------------------------------------------------------------------------
__global__ __launch_bounds__(128)
void ln_rope_h(const float* __restrict__ in,
               __half* __restrict__ oh,
               const float* __restrict__ gw,
               const float* __restrict__ bw,
               int H)
{
    const int s = blockIdx.x;
    const int h = blockIdx.y;
    const int d = threadIdx.x;
    __shared__ float red[8];
    __shared__ float xs[HD_];

    const int dd = d & 63;
    const float inv = exp2f(-(float)dd * (LOG2_THETA / 64.0f));
    const float th = (float)s * inv;
    float sn, cs;
    sincosf(th, &sn, &cs);

    const int lane = d & 31;
    const int w = d >> 5;

    const float v = in[((size_t)s * H + h) * HD_ + d];
    float s1 = v, s2 = v * v;
#pragma unroll
    for (int off = 16; off > 0; off >>= 1) {
        s1 += __shfl_xor_sync(0xffffffffu, s1, off);
        s2 += __shfl_xor_sync(0xffffffffu, s2, off);
    }
    if (lane == 0) { red[w] = s1; red[4 + w] = s2; }
    __syncthreads();
    const float sum = red[0] + red[1] + red[2] + red[3];
    const float sq  = red[4] + red[5] + red[6] + red[7];
    const float mu  = sum * (1.0f / HD_);
    const float var = sq * (1.0f / HD_) - mu * mu;
    const float r   = rsqrtf(var + EPS_);
    const float xn  = (v - mu) * r * gw[d] + bw[d];
    xs[d] = xn;
    __syncthreads();
    const float other = (d < 64) ? -xs[d + 64] : xs[d - 64];
    oh[((size_t)s * H + h) * HD_ + d] = __float2half_rn(xn * cs + other * sn);
}

// ---------------------------------------------------------------------------
// Flash attention on mma.sync fp16 — all operands plain fp16.
// BR=128 (8 warps x m16), BC=64, 256 threads.
// QK 1 term; PV 1 term. SMEM: Q 32KB + 2 KV buffers of [K|V] = 96KB.
// ---------------------------------------------------------------------------
#define FBR 128
#define FBC 64
#define FQ_CH 8192
#define FKV_CH 4096
#define FKV_TILE 16384
#define FBUF 32768
#define FSMEM (32768 + 2 * FBUF)

__device__ __forceinline__ void kv_stage(
    uint32_t dstbase,
    const __half* __restrict__ Kp, const __half* __restrict__ Vp,
    int kvh, int k0, int tid)
{
#pragma unroll
    for (int it = 0; it < 8; it++) {
        const int idx = it * 256 + tid;
        const int tile = idx >> 10;             // 0=K, 1=V
        const int sub = idx & 1023;
        const int row = sub >> 4;               // 0..63
        const int u8 = sub & 15;
        const __half* base = (tile == 0) ? Kp : Vp;
        const __half* src = base + ((size_t)(k0 + row) * NKV_ + kvh) * HD_ + u8 * 8;
        const uint32_t dst = dstbase + tile * FKV_TILE + (u8 >> 2) * FKV_CH
                           + row * 64 + (uint32_t)(((u8 & 3) ^ (row & 3)) << 4);
        cpa16(dst, src);
    }
}

__global__ __launch_bounds__(256, 1)
void flash_mma(const __half* __restrict__ Q16,
               const __half* __restrict__ K16,
               const __half* __restrict__ V16,
               __half* __restrict__ O16)
{
    extern __shared__ __align__(1024) char smem[];
    const uint32_t sbase = smem_u32(smem);
    const int qb = (int)gridDim.x - 1 - (int)blockIdx.x;   // big tiles first
    const int h = blockIdx.y;
    const int kvh = h >> 2;
    const int q0 = qb * FBR;
    const int tid = threadIdx.x;
    const int w = tid >> 5;
    const int lane = tid & 31;

    // prologue: Q + KV block 0
#pragma unroll
    for (int it = 0; it < 8; it++) {
        const int idx = it * 256 + tid;
        const int row = idx >> 4;
        const int u8 = idx & 15;
        const __half* src = Q16 + ((size_t)(q0 + row) * NH_ + h) * HD_ + u8 * 8;
        const uint32_t dst = sbase + (u8 >> 2) * FQ_CH + row * 64
                           + (uint32_t)(((u8 & 3) ^ (row & 3)) << 4);
        cpa16(dst, src);
    }
    kv_stage(sbase + 32768, K16, V16, kvh, 0, tid);
    asm volatile("cp.async.commit_group;");

    float o[16][4];
#pragma unroll
    for (int i = 0; i < 16; i++)
#pragma unroll
        for (int c = 0; c < 4; c++) o[i][c] = 0.f;
    float m0 = -1e30f, m1 = -1e30f, l0 = 0.f, l1 = 0.f;

    const int l7 = lane & 7;
    const int qrow = w * 16 + ((lane >> 3) & 1) * 8 + l7;
    const int qm2 = lane >> 4;
    const int krow_base = ((lane >> 4) << 3) + l7;
    const int kh_sel = (lane >> 3) & 1;
    const int vrow_base = ((lane >> 3) & 1) * 8 + l7;
    const int vm2 = lane >> 4;

    const int nb = 2 * qb + 2;
    for (int kb = 0; kb < nb; kb++) {
        if (kb + 1 < nb)
            kv_stage(sbase + 32768 + ((kb + 1) & 1) * FBUF,
                     K16, V16, kvh, (kb + 1) * FBC, tid);
        asm volatile("cp.async.commit_group;");
        asm volatile("cp.async.wait_group 1;");
        __syncthreads();

        const uint32_t B = sbase + 32768 + (uint32_t)(kb & 1) * FBUF;

        // ---- QK: sc = Q K^T ----
        float sc[8][4];
#pragma unroll
        for (int i = 0; i < 8; i++)
#pragma unroll
            for (int c = 0; c < 4; c++) sc[i][c] = 0.f;

#pragma unroll
        for (int kd = 0; kd < 8; kd++) {
            uint32_t qa[4];
            {
                const int u8 = kd * 2 + qm2;
                ldsm4(qa, sbase + (u8 >> 2) * FQ_CH + qrow * 64
                          + (uint32_t)(((u8 & 3) ^ (qrow & 3)) << 4));
            }
            const int u8k = kd * 2 + kh_sel;
#pragma unroll
            for (int j = 0; j < 4; j++) {
                const int krow = j * 16 + krow_base;
                const uint32_t koff = (u8k >> 2) * FKV_CH + krow * 64
                                    + (uint32_t)(((u8k & 3) ^ (krow & 3)) << 4);
                uint32_t kb4[4];
                ldsm4(kb4, B + koff);
                mma_f16(sc[2 * j],     qa, &kb4[0]);
                mma_f16(sc[2 * j + 1], qa, &kb4[2]);
            }
        }

        // ---- softmax (exp2 domain) ----
        const int row0 = q0 + w * 16 + (lane >> 2);
        const int col_base = kb * FBC + (lane & 3) * 2;
        const bool maybe_mask = (kb * FBC + FBC - 1) > (q0 + w * 16);
        float mx0 = -1e30f, mx1 = -1e30f;
#pragma unroll
        for (int nt = 0; nt < 8; nt++) {
            float v0 = sc[nt][0] * SC2_;
            float v1 = sc[nt][1] * SC2_;
            float v2 = sc[nt][2] * SC2_;
            float v3 = sc[nt][3] * SC2_;
            if (maybe_mask) {
                const int c0 = col_base + nt * 8;
                if (c0 > row0)         v0 = -1e30f;
                if (c0 + 1 > row0)     v1 = -1e30f;
                if (c0 > row0 + 8)     v2 = -1e30f;
                if (c0 + 1 > row0 + 8) v3 = -1e30f;
            }
            sc[nt][0] = v0; sc[nt][1] = v1; sc[nt][2] = v2; sc[nt][3] = v3;
            mx0 = fmaxf(mx0, fmaxf(v0, v1));
            mx1 = fmaxf(mx1, fmaxf(v2, v3));
        }
        mx0 = fmaxf(mx0, __shfl_xor_sync(0xffffffffu, mx0, 1));
        mx0 = fmaxf(mx0, __shfl_xor_sync(0xffffffffu, mx0, 2));
        mx1 = fmaxf(mx1, __shfl_xor_sync(0xffffffffu, mx1, 1));
        mx1 = fmaxf(mx1, __shfl_xor_sync(0xffffffffu, mx1, 2));
        const float mn0 = fmaxf(m0, mx0);
        const float mn1 = fmaxf(m1, mx1);
        const float al0 = exp2f(m0 - mn0);
        const float al1 = exp2f(m1 - mn1);
        m0 = mn0; m1 = mn1;

        uint32_t ph[8][2];
        float rs0 = 0.f, rs1 = 0.f;
#pragma unroll
        for (int nt = 0; nt < 8; nt++) {
            const float p0 = exp2f(sc[nt][0] - mn0);
            const float p1 = exp2f(sc[nt][1] - mn0);
            const float p2 = exp2f(sc[nt][2] - mn1);
            const float p3 = exp2f(sc[nt][3] - mn1);
            rs0 += p0 + p1; rs1 += p2 + p3;
            ph[nt][0] = pkh(__float2half_rn(p0), __float2half_rn(p1));
            ph[nt][1] = pkh(__float2half_rn(p2), __float2half_rn(p3));
        }
        rs0 += __shfl_xor_sync(0xffffffffu, rs0, 1);
        rs0 += __shfl_xor_sync(0xffffffffu, rs0, 2);
        rs1 += __shfl_xor_sync(0xffffffffu, rs1, 1);
        rs1 += __shfl_xor_sync(0xffffffffu, rs1, 2);
        l0 = l0 * al0 + rs0;
        l1 = l1 * al1 + rs1;
#pragma unroll
        for (int j = 0; j < 16; j++) {
            o[j][0] *= al0; o[j][1] *= al0;
            o[j][2] *= al1; o[j][3] *= al1;
        }

        // ---- PV: o += P V ----
#pragma unroll
        for (int ks = 0; ks < 4; ks++) {
            uint32_t aph[4] = { ph[2 * ks][0], ph[2 * ks][1],
                                ph[2 * ks + 1][0], ph[2 * ks + 1][1] };
            const int vrow = ks * 16 + vrow_base;
#pragma unroll
            for (int j = 0; j < 8; j++) {
                const int u8 = 2 * j + vm2;
                const uint32_t voff = (u8 >> 2) * FKV_CH + vrow * 64
                                    + (uint32_t)(((u8 & 3) ^ (vrow & 3)) << 4);
                uint32_t vh4[4];
                ldsm4t(vh4, B + FKV_TILE + voff);
                mma_f16(o[2 * j],     aph, &vh4[0]);
                mma_f16(o[2 * j + 1], aph, &vh4[2]);
            }
        }
        __syncthreads();
    }

    // ---- epilogue: O /= l, store plain fp16 ----
    const float inv0 = 1.f / l0;
    const float inv1 = 1.f / l1;
    const int r0 = q0 + w * 16 + (lane >> 2);
    const size_t base0 = ((size_t)r0 * NH_ + h) * HD_ + (lane & 3) * 2;
    const size_t base1 = ((size_t)(r0 + 8) * NH_ + h) * HD_ + (lane & 3) * 2;
#pragma unroll
    for (int nt = 0; nt < 16; nt++) {
        *(uint32_t*)(O16 + base0 + nt * 8) =
            pkh(__float2half_rn(o[nt][0] * inv0), __float2half_rn(o[nt][1] * inv0));
        *(uint32_t*)(O16 + base1 + nt * 8) =
            pkh(__float2half_rn(o[nt][2] * inv1), __float2half_rn(o[nt][3] * inv1));
    }
}

// ---------------------------------------------------------------------------
// Launch
// ---------------------------------------------------------------------------
extern "C" void kernel_launch(void* const* d_in, const int* in_sizes, int n_in,
                              void* d_out, int out_size)
{
    const float* x   = (const float*)d_in[0];
    const float* Wq  = (const float*)d_in[1];
    const float* bq  = (const float*)d_in[2];
    const float* Wk  = (const float*)d_in[3];
    const float* bk  = (const float*)d_in[4];
    const float* Wv  = (const float*)d_in[5];
    const float* bv  = (const float*)d_in[6];
    const float* Wo  = (const float*)d_in[7];
    const float* bo  = (const float*)d_in[8];
    const float* qng = (const float*)d_in[9];
    const float* qnb = (const float*)d_in[10];
    const float* kng = (const float*)d_in[11];
    const float* knb = (const float*)d_in[12];
    float* out = (float*)d_out;

    float *qp, *kp, *vp;
    __half *x16, *wq16, *wk16, *wv16, *wo16, *ao16;
    __half *q16, *k16, *v16;
    cudaGetSymbolAddress((void**)&qp, g_q);
    cudaGetSymbolAddress((void**)&kp, g_k);
    cudaGetSymbolAddress((void**)&vp, g_v);
    cudaGetSymbolAddress((void**)&x16, g_x16);
    cudaGetSymbolAddress((void**)&wq16, g_wq16);
    cudaGetSymbolAddress((void**)&wk16, g_wk16);
    cudaGetSymbolAddress((void**)&wv16, g_wv16);
    cudaGetSymbolAddress((void**)&wo16, g_wo16);
    cudaGetSymbolAddress((void**)&ao16, g_ao16);
    cudaGetSymbolAddress((void**)&q16, g_q16);
    cudaGetSymbolAddress((void**)&k16, g_k16);
    cudaGetSymbolAddress((void**)&v16, g_v16);

    cudaFuncSetAttribute(gemm_qkv, cudaFuncAttributeMaxDynamicSharedMemorySize,
                         GEMM_SMEM);
    cudaFuncSetAttribute(gemm_f16_pipe, cudaFuncAttributeMaxDynamicSharedMemorySize,
                         GEMM_SMEM);
    cudaFuncSetAttribute(flash_mma, cudaFuncAttributeMaxDynamicSharedMemorySize,
                         FSMEM);

    const int n8_x  = S_ * HID_ / 8;
    const int n8_wq = NH_ * HD_ * HID_ / 8;
    const int n8_wk = NKV_ * HD_ * HID_ / 8;
    const int n8_wo = HID_ * HID_ / 8;
    const int n8_v  = S_ * NKV_ * HD_ / 8;
    cast_kernel<<<n8_x / 256, 256>>>(x, x16, n8_x);
    cast_kernel<<<n8_wq / 256, 256>>>(Wq, wq16, n8_wq);
    cast_kernel<<<n8_wk / 256, 256>>>(Wk, wk16, n8_wk);
    cast_kernel<<<n8_wk / 256, 256>>>(Wv, wv16, n8_wk);
    cast_kernel<<<n8_wo / 256, 256>>>(Wo, wo16, n8_wo);

    // fused QKV projection (plain fp16)
    gemm_qkv<<<dim3(48, S_ / GBM), 256, GEMM_SMEM>>>(
        x16, wq16, wk16, wv16, bq, bk, bv, qp, kp, vp);

    // LayerNorm + RoPE -> plain fp16 (one block per token-head)
    ln_rope_h<<<dim3(S_, NH_), HD_>>>(qp, q16, qng, qnb, NH_);
    ln_rope_h<<<dim3(S_, NKV_), HD_>>>(kp, k16, kng, knb, NKV_);
    // V -> plain fp16
    cast_kernel<<<n8_v / 256, 256>>>(vp, v16, n8_v);

    // flash attention on tensor cores -> plain fp16 output
    flash_mma<<<dim3(S_ / FBR, NH_), 256, FSMEM>>>(q16, k16, v16, ao16);

    // output projection (plain fp16)
    gemm_f16_pipe<<<dim3(HID_ / GBN, S_ / GBM), 256, GEMM_SMEM>>>(
        S_, HID_, HID_, ao16, wo16, bo, out);
}

// round 16
// speedup vs baseline: 7.6893x; 1.2184x over previous
#include <cuda_runtime.h>
#include <cuda_fp16.h>
#include <math.h>
#include <cstdint>

// Problem constants
#define S_    2048
#define HID_  4096
#define NH_   32
#define NKV_  8
#define HD_   128
#define EPS_  1e-5f
#define SCALE_ 0.088388347648318447f
#define SC2_  (SCALE_ * 1.4426950408889634f)
#define LOG2_THETA 18.931568569324174f

// ---------------------------------------------------------------------------
// Scratch (device globals; no allocation allowed)
// ---------------------------------------------------------------------------
__device__ float g_q[S_ * NH_ * HD_];
__device__ float g_k[S_ * NKV_ * HD_];
__device__ __half g_x16[S_ * HID_];
__device__ __half g_wq16[NH_ * HD_ * HID_];
__device__ __half g_wk16[NKV_ * HD_ * HID_];
__device__ __half g_wv16[NKV_ * HD_ * HID_];
__device__ __half g_wo16[HID_ * HID_];
__device__ __half g_ao16[S_ * HID_];
__device__ __half g_q16[S_ * NH_ * HD_];
__device__ __half g_k16[S_ * NKV_ * HD_];
__device__ __half g_v16[S_ * NKV_ * HD_];

// ---------------------------------------------------------------------------
// Helpers
// ---------------------------------------------------------------------------
__device__ __forceinline__ uint32_t smem_u32(const void* p) {
    uint32_t a;
    asm("{ .reg .u64 t; cvta.to.shared.u64 t, %1; cvt.u32.u64 %0, t; }"
        : "=r"(a) : "l"(p));
    return a;
}

__device__ __forceinline__ void ldsm4(uint32_t* r, uint32_t addr) {
    asm volatile("ldmatrix.sync.aligned.m8n8.x4.shared.b16 {%0,%1,%2,%3}, [%4];"
                 : "=r"(r[0]), "=r"(r[1]), "=r"(r[2]), "=r"(r[3]) : "r"(addr));
}

__device__ __forceinline__ void ldsm4t(uint32_t* r, uint32_t addr) {
    asm volatile("ldmatrix.sync.aligned.m8n8.x4.trans.shared.b16 {%0,%1,%2,%3}, [%4];"
                 : "=r"(r[0]), "=r"(r[1]), "=r"(r[2]), "=r"(r[3]) : "r"(addr));
}

__device__ __forceinline__ void mma_f16(float* d, const uint32_t* a, const uint32_t* b) {
    asm volatile(
        "mma.sync.aligned.m16n8k16.row.col.f32.f16.f16.f32 "
        "{%0,%1,%2,%3}, {%4,%5,%6,%7}, {%8,%9}, {%0,%1,%2,%3};"
        : "+f"(d[0]), "+f"(d[1]), "+f"(d[2]), "+f"(d[3])
        : "r"(a[0]), "r"(a[1]), "r"(a[2]), "r"(a[3]), "r"(b[0]), "r"(b[1]));
}

__device__ __forceinline__ void cpa16(uint32_t dst, const void* src) {
    asm volatile("cp.async.cg.shared.global [%0], [%1], 16;" :: "r"(dst), "l"(src));
}

__device__ __forceinline__ uint32_t pkh(__half a, __half b) {
    __half2 t = __halves2half2(a, b);
    return *reinterpret_cast<uint32_t*>(&t);
}

__device__ __forceinline__ uint2 cast4_h(float4 v) {
    uint2 r;
    r.x = pkh(__float2half_rn(v.x), __float2half_rn(v.y));
    r.y = pkh(__float2half_rn(v.z), __float2half_rn(v.w));
    return r;
}

// ---------------------------------------------------------------------------
// fp32 -> fp16 cast, 64 bytes out per thread (4 independent LDG.128)
// ---------------------------------------------------------------------------
__global__ __launch_bounds__(256)
void cast_kernel(const float* __restrict__ in, __half* __restrict__ out, int n16)
{
    const int idx = blockIdx.x * 256 + threadIdx.x;
    if (idx >= n16) return;
    const float4* p = (const float4*)in + 4 * (size_t)idx;
    float4 a = p[0];
    float4 b = p[1];
    float4 c = p[2];
    float4 d = p[3];
    uint2 ra = cast4_h(a), rb = cast4_h(b), rc = cast4_h(c), rd = cast4_h(d);
    uint4* q = (uint4*)out + 2 * (size_t)idx;
    uint4 o0, o1;
    o0.x = ra.x; o0.y = ra.y; o0.z = rb.x; o0.w = rb.y;
    o1.x = rc.x; o1.y = rc.y; o1.z = rd.x; o1.w = rd.y;
    q[0] = o0;
    q[1] = o1;
}

// ---------------------------------------------------------------------------
// Plain fp16 GEMM — warp tile 64x64 probe.
// CTA 128x128, BK=32, 128 threads (4 warps 2x2), 2 CTAs/SM, 5-stage cp.async.
// Stage: A(8K) B(8K) = 16KB; rows 64B, swizzle chunk ^= (row&3).
// Epilogue writes fp32 (C) or fp16 (C16), one of which is null.
// ---------------------------------------------------------------------------
#define GBM 128
#define GBN 128
#define GBK 32
#define OFF_B  8192
#define BUF_B  16384
#define NSTAGE 5
#define GEMM_SMEM (NSTAGE * BUF_B)

__device__ __forceinline__ void issue_stage(
    uint32_t sdst,
    const __half* __restrict__ A, const __half* __restrict__ B,
    int K, int k0, int tid)
{
#pragma unroll
    for (int it = 0; it < 8; it++) {
        const int tile = it >> 2;                 // 0=A, 1=B
        const int sub = (it & 3) * 128 + tid;     // 0..511
        const int row = sub >> 2;                 // 0..127
        const int col = sub & 3;                  // 16B chunk within 64B row
        const uint32_t dst = sdst + tile * 8192 + row * 64
                           + (uint32_t)((col ^ (row & 3)) << 4);
        const __half* src = (tile == 0)
            ? A + (size_t)row * K + k0 + col * 8
            : B + (size_t)row * K + k0 + col * 8;
        cpa16(dst, src);
    }
}

__device__ __forceinline__ void gemm_body(
    const __half* __restrict__ Ab, const __half* __restrict__ Bb,
    const float* __restrict__ bias,
    float* __restrict__ C, __half* __restrict__ C16,
    int N, int K, int bm, int bn, char* smem)
{
    const uint32_t sbase = smem_u32(smem);
    const int tid = threadIdx.x;
    const int wid = tid >> 5;
    const int lane = tid & 31;
    const int warp_m = wid >> 1;      // 0..1
    const int warp_n = wid & 1;       // 0..1

    const int l7 = lane & 7;
    const int l3 = lane & 3;
    const int amat = lane >> 3;
    const uint32_t a_row64 = (uint32_t)(warp_m * 64 + ((amat & 1) << 3) + l7) * 64;
    const int a_kh = amat >> 1;
    const int b_kh = (lane >> 3) & 1;
    const uint32_t b_row64 = (uint32_t)(warp_n * 64 + ((lane >> 4) << 3) + l7) * 64;

    float acc[4][8][4];
#pragma unroll
    for (int i = 0; i < 4; i++)
#pragma unroll
        for (int j = 0; j < 8; j++)
#pragma unroll
            for (int c = 0; c < 4; c++) acc[i][j][c] = 0.f;

    const int NB = K / GBK;

    issue_stage(sbase, Ab, Bb, K, 0, tid);
    asm volatile("cp.async.commit_group;");
    issue_stage(sbase + BUF_B, Ab, Bb, K, GBK, tid);
    asm volatile("cp.async.commit_group;");
    issue_stage(sbase + 2 * BUF_B, Ab, Bb, K, 2 * GBK, tid);
    asm volatile("cp.async.commit_group;");
    issue_stage(sbase + 3 * BUF_B, Ab, Bb, K, 3 * GBK, tid);
    asm volatile("cp.async.commit_group;");

    for (int kb = 0; kb < NB; kb++) {
        asm volatile("cp.async.wait_group 3;");
        __syncthreads();

        const int nk = kb + 4;
        if (nk < NB)
            issue_stage(sbase + (uint32_t)(nk % NSTAGE) * BUF_B,
                        Ab, Bb, K, nk * GBK, tid);
        asm volatile("cp.async.commit_group;");

        const uint32_t bufc = sbase + (uint32_t)(kb % NSTAGE) * BUF_B;

#pragma unroll
        for (int ks = 0; ks < 2; ks++) {
            const uint32_t a_swoff = (uint32_t)(((ks * 2 + a_kh) ^ l3) << 4);
            const uint32_t b_swoff = (uint32_t)(((ks * 2 + b_kh) ^ l3) << 4);

            uint32_t ah[4][4];
#pragma unroll
            for (int mt = 0; mt < 4; mt++)
                ldsm4(ah[mt], bufc + a_row64 + (uint32_t)mt * 1024 + a_swoff);

            uint32_t bh[4][4];
#pragma unroll
            for (int p = 0; p < 4; p++)
                ldsm4(bh[p], bufc + OFF_B + b_row64 + (uint32_t)p * 1024 + b_swoff);

#pragma unroll
            for (int mt = 0; mt < 4; mt++)
#pragma unroll
                for (int nt = 0; nt < 8; nt++)
                    mma_f16(acc[mt][nt], ah[mt], &bh[nt >> 1][(nt & 1) * 2]);
        }
    }

    const int g = lane >> 2;
    const int t = lane & 3;
#pragma unroll
    for (int nt = 0; nt < 8; nt++) {
        const int col = bn + warp_n * 64 + nt * 8 + 2 * t;
        const float b0 = bias[col];
        const float b1 = bias[col + 1];
#pragma unroll
        for (int mt = 0; mt < 4; mt++) {
            const int row = bm + warp_m * 64 + mt * 16 + g;
            const float v00 = acc[mt][nt][0] + b0;
            const float v01 = acc[mt][nt][1] + b1;
            const float v10 = acc[mt][nt][2] + b0;
            const float v11 = acc[mt][nt][3] + b1;
            if (C16) {
                *(uint32_t*)(C16 + (size_t)row * N + col) =
                    pkh(__float2half_rn(v00), __float2half_rn(v01));
                *(uint32_t*)(C16 + (size_t)(row + 8) * N + col) =
                    pkh(__float2half_rn(v10), __float2half_rn(v11));
            } else {
                float2 v0, v1;
                v0.x = v00; v0.y = v01;
                v1.x = v10; v1.y = v11;
                *(float2*)(C + (size_t)row * N + col) = v0;
                *(float2*)(C + (size_t)(row + 8) * N + col) = v1;
            }
        }
    }
}

// Fused Q/K/V projection: grid.x in [0,48): [0,32)->Q, [32,40)->K, [40,48)->V
// V is written directly as fp16 (no LayerNorm on V).
__global__ __launch_bounds__(128, 2)
void gemm_qkv(const __half* __restrict__ x16,
              const __half* __restrict__ wq, const __half* __restrict__ wk,
              const __half* __restrict__ wv,
              const float* __restrict__ bq, const float* __restrict__ bk,
              const float* __restrict__ bv,
              float* __restrict__ q, float* __restrict__ k,
              __half* __restrict__ v16)
{
    extern __shared__ __align__(1024) char smem[];
    const int bx = blockIdx.x;
    const int bm = blockIdx.y * GBM;

    const __half* Bh;
    const float* bias;
    float* C = nullptr;
    __half* C16 = nullptr;
    int N, bn;
    if (bx < 32) {
        Bh = wq; bias = bq; C = q; N = NH_ * HD_; bn = bx * GBN;
    } else if (bx < 40) {
        Bh = wk; bias = bk; C = k; N = NKV_ * HD_; bn = (bx - 32) * GBN;
    } else {
        Bh = wv; bias = bv; C16 = v16; N = NKV_ * HD_; bn = (bx - 40) * GBN;
    }

    gemm_body(x16 + (size_t)bm * HID_, Bh + (size_t)bn * HID_,
              bias, C, C16, N, HID_, bm, bn, smem);
}

__global__ __launch_bounds__(128, 2)
void gemm_f16_pipe(int M, int N, int K,
                   const __half* __restrict__ A16,
                   const __half* __restrict__ B16,
                   const float* __restrict__ bias,
                   float* __restrict__ C)
{
    extern __shared__ __align__(1024) char smem[];
    const int bm = blockIdx.y * GBM;
    const int bn = blockIdx.x * GBN;
    gemm_body(A16 + (size_t)bm * K, B16 + (size_t)bn * K,
              bias, C, nullptr, N, K, bm, bn, smem);
}

// ---------------------------------------------------------------------------
// Fused per-head LayerNorm + RoPE; one block per (token, head).
// ---------------------------------------------------------------------------
__global__ __launch_bounds__(128)
void ln_rope_h(const float* __restrict__ in,
               __half* __restrict__ oh,
               const float* __restrict__ gw,
               const float* __restrict__ bw,
               int H)
{
    const int s = blockIdx.x;
    const int h = blockIdx.y;
    const int d = threadIdx.x;
    __shared__ float red[8];
    __shared__ float xs[HD_];

    const int dd = d & 63;
    const float inv = exp2f(-(float)dd * (LOG2_THETA / 64.0f));
    const float th = (float)s * inv;
    float sn, cs;
    sincosf(th, &sn, &cs);

    const int lane = d & 31;
    const int w = d >> 5;

    const float v = in[((size_t)s * H + h) * HD_ + d];
    float s1 = v, s2 = v * v;
#pragma unroll
    for (int off = 16; off > 0; off >>= 1) {
        s1 += __shfl_xor_sync(0xffffffffu, s1, off);
        s2 += __shfl_xor_sync(0xffffffffu, s2, off);
    }
    if (lane == 0) { red[w] = s1; red[4 + w] = s2; }
    __syncthreads();
    const float sum = red[0] + red[1] + red[2] + red[3];
    const float sq  = red[4] + red[5] + red[6] + red[7];
    const float mu  = sum * (1.0f / HD_);
    const float var = sq * (1.0f / HD_) - mu * mu;
    const float r   = rsqrtf(var + EPS_);
    const float xn  = (v - mu) * r * gw[d] + bw[d];
    xs[d] = xn;
    __syncthreads();
    const float other = (d < 64) ? -xs[d + 64] : xs[d - 64];
    oh[((size_t)s * H + h) * HD_ + d] = __float2half_rn(xn * cs + other * sn);
}

// ---------------------------------------------------------------------------
// Flash attention on mma.sync fp16 (unchanged from R15 — passing).
// BR=128 (8 warps x m16), BC=64, 256 threads.
// QK 1 term; PV 1 term. SMEM: Q 32KB + 2 KV buffers of [K|V] = 96KB.
// ---------------------------------------------------------------------------
#define FBR 128
#define FBC 64
#define FQ_CH 8192
#define FKV_CH 4096
#define FKV_TILE 16384
#define FBUF 32768
#define FSMEM (32768 + 2 * FBUF)

__device__ __forceinline__ void kv_stage(
    uint32_t dstbase,
    const __half* __restrict__ Kp, const __half* __restrict__ Vp,
    int kvh, int k0, int tid)
{
#pragma unroll
    for (int it = 0; it < 8; it++) {
        const int idx = it * 256 + tid;
        const int tile = idx >> 10;             // 0=K, 1=V
        const int sub = idx & 1023;
        const int row = sub >> 4;               // 0..63
        const int u8 = sub & 15;
        const __half* base = (tile == 0) ? Kp : Vp;
        const __half* src = base + ((size_t)(k0 + row) * NKV_ + kvh) * HD_ + u8 * 8;
        const uint32_t dst = dstbase + tile * FKV_TILE + (u8 >> 2) * FKV_CH
                           + row * 64 + (uint32_t)(((u8 & 3) ^ (row & 3)) << 4);
        cpa16(dst, src);
    }
}

__global__ __launch_bounds__(256, 1)
void flash_mma(const __half* __restrict__ Q16,
               const __half* __restrict__ K16,
               const __half* __restrict__ V16,
               __half* __restrict__ O16)
{
    extern __shared__ __align__(1024) char smem[];
    const uint32_t sbase = smem_u32(smem);
    const int qb = (int)gridDim.x - 1 - (int)blockIdx.x;   // big tiles first
    const int h = blockIdx.y;
    const int kvh = h >> 2;
    const int q0 = qb * FBR;
    const int tid = threadIdx.x;
    const int w = tid >> 5;
    const int lane = tid & 31;

#pragma unroll
    for (int it = 0; it < 8; it++) {
        const int idx = it * 256 + tid;
        const int row = idx >> 4;
        const int u8 = idx & 15;
        const __half* src = Q16 + ((size_t)(q0 + row) * NH_ + h) * HD_ + u8 * 8;
        const uint32_t dst = sbase + (u8 >> 2) * FQ_CH + row * 64
                           + (uint32_t)(((u8 & 3) ^ (row & 3)) << 4);
        cpa16(dst, src);
    }
    kv_stage(sbase + 32768, K16, V16, kvh, 0, tid);
    asm volatile("cp.async.commit_group;");

    float o[16][4];
#pragma unroll
    for (int i = 0; i < 16; i++)
#pragma unroll
        for (int c = 0; c < 4; c++) o[i][c] = 0.f;
    float m0 = -1e30f, m1 = -1e30f, l0 = 0.f, l1 = 0.f;

    const int l7 = lane & 7;
    const int qrow = w * 16 + ((lane >> 3) & 1) * 8 + l7;
    const int qm2 = lane >> 4;
    const int krow_base = ((lane >> 4) << 3) + l7;
    const int kh_sel = (lane >> 3) & 1;
    const int vrow_base = ((lane >> 3) & 1) * 8 + l7;
    const int vm2 = lane >> 4;

    const int nb = 2 * qb + 2;
    for (int kb = 0; kb < nb; kb++) {
        if (kb + 1 < nb)
            kv_stage(sbase + 32768 + ((kb + 1) & 1) * FBUF,
                     K16, V16, kvh, (kb + 1) * FBC, tid);
        asm volatile("cp.async.commit_group;");
        asm volatile("cp.async.wait_group 1;");
        __syncthreads();

        const uint32_t B = sbase + 32768 + (uint32_t)(kb & 1) * FBUF;

        float sc[8][4];
#pragma unroll
        for (int i = 0; i < 8; i++)
#pragma unroll
            for (int c = 0; c < 4; c++) sc[i][c] = 0.f;

#pragma unroll
        for (int kd = 0; kd < 8; kd++) {
            uint32_t qa[4];
            {
                const int u8 = kd * 2 + qm2;
                ldsm4(qa, sbase + (u8 >> 2) * FQ_CH + qrow * 64
                          + (uint32_t)(((u8 & 3) ^ (qrow & 3)) << 4));
            }
            const int u8k = kd * 2 + kh_sel;
#pragma unroll
            for (int j = 0; j < 4; j++) {
                const int krow = j * 16 + krow_base;
                const uint32_t koff = (u8k >> 2) * FKV_CH + krow * 64
                                    + (uint32_t)(((u8k & 3) ^ (krow & 3)) << 4);
                uint32_t kb4[4];
                ldsm4(kb4, B + koff);
                mma_f16(sc[2 * j],     qa, &kb4[0]);
                mma_f16(sc[2 * j + 1], qa, &kb4[2]);
            }
        }

        const int row0 = q0 + w * 16 + (lane >> 2);
        const int col_base = kb * FBC + (lane & 3) * 2;
        const bool maybe_mask = (kb * FBC + FBC - 1) > (q0 + w * 16);
        float mx0 = -1e30f, mx1 = -1e30f;
#pragma unroll
        for (int nt = 0; nt < 8; nt++) {
            float v0 = sc[nt][0] * SC2_;
            float v1 = sc[nt][1] * SC2_;
            float v2 = sc[nt][2] * SC2_;
            float v3 = sc[nt][3] * SC2_;
            if (maybe_mask) {
                const int c0 = col_base + nt * 8;
                if (c0 > row0)         v0 = -1e30f;
                if (c0 + 1 > row0)     v1 = -1e30f;
                if (c0 > row0 + 8)     v2 = -1e30f;
                if (c0 + 1 > row0 + 8) v3 = -1e30f;
            }
            sc[nt][0] = v0; sc[nt][1] = v1; sc[nt][2] = v2; sc[nt][3] = v3;
            mx0 = fmaxf(mx0, fmaxf(v0, v1));
            mx1 = fmaxf(mx1, fmaxf(v2, v3));
        }
        mx0 = fmaxf(mx0, __shfl_xor_sync(0xffffffffu, mx0, 1));
        mx0 = fmaxf(mx0, __shfl_xor_sync(0xffffffffu, mx0, 2));
        mx1 = fmaxf(mx1, __shfl_xor_sync(0xffffffffu, mx1, 1));
        mx1 = fmaxf(mx1, __shfl_xor_sync(0xffffffffu, mx1, 2));
        const float mn0 = fmaxf(m0, mx0);
        const float mn1 = fmaxf(m1, mx1);
        const float al0 = exp2f(m0 - mn0);
        const float al1 = exp2f(m1 - mn1);
        m0 = mn0; m1 = mn1;

        uint32_t ph[8][2];
        float rs0 = 0.f, rs1 = 0.f;
#pragma unroll
        for (int nt = 0; nt < 8; nt++) {
            const float p0 = exp2f(sc[nt][0] - mn0);
            const float p1 = exp2f(sc[nt][1] - mn0);
            const float p2 = exp2f(sc[nt][2] - mn1);
            const float p3 = exp2f(sc[nt][3] - mn1);
            rs0 += p0 + p1; rs1 += p2 + p3;
            ph[nt][0] = pkh(__float2half_rn(p0), __float2half_rn(p1));
            ph[nt][1] = pkh(__float2half_rn(p2), __float2half_rn(p3));
        }
        rs0 += __shfl_xor_sync(0xffffffffu, rs0, 1);
        rs0 += __shfl_xor_sync(0xffffffffu, rs0, 2);
        rs1 += __shfl_xor_sync(0xffffffffu, rs1, 1);
        rs1 += __shfl_xor_sync(0xffffffffu, rs1, 2);
        l0 = l0 * al0 + rs0;
        l1 = l1 * al1 + rs1;
#pragma unroll
        for (int j = 0; j < 16; j++) {
            o[j][0] *= al0; o[j][1] *= al0;
            o[j][2] *= al1; o[j][3] *= al1;
        }

#pragma unroll
        for (int ks = 0; ks < 4; ks++) {
            uint32_t aph[4] = { ph[2 * ks][0], ph[2 * ks][1],
                                ph[2 * ks + 1][0], ph[2 * ks + 1][1] };
            const int vrow = ks * 16 + vrow_base;
#pragma unroll
            for (int j = 0; j < 8; j++) {
                const int u8 = 2 * j + vm2;
                const uint32_t voff = (u8 >> 2) * FKV_CH + vrow * 64
                                    + (uint32_t)(((u8 & 3) ^ (vrow & 3)) << 4);
                uint32_t vh4[4];
                ldsm4t(vh4, B + FKV_TILE + voff);
                mma_f16(o[2 * j],     aph, &vh4[0]);
                mma_f16(o[2 * j + 1], aph, &vh4[2]);
            }
        }
        __syncthreads();
    }

    const float inv0 = 1.f / l0;
    const float inv1 = 1.f / l1;
    const int r0 = q0 + w * 16 + (lane >> 2);
    const size_t base0 = ((size_t)r0 * NH_ + h) * HD_ + (lane & 3) * 2;
    const size_t base1 = ((size_t)(r0 + 8) * NH_ + h) * HD_ + (lane & 3) * 2;
#pragma unroll
    for (int nt = 0; nt < 16; nt++) {
        *(uint32_t*)(O16 + base0 + nt * 8) =
            pkh(__float2half_rn(o[nt][0] * inv0), __float2half_rn(o[nt][1] * inv0));
        *(uint32_t*)(O16 + base1 + nt * 8) =
            pkh(__float2half_rn(o[nt][2] * inv1), __float2half_rn(o[nt][3] * inv1));
    }
}

// ---------------------------------------------------------------------------
// Launch
// ---------------------------------------------------------------------------
extern "C" void kernel_launch(void* const* d_in, const int* in_sizes, int n_in,
                              void* d_out, int out_size)
{
    const float* x   = (const float*)d_in[0];
    const float* Wq  = (const float*)d_in[1];
    const float* bq  = (const float*)d_in[2];
    const float* Wk  = (const float*)d_in[3];
    const float* bk  = (const float*)d_in[4];
    const float* Wv  = (const float*)d_in[5];
    const float* bv  = (const float*)d_in[6];
    const float* Wo  = (const float*)d_in[7];
    const float* bo  = (const float*)d_in[8];
    const float* qng = (const float*)d_in[9];
    const float* qnb = (const float*)d_in[10];
    const float* kng = (const float*)d_in[11];
    const float* knb = (const float*)d_in[12];
    float* out = (float*)d_out;

    float *qp, *kp;
    __half *x16, *wq16, *wk16, *wv16, *wo16, *ao16;
    __half *q16, *k16, *v16;
    cudaGetSymbolAddress((void**)&qp, g_q);
    cudaGetSymbolAddress((void**)&kp, g_k);
    cudaGetSymbolAddress((void**)&x16, g_x16);
    cudaGetSymbolAddress((void**)&wq16, g_wq16);
    cudaGetSymbolAddress((void**)&wk16, g_wk16);
    cudaGetSymbolAddress((void**)&wv16, g_wv16);
    cudaGetSymbolAddress((void**)&wo16, g_wo16);
    cudaGetSymbolAddress((void**)&ao16, g_ao16);
    cudaGetSymbolAddress((void**)&q16, g_q16);
    cudaGetSymbolAddress((void**)&k16, g_k16);
    cudaGetSymbolAddress((void**)&v16, g_v16);

    cudaFuncSetAttribute(gemm_qkv, cudaFuncAttributeMaxDynamicSharedMemorySize,
                         GEMM_SMEM);
    cudaFuncSetAttribute(gemm_f16_pipe, cudaFuncAttributeMaxDynamicSharedMemorySize,
                         GEMM_SMEM);
    cudaFuncSetAttribute(flash_mma, cudaFuncAttributeMaxDynamicSharedMemorySize,
                         FSMEM);

    const int n16_x  = S_ * HID_ / 16;
    const int n16_wq = NH_ * HD_ * HID_ / 16;
    const int n16_wk = NKV_ * HD_ * HID_ / 16;
    const int n16_wo = HID_ * HID_ / 16;
    cast_kernel<<<n16_x / 256, 256>>>(x, x16, n16_x);
    cast_kernel<<<n16_wq / 256, 256>>>(Wq, wq16, n16_wq);
    cast_kernel<<<n16_wk / 256, 256>>>(Wk, wk16, n16_wk);
    cast_kernel<<<n16_wk / 256, 256>>>(Wv, wv16, n16_wk);
    cast_kernel<<<n16_wo / 256, 256>>>(Wo, wo16, n16_wo);

    // fused QKV projection (plain fp16); V written directly as fp16
    gemm_qkv<<<dim3(48, S_ / GBM), 128, GEMM_SMEM>>>(
        x16, wq16, wk16, wv16, bq, bk, bv, qp, kp, v16);

    // LayerNorm + RoPE -> plain fp16 (one block per token-head)
    ln_rope_h<<<dim3(S_, NH_), HD_>>>(qp, q16, qng, qnb, NH_);
    ln_rope_h<<<dim3(S_, NKV_), HD_>>>(kp, k16, kng, knb, NKV_);

    // flash attention on tensor cores -> plain fp16 output
    flash_mma<<<dim3(S_ / FBR, NH_), 256, FSMEM>>>(q16, k16, v16, ao16);

    // output projection (plain fp16)
    gemm_f16_pipe<<<dim3(HID_ / GBN, S_ / GBM), 256 / 2, GEMM_SMEM>>>(
        S_, HID_, HID_, ao16, wo16, bo, out);
}

// round 17
// speedup vs baseline: 7.7953x; 1.0138x over previous
#include <cuda_runtime.h>
#include <cuda_fp16.h>
#include <math.h>
#include <cstdint>

// Problem constants
#define S_    2048
#define HID_  4096
#define NH_   32
#define NKV_  8
#define HD_   128
#define EPS_  1e-5f
#define SCALE_ 0.088388347648318447f
#define SC2_  (SCALE_ * 1.4426950408889634f)
#define LOG2_THETA 18.931568569324174f

// ---------------------------------------------------------------------------
// Scratch (device globals; no allocation allowed)
// ---------------------------------------------------------------------------
__device__ float g_q[S_ * NH_ * HD_];
__device__ float g_k[S_ * NKV_ * HD_];
__device__ __half g_x16[S_ * HID_];
__device__ __half g_wq16[NH_ * HD_ * HID_];
__device__ __half g_wk16[NKV_ * HD_ * HID_];
__device__ __half g_wv16[NKV_ * HD_ * HID_];
__device__ __half g_wo16[HID_ * HID_];
__device__ __half g_ao16[S_ * HID_];
__device__ __half g_q16[S_ * NH_ * HD_];
__device__ __half g_k16[S_ * NKV_ * HD_];
__device__ __half g_v16[S_ * NKV_ * HD_];

// ---------------------------------------------------------------------------
// Helpers
// ---------------------------------------------------------------------------
__device__ __forceinline__ uint32_t smem_u32(const void* p) {
    uint32_t a;
    asm("{ .reg .u64 t; cvta.to.shared.u64 t, %1; cvt.u32.u64 %0, t; }"
        : "=r"(a) : "l"(p));
    return a;
}

__device__ __forceinline__ void ldsm4(uint32_t* r, uint32_t addr) {
    asm volatile("ldmatrix.sync.aligned.m8n8.x4.shared.b16 {%0,%1,%2,%3}, [%4];"
                 : "=r"(r[0]), "=r"(r[1]), "=r"(r[2]), "=r"(r[3]) : "r"(addr));
}

__device__ __forceinline__ void ldsm4t(uint32_t* r, uint32_t addr) {
    asm volatile("ldmatrix.sync.aligned.m8n8.x4.trans.shared.b16 {%0,%1,%2,%3}, [%4];"
                 : "=r"(r[0]), "=r"(r[1]), "=r"(r[2]), "=r"(r[3]) : "r"(addr));
}

__device__ __forceinline__ void mma_f16(float* d, const uint32_t* a, const uint32_t* b) {
    asm volatile(
        "mma.sync.aligned.m16n8k16.row.col.f32.f16.f16.f32 "
        "{%0,%1,%2,%3}, {%4,%5,%6,%7}, {%8,%9}, {%0,%1,%2,%3};"
        : "+f"(d[0]), "+f"(d[1]), "+f"(d[2]), "+f"(d[3])
        : "r"(a[0]), "r"(a[1]), "r"(a[2]), "r"(a[3]), "r"(b[0]), "r"(b[1]));
}

__device__ __forceinline__ void cpa16(uint32_t dst, const void* src) {
    asm volatile("cp.async.cg.shared.global [%0], [%1], 16;" :: "r"(dst), "l"(src));
}

__device__ __forceinline__ uint32_t pkh(__half a, __half b) {
    __half2 t = __halves2half2(a, b);
    return *reinterpret_cast<uint32_t*>(&t);
}

__device__ __forceinline__ uint2 cast4_h(float4 v) {
    uint2 r;
    r.x = pkh(__float2half_rn(v.x), __float2half_rn(v.y));
    r.y = pkh(__float2half_rn(v.z), __float2half_rn(v.w));
    return r;
}

// ---------------------------------------------------------------------------
// fp32 -> fp16 cast, 64 bytes out per thread (4 independent LDG.128)
// ---------------------------------------------------------------------------
__global__ __launch_bounds__(256)
void cast_kernel(const float* __restrict__ in, __half* __restrict__ out, int n16)
{
    const int idx = blockIdx.x * 256 + threadIdx.x;
    if (idx >= n16) return;
    const float4* p = (const float4*)in + 4 * (size_t)idx;
    float4 a = p[0];
    float4 b = p[1];
    float4 c = p[2];
    float4 d = p[3];
    uint2 ra = cast4_h(a), rb = cast4_h(b), rc = cast4_h(c), rd = cast4_h(d);
    uint4* q = (uint4*)out + 2 * (size_t)idx;
    uint4 o0, o1;
    o0.x = ra.x; o0.y = ra.y; o0.z = rb.x; o0.w = rb.y;
    o1.x = rc.x; o1.y = rc.y; o1.z = rd.x; o1.w = rd.y;
    q[0] = o0;
    q[1] = o1;
}

// ---------------------------------------------------------------------------
// Plain fp16 GEMM — warp tile 64x64 (unchanged from R16, passing).
// CTA 128x128, BK=32, 128 threads (4 warps 2x2), 2 CTAs/SM, 5-stage cp.async.
// ---------------------------------------------------------------------------
#define GBM 128
#define GBN 128
#define GBK 32
#define OFF_B  8192
#define BUF_B  16384
#define NSTAGE 5
#define GEMM_SMEM (NSTAGE * BUF_B)

__device__ __forceinline__ void issue_stage(
    uint32_t sdst,
    const __half* __restrict__ A, const __half* __restrict__ B,
    int K, int k0, int tid)
{
#pragma unroll
    for (int it = 0; it < 8; it++) {
        const int tile = it >> 2;
        const int sub = (it & 3) * 128 + tid;
        const int row = sub >> 2;
        const int col = sub & 3;
        const uint32_t dst = sdst + tile * 8192 + row * 64
                           + (uint32_t)((col ^ (row & 3)) << 4);
        const __half* src = (tile == 0)
            ? A + (size_t)row * K + k0 + col * 8
            : B + (size_t)row * K + k0 + col * 8;
        cpa16(dst, src);
    }
}

__device__ __forceinline__ void gemm_body(
    const __half* __restrict__ Ab, const __half* __restrict__ Bb,
    const float* __restrict__ bias,
    float* __restrict__ C, __half* __restrict__ C16,
    int N, int K, int bm, int bn, char* smem)
{
    const uint32_t sbase = smem_u32(smem);
    const int tid = threadIdx.x;
    const int wid = tid >> 5;
    const int lane = tid & 31;
    const int warp_m = wid >> 1;
    const int warp_n = wid & 1;

    const int l7 = lane & 7;
    const int l3 = lane & 3;
    const int amat = lane >> 3;
    const uint32_t a_row64 = (uint32_t)(warp_m * 64 + ((amat & 1) << 3) + l7) * 64;
    const int a_kh = amat >> 1;
    const int b_kh = (lane >> 3) & 1;
    const uint32_t b_row64 = (uint32_t)(warp_n * 64 + ((lane >> 4) << 3) + l7) * 64;

    float acc[4][8][4];
#pragma unroll
    for (int i = 0; i < 4; i++)
#pragma unroll
        for (int j = 0; j < 8; j++)
#pragma unroll
            for (int c = 0; c < 4; c++) acc[i][j][c] = 0.f;

    const int NB = K / GBK;

    issue_stage(sbase, Ab, Bb, K, 0, tid);
    asm volatile("cp.async.commit_group;");
    issue_stage(sbase + BUF_B, Ab, Bb, K, GBK, tid);
    asm volatile("cp.async.commit_group;");
    issue_stage(sbase + 2 * BUF_B, Ab, Bb, K, 2 * GBK, tid);
    asm volatile("cp.async.commit_group;");
    issue_stage(sbase + 3 * BUF_B, Ab, Bb, K, 3 * GBK, tid);
    asm volatile("cp.async.commit_group;");

    for (int kb = 0; kb < NB; kb++) {
        asm volatile("cp.async.wait_group 3;");
        __syncthreads();

        const int nk = kb + 4;
        if (nk < NB)
            issue_stage(sbase + (uint32_t)(nk % NSTAGE) * BUF_B,
                        Ab, Bb, K, nk * GBK, tid);
        asm volatile("cp.async.commit_group;");

        const uint32_t bufc = sbase + (uint32_t)(kb % NSTAGE) * BUF_B;

#pragma unroll
        for (int ks = 0; ks < 2; ks++) {
            const uint32_t a_swoff = (uint32_t)(((ks * 2 + a_kh) ^ l3) << 4);
            const uint32_t b_swoff = (uint32_t)(((ks * 2 + b_kh) ^ l3) << 4);

            uint32_t ah[4][4];
#pragma unroll
            for (int mt = 0; mt < 4; mt++)
                ldsm4(ah[mt], bufc + a_row64 + (uint32_t)mt * 1024 + a_swoff);

            uint32_t bh[4][4];
#pragma unroll
            for (int p = 0; p < 4; p++)
                ldsm4(bh[p], bufc + OFF_B + b_row64 + (uint32_t)p * 1024 + b_swoff);

#pragma unroll
            for (int mt = 0; mt < 4; mt++)
#pragma unroll
                for (int nt = 0; nt < 8; nt++)
                    mma_f16(acc[mt][nt], ah[mt], &bh[nt >> 1][(nt & 1) * 2]);
        }
    }

    const int g = lane >> 2;
    const int t = lane & 3;
#pragma unroll
    for (int nt = 0; nt < 8; nt++) {
        const int col = bn + warp_n * 64 + nt * 8 + 2 * t;
        const float b0 = bias[col];
        const float b1 = bias[col + 1];
#pragma unroll
        for (int mt = 0; mt < 4; mt++) {
            const int row = bm + warp_m * 64 + mt * 16 + g;
            const float v00 = acc[mt][nt][0] + b0;
            const float v01 = acc[mt][nt][1] + b1;
            const float v10 = acc[mt][nt][2] + b0;
            const float v11 = acc[mt][nt][3] + b1;
            if (C16) {
                *(uint32_t*)(C16 + (size_t)row * N + col) =
                    pkh(__float2half_rn(v00), __float2half_rn(v01));
                *(uint32_t*)(C16 + (size_t)(row + 8) * N + col) =
                    pkh(__float2half_rn(v10), __float2half_rn(v11));
            } else {
                float2 v0, v1;
                v0.x = v00; v0.y = v01;
                v1.x = v10; v1.y = v11;
                *(float2*)(C + (size_t)row * N + col) = v0;
                *(float2*)(C + (size_t)(row + 8) * N + col) = v1;
            }
        }
    }
}

__global__ __launch_bounds__(128, 2)
void gemm_qkv(const __half* __restrict__ x16,
              const __half* __restrict__ wq, const __half* __restrict__ wk,
              const __half* __restrict__ wv,
              const float* __restrict__ bq, const float* __restrict__ bk,
              const float* __restrict__ bv,
              float* __restrict__ q, float* __restrict__ k,
              __half* __restrict__ v16)
{
    extern __shared__ __align__(1024) char smem[];
    const int bx = blockIdx.x;
    const int bm = blockIdx.y * GBM;

    const __half* Bh;
    const float* bias;
    float* C = nullptr;
    __half* C16 = nullptr;
    int N, bn;
    if (bx < 32) {
        Bh = wq; bias = bq; C = q; N = NH_ * HD_; bn = bx * GBN;
    } else if (bx < 40) {
        Bh = wk; bias = bk; C = k; N = NKV_ * HD_; bn = (bx - 32) * GBN;
    } else {
        Bh = wv; bias = bv; C16 = v16; N = NKV_ * HD_; bn = (bx - 40) * GBN;
    }

    gemm_body(x16 + (size_t)bm * HID_, Bh + (size_t)bn * HID_,
              bias, C, C16, N, HID_, bm, bn, smem);
}

__global__ __launch_bounds__(128, 2)
void gemm_f16_pipe(int M, int N, int K,
                   const __half* __restrict__ A16,
                   const __half* __restrict__ B16,
                   const float* __restrict__ bias,
                   float* __restrict__ C)
{
    extern __shared__ __align__(1024) char smem[];
    const int bm = blockIdx.y * GBM;
    const int bn = blockIdx.x * GBN;
    gemm_body(A16 + (size_t)bm * K, B16 + (size_t)bn * K,
              bias, C, nullptr, N, K, bm, bn, smem);
}

// ---------------------------------------------------------------------------
// Fused per-head LayerNorm + RoPE; one block per (token, head).
// ---------------------------------------------------------------------------
__global__ __launch_bounds__(128)
void ln_rope_h(const float* __restrict__ in,
               __half* __restrict__ oh,
               const float* __restrict__ gw,
               const float* __restrict__ bw,
               int H)
{
    const int s = blockIdx.x;
    const int h = blockIdx.y;
    const int d = threadIdx.x;
    __shared__ float red[8];
    __shared__ float xs[HD_];

    const int dd = d & 63;
    const float inv = exp2f(-(float)dd * (LOG2_THETA / 64.0f));
    const float th = (float)s * inv;
    float sn, cs;
    sincosf(th, &sn, &cs);

    const int lane = d & 31;
    const int w = d >> 5;

    const float v = in[((size_t)s * H + h) * HD_ + d];
    float s1 = v, s2 = v * v;
#pragma unroll
    for (int off = 16; off > 0; off >>= 1) {
        s1 += __shfl_xor_sync(0xffffffffu, s1, off);
        s2 += __shfl_xor_sync(0xffffffffu, s2, off);
    }
    if (lane == 0) { red[w] = s1; red[4 + w] = s2; }
    __syncthreads();
    const float sum = red[0] + red[1] + red[2] + red[3];
    const float sq  = red[4] + red[5] + red[6] + red[7];
    const float mu  = sum * (1.0f / HD_);
    const float var = sq * (1.0f / HD_) - mu * mu;
    const float r   = rsqrtf(var + EPS_);
    const float xn  = (v - mu) * r * gw[d] + bw[d];
    xs[d] = xn;
    __syncthreads();
    const float other = (d < 64) ? -xs[d + 64] : xs[d - 64];
    oh[((size_t)s * H + h) * HD_ + d] = __float2half_rn(xn * cs + other * sn);
}

// ---------------------------------------------------------------------------
// Flash attention on mma.sync fp16 — BR=256: 8 warps x 32 Q-rows (2 m16 tiles),
// K/V fragments loaded once per warp and reused across both m-tiles.
// QK 1 term; PV 1 term. SMEM: Q 64KB + 2 KV buffers of [K|V] 32KB = 128KB.
// ---------------------------------------------------------------------------
#define FBR 256
#define FBC 64
#define FQ_CH 16384
#define FKV_CH 4096
#define FKV_TILE 16384
#define FBUF 32768
#define FQ_BYTES 65536
#define FSMEM (FQ_BYTES + 2 * FBUF)

__device__ __forceinline__ void kv_stage(
    uint32_t dstbase,
    const __half* __restrict__ Kp, const __half* __restrict__ Vp,
    int kvh, int k0, int tid)
{
#pragma unroll
    for (int it = 0; it < 8; it++) {
        const int idx = it * 256 + tid;
        const int tile = idx >> 10;             // 0=K, 1=V
        const int sub = idx & 1023;
        const int row = sub >> 4;               // 0..63
        const int u8 = sub & 15;
        const __half* base = (tile == 0) ? Kp : Vp;
        const __half* src = base + ((size_t)(k0 + row) * NKV_ + kvh) * HD_ + u8 * 8;
        const uint32_t dst = dstbase + tile * FKV_TILE + (u8 >> 2) * FKV_CH
                           + row * 64 + (uint32_t)(((u8 & 3) ^ (row & 3)) << 4);
        cpa16(dst, src);
    }
}

__global__ __launch_bounds__(256)
void flash_mma(const __half* __restrict__ Q16,
               const __half* __restrict__ K16,
               const __half* __restrict__ V16,
               __half* __restrict__ O16)
{
    extern __shared__ __align__(1024) char smem[];
    const uint32_t sbase = smem_u32(smem);
    const int qb = (int)gridDim.x - 1 - (int)blockIdx.x;   // big tiles first
    const int h = blockIdx.y;
    const int kvh = h >> 2;
    const int q0 = qb * FBR;
    const int tid = threadIdx.x;
    const int w = tid >> 5;
    const int lane = tid & 31;

    // prologue: Q (256 rows) + KV block 0
#pragma unroll
    for (int it = 0; it < 16; it++) {
        const int idx = it * 256 + tid;
        const int row = idx >> 4;
        const int u8 = idx & 15;
        const __half* src = Q16 + ((size_t)(q0 + row) * NH_ + h) * HD_ + u8 * 8;
        const uint32_t dst = sbase + (u8 >> 2) * FQ_CH + row * 64
                           + (uint32_t)(((u8 & 3) ^ (row & 3)) << 4);
        cpa16(dst, src);
    }
    kv_stage(sbase + FQ_BYTES, K16, V16, kvh, 0, tid);
    asm volatile("cp.async.commit_group;");

    float o[2][16][4];
#pragma unroll
    for (int mt = 0; mt < 2; mt++)
#pragma unroll
        for (int i = 0; i < 16; i++)
#pragma unroll
            for (int c = 0; c < 4; c++) o[mt][i][c] = 0.f;
    float m[2][2], l[2][2];
#pragma unroll
    for (int mt = 0; mt < 2; mt++) {
        m[mt][0] = -1e30f; m[mt][1] = -1e30f;
        l[mt][0] = 0.f;    l[mt][1] = 0.f;
    }

    const int l7 = lane & 7;
    const int qrow_b = w * 32 + ((lane >> 3) & 1) * 8 + l7;   // + mt*16
    const int qm2 = lane >> 4;
    const int krow_base = ((lane >> 4) << 3) + l7;
    const int kh_sel = (lane >> 3) & 1;
    const int vrow_base = ((lane >> 3) & 1) * 8 + l7;
    const int vm2 = lane >> 4;

    const int nb = 4 * qb + 4;
    for (int kb = 0; kb < nb; kb++) {
        if (kb + 1 < nb)
            kv_stage(sbase + FQ_BYTES + ((kb + 1) & 1) * FBUF,
                     K16, V16, kvh, (kb + 1) * FBC, tid);
        asm volatile("cp.async.commit_group;");
        asm volatile("cp.async.wait_group 1;");
        __syncthreads();

        const uint32_t B = sbase + FQ_BYTES + (uint32_t)(kb & 1) * FBUF;

        // ---- QK: sc[mt] = Q[mt] K^T, K fragments shared across m-tiles ----
        float sc[2][8][4];
#pragma unroll
        for (int mt = 0; mt < 2; mt++)
#pragma unroll
            for (int i = 0; i < 8; i++)
#pragma unroll
                for (int c = 0; c < 4; c++) sc[mt][i][c] = 0.f;

#pragma unroll
        for (int kd = 0; kd < 8; kd++) {
            uint32_t qa[2][4];
            const int u8 = kd * 2 + qm2;
#pragma unroll
            for (int mt = 0; mt < 2; mt++) {
                const int qr = qrow_b + mt * 16;
                ldsm4(qa[mt], sbase + (u8 >> 2) * FQ_CH + qr * 64
                              + (uint32_t)(((u8 & 3) ^ (qr & 3)) << 4));
            }
            const int u8k = kd * 2 + kh_sel;
#pragma unroll
            for (int j = 0; j < 4; j++) {
                const int krow = j * 16 + krow_base;
                const uint32_t koff = (u8k >> 2) * FKV_CH + krow * 64
                                    + (uint32_t)(((u8k & 3) ^ (krow & 3)) << 4);
                uint32_t kb4[4];
                ldsm4(kb4, B + koff);
                mma_f16(sc[0][2 * j],     qa[0], &kb4[0]);
                mma_f16(sc[0][2 * j + 1], qa[0], &kb4[2]);
                mma_f16(sc[1][2 * j],     qa[1], &kb4[0]);
                mma_f16(sc[1][2 * j + 1], qa[1], &kb4[2]);
            }
        }

        // ---- softmax per m-tile (exp2 domain) ----
        uint32_t ph[2][8][2];
#pragma unroll
        for (int mt = 0; mt < 2; mt++) {
            const int rbase = q0 + w * 32 + mt * 16;
            const int row0 = rbase + (lane >> 2);
            const int col_base = kb * FBC + (lane & 3) * 2;
            const bool maybe_mask = (kb * FBC + FBC - 1) > rbase;
            float mx0 = -1e30f, mx1 = -1e30f;
#pragma unroll
            for (int nt = 0; nt < 8; nt++) {
                float v0 = sc[mt][nt][0] * SC2_;
                float v1 = sc[mt][nt][1] * SC2_;
                float v2 = sc[mt][nt][2] * SC2_;
                float v3 = sc[mt][nt][3] * SC2_;
                if (maybe_mask) {
                    const int c0 = col_base + nt * 8;
                    if (c0 > row0)         v0 = -1e30f;
                    if (c0 + 1 > row0)     v1 = -1e30f;
                    if (c0 > row0 + 8)     v2 = -1e30f;
                    if (c0 + 1 > row0 + 8) v3 = -1e30f;
                }
                sc[mt][nt][0] = v0; sc[mt][nt][1] = v1;
                sc[mt][nt][2] = v2; sc[mt][nt][3] = v3;
                mx0 = fmaxf(mx0, fmaxf(v0, v1));
                mx1 = fmaxf(mx1, fmaxf(v2, v3));
            }
            mx0 = fmaxf(mx0, __shfl_xor_sync(0xffffffffu, mx0, 1));
            mx0 = fmaxf(mx0, __shfl_xor_sync(0xffffffffu, mx0, 2));
            mx1 = fmaxf(mx1, __shfl_xor_sync(0xffffffffu, mx1, 1));
            mx1 = fmaxf(mx1, __shfl_xor_sync(0xffffffffu, mx1, 2));
            const float mn0 = fmaxf(m[mt][0], mx0);
            const float mn1 = fmaxf(m[mt][1], mx1);
            const float al0 = exp2f(m[mt][0] - mn0);
            const float al1 = exp2f(m[mt][1] - mn1);
            m[mt][0] = mn0; m[mt][1] = mn1;

            float rs0 = 0.f, rs1 = 0.f;
#pragma unroll
            for (int nt = 0; nt < 8; nt++) {
                const float p0 = exp2f(sc[mt][nt][0] - mn0);
                const float p1 = exp2f(sc[mt][nt][1] - mn0);
                const float p2 = exp2f(sc[mt][nt][2] - mn1);
                const float p3 = exp2f(sc[mt][nt][3] - mn1);
                rs0 += p0 + p1; rs1 += p2 + p3;
                ph[mt][nt][0] = pkh(__float2half_rn(p0), __float2half_rn(p1));
                ph[mt][nt][1] = pkh(__float2half_rn(p2), __float2half_rn(p3));
            }
            rs0 += __shfl_xor_sync(0xffffffffu, rs0, 1);
            rs0 += __shfl_xor_sync(0xffffffffu, rs0, 2);
            rs1 += __shfl_xor_sync(0xffffffffu, rs1, 1);
            rs1 += __shfl_xor_sync(0xffffffffu, rs1, 2);
            l[mt][0] = l[mt][0] * al0 + rs0;
            l[mt][1] = l[mt][1] * al1 + rs1;
#pragma unroll
            for (int j = 0; j < 16; j++) {
                o[mt][j][0] *= al0; o[mt][j][1] *= al0;
                o[mt][j][2] *= al1; o[mt][j][3] *= al1;
            }
        }

        // ---- PV: V fragments shared across m-tiles ----
#pragma unroll
        for (int ks = 0; ks < 4; ks++) {
            uint32_t aph0[4] = { ph[0][2 * ks][0], ph[0][2 * ks][1],
                                 ph[0][2 * ks + 1][0], ph[0][2 * ks + 1][1] };
            uint32_t aph1[4] = { ph[1][2 * ks][0], ph[1][2 * ks][1],
                                 ph[1][2 * ks + 1][0], ph[1][2 * ks + 1][1] };
            const int vrow = ks * 16 + vrow_base;
#pragma unroll
            for (int j = 0; j < 8; j++) {
                const int u8 = 2 * j + vm2;
                const uint32_t voff = (u8 >> 2) * FKV_CH + vrow * 64
                                    + (uint32_t)(((u8 & 3) ^ (vrow & 3)) << 4);
                uint32_t vh4[4];
                ldsm4t(vh4, B + FKV_TILE + voff);
                mma_f16(o[0][2 * j],     aph0, &vh4[0]);
                mma_f16(o[0][2 * j + 1], aph0, &vh4[2]);
                mma_f16(o[1][2 * j],     aph1, &vh4[0]);
                mma_f16(o[1][2 * j + 1], aph1, &vh4[2]);
            }
        }
        __syncthreads();
    }

    // ---- epilogue: O /= l, store plain fp16 ----
#pragma unroll
    for (int mt = 0; mt < 2; mt++) {
        const float inv0 = 1.f / l[mt][0];
        const float inv1 = 1.f / l[mt][1];
        const int r0 = q0 + w * 32 + mt * 16 + (lane >> 2);
        const size_t base0 = ((size_t)r0 * NH_ + h) * HD_ + (lane & 3) * 2;
        const size_t base1 = ((size_t)(r0 + 8) * NH_ + h) * HD_ + (lane & 3) * 2;
#pragma unroll
        for (int nt = 0; nt < 16; nt++) {
            *(uint32_t*)(O16 + base0 + nt * 8) =
                pkh(__float2half_rn(o[mt][nt][0] * inv0),
                    __float2half_rn(o[mt][nt][1] * inv0));
            *(uint32_t*)(O16 + base1 + nt * 8) =
                pkh(__float2half_rn(o[mt][nt][2] * inv1),
                    __float2half_rn(o[mt][nt][3] * inv1));
        }
    }
}

// ---------------------------------------------------------------------------
// Launch
// ---------------------------------------------------------------------------
extern "C" void kernel_launch(void* const* d_in, const int* in_sizes, int n_in,
                              void* d_out, int out_size)
{
    const float* x   = (const float*)d_in[0];
    const float* Wq  = (const float*)d_in[1];
    const float* bq  = (const float*)d_in[2];
    const float* Wk  = (const float*)d_in[3];
    const float* bk  = (const float*)d_in[4];
    const float* Wv  = (const float*)d_in[5];
    const float* bv  = (const float*)d_in[6];
    const float* Wo  = (const float*)d_in[7];
    const float* bo  = (const float*)d_in[8];
    const float* qng = (const float*)d_in[9];
    const float* qnb = (const float*)d_in[10];
    const float* kng = (const float*)d_in[11];
    const float* knb = (const float*)d_in[12];
    float* out = (float*)d_out;

    float *qp, *kp;
    __half *x16, *wq16, *wk16, *wv16, *wo16, *ao16;
    __half *q16, *k16, *v16;
    cudaGetSymbolAddress((void**)&qp, g_q);
    cudaGetSymbolAddress((void**)&kp, g_k);
    cudaGetSymbolAddress((void**)&x16, g_x16);
    cudaGetSymbolAddress((void**)&wq16, g_wq16);
    cudaGetSymbolAddress((void**)&wk16, g_wk16);
    cudaGetSymbolAddress((void**)&wv16, g_wv16);
    cudaGetSymbolAddress((void**)&wo16, g_wo16);
    cudaGetSymbolAddress((void**)&ao16, g_ao16);
    cudaGetSymbolAddress((void**)&q16, g_q16);
    cudaGetSymbolAddress((void**)&k16, g_k16);
    cudaGetSymbolAddress((void**)&v16, g_v16);

    cudaFuncSetAttribute(gemm_qkv, cudaFuncAttributeMaxDynamicSharedMemorySize,
                         GEMM_SMEM);
    cudaFuncSetAttribute(gemm_f16_pipe, cudaFuncAttributeMaxDynamicSharedMemorySize,
                         GEMM_SMEM);
    cudaFuncSetAttribute(flash_mma, cudaFuncAttributeMaxDynamicSharedMemorySize,
                         FSMEM);

    const int n16_x  = S_ * HID_ / 16;
    const int n16_wq = NH_ * HD_ * HID_ / 16;
    const int n16_wk = NKV_ * HD_ * HID_ / 16;
    const int n16_wo = HID_ * HID_ / 16;
    cast_kernel<<<n16_x / 256, 256>>>(x, x16, n16_x);
    cast_kernel<<<n16_wq / 256, 256>>>(Wq, wq16, n16_wq);
    cast_kernel<<<n16_wk / 256, 256>>>(Wk, wk16, n16_wk);
    cast_kernel<<<n16_wk / 256, 256>>>(Wv, wv16, n16_wk);
    cast_kernel<<<n16_wo / 256, 256>>>(Wo, wo16, n16_wo);

    // fused QKV projection (plain fp16); V written directly as fp16
    gemm_qkv<<<dim3(48, S_ / GBM), 128, GEMM_SMEM>>>(
        x16, wq16, wk16, wv16, bq, bk, bv, qp, kp, v16);

    // LayerNorm + RoPE -> plain fp16 (one block per token-head)
    ln_rope_h<<<dim3(S_, NH_), HD_>>>(qp, q16, qng, qnb, NH_);
    ln_rope_h<<<dim3(S_, NKV_), HD_>>>(kp, k16, kng, knb, NKV_);

    // flash attention on tensor cores (BR=256) -> plain fp16 output
    flash_mma<<<dim3(S_ / FBR, NH_), 256, FSMEM>>>(q16, k16, v16, ao16);

    // output projection (plain fp16)
    gemm_f16_pipe<<<dim3(HID_ / GBN, S_ / GBM), 128, GEMM_SMEM>>>(
        S_, HID_, HID_, ao16, wo16, bo, out);
}